// round 7
// baseline (speedup 1.0000x reference)
#include <cuda_runtime.h>
#include <cuda_bf16.h>
#include <math.h>
#include <stdint.h>

#define BATCH 16384
#define DIM   1024
#define DIM2  2048

// ---------------- scratch (device globals; no allocs) ----------------
// int8 quantized operands (2-level) + per-row scales
__device__ int8_t g_xu1[(size_t)BATCH*DIM],  g_xu2[(size_t)BATCH*DIM];
__device__ int8_t g_xm1[(size_t)BATCH*DIM],  g_xm2[(size_t)BATCH*DIM];
__device__ int8_t g_zn1[(size_t)BATCH*DIM2], g_zn2[(size_t)BATCH*DIM2];
__device__ int8_t g_B1q1[DIM*DIM], g_B1q2[DIM*DIM];
__device__ int8_t g_B2q1[DIM*DIM], g_B2q2[DIM*DIM];
__device__ int8_t g_wp1[DIM*DIM2], g_wp2[DIM*DIM2];
__device__ float  g_sxu[BATCH], g_sxm[BATCH], g_szn[BATCH];
__device__ float  g_sB1[DIM], g_sB2[DIM], g_swp[DIM];
// fp32 intermediates
__device__ float  g_z[(size_t)BATCH*DIM2];
__device__ float  g_B1t[DIM*DIM], g_B2t[DIM*DIM];
__device__ float  g_c1[DIM], g_c2[DIM];
// bf16 hi/lo for the tiny weight-combine GEMMs
__device__ __nv_bfloat16 g_wo1_hi[DIM*DIM], g_wo1_lo[DIM*DIM];
__device__ __nv_bfloat16 g_wo2_hi[DIM*DIM], g_wo2_lo[DIM*DIM];
__device__ __nv_bfloat16 g_wv1t_hi[DIM*DIM], g_wv1t_lo[DIM*DIM];
__device__ __nv_bfloat16 g_wv2t_hi[DIM*DIM], g_wv2t_lo[DIM*DIM];

// ---------------- low-level helpers (sm_80-baseline PTX only) ----------------
__device__ __forceinline__ uint32_t s2u(const void* p) {
    uint32_t a;
    asm("{ .reg .u64 t; cvta.to.shared.u64 t, %1; cvt.u32.u64 %0, t; }" : "=r"(a) : "l"(p));
    return a;
}
__device__ __forceinline__ void cp16(uint32_t d, const void* s) {
    asm volatile("cp.async.cg.shared.global [%0], [%1], 16;" :: "r"(d), "l"(s));
}
__device__ __forceinline__ void ldm4(uint32_t* r, uint32_t addr) {
    asm volatile("ldmatrix.sync.aligned.m8n8.x4.shared.b16 {%0,%1,%2,%3}, [%4];"
                 : "=r"(r[0]), "=r"(r[1]), "=r"(r[2]), "=r"(r[3]) : "r"(addr));
}
__device__ __forceinline__ void mma16816(float* d, const uint32_t* a, const uint32_t* b) {
    asm volatile(
        "mma.sync.aligned.m16n8k16.row.col.f32.bf16.bf16.f32 "
        "{%0,%1,%2,%3}, {%4,%5,%6,%7}, {%8,%9}, {%0,%1,%2,%3};"
        : "+f"(d[0]), "+f"(d[1]), "+f"(d[2]), "+f"(d[3])
        : "r"(a[0]), "r"(a[1]), "r"(a[2]), "r"(a[3]), "r"(b[0]), "r"(b[1]));
}
__device__ __forceinline__ void mma_s8(int* d, const uint32_t* a, uint32_t b0, uint32_t b1) {
    asm volatile(
        "mma.sync.aligned.m16n8k32.row.col.s32.s8.s8.s32 "
        "{%0,%1,%2,%3}, {%4,%5,%6,%7}, {%8,%9}, {%0,%1,%2,%3};"
        : "+r"(d[0]), "+r"(d[1]), "+r"(d[2]), "+r"(d[3])
        : "r"(a[0]), "r"(a[1]), "r"(a[2]), "r"(a[3]), "r"(b0), "r"(b1));
}

// ============================================================================
// INT8 3-pass GEMM: C[m,n] = sA[m]*sB[n]*( q1A.q1B + (q1A.q2B + q2A.q1B)/256 )
// A: [M,K] int8 (A1, A2), B: [N,K] int8 (B1, B2), both K-major.
// CTA 128x128, K-chunk 128, 3-stage cp.async, 8 warps, warp tile 32x64.
// ============================================================================
#define QPITCH 144
#define QTILE  (128*QPITCH)      // 18432 B per (matrix,level)
#define QSTAGE (4*QTILE)         // 73728 B
#define QSMEM  (3*QSTAGE)        // 221184 B

template <bool GELU>
__global__ __launch_bounds__(256, 1)
void qgemm(const int8_t* __restrict__ A1, const int8_t* __restrict__ A2,
           const float* __restrict__ sA,
           const int8_t* __restrict__ B1, const int8_t* __restrict__ B2,
           const float* __restrict__ sB,
           float* __restrict__ C, int ldc, const float* __restrict__ bias, int K)
{
    extern __shared__ char smem[];
    const uint32_t base = s2u(smem);
    const int tid = threadIdx.x, wid = tid >> 5, lane = tid & 31;
    const int m0 = blockIdx.y * 128, n0 = blockIdx.x * 128;
    const int wm = (wid & 3) * 32;          // warp M offset (4 warps x 32)
    const int wn = (wid >> 2) * 64;         // warp N offset (2 warps x 64)

    int accM[2][8][4], accC[2][8][4];
#pragma unroll
    for (int a = 0; a < 2; a++)
#pragma unroll
        for (int j = 0; j < 8; j++)
#pragma unroll
            for (int q = 0; q < 4; q++) { accM[a][j][q] = 0; accC[a][j][q] = 0; }

    auto load_stage = [&](int s, int k0) {
        const uint32_t st = base + s * QSTAGE;
        for (int i = tid; i < 1024; i += 256) {
            const int r = i >> 3, seg = i & 7;
            const uint32_t off = (uint32_t)(r * QPITCH + seg * 16);
            const size_t ga = (size_t)(m0 + r) * K + k0 + seg * 16;
            const size_t gb = (size_t)(n0 + r) * K + k0 + seg * 16;
            cp16(st + off,              A1 + ga);
            cp16(st + QTILE + off,      A2 + ga);
            cp16(st + 2 * QTILE + off,  B1 + gb);
            cp16(st + 3 * QTILE + off,  B2 + gb);
        }
        asm volatile("cp.async.commit_group;" ::: "memory");
    };

    const int nk = K >> 7;
    load_stage(0, 0);
    load_stage(1, 128);

    const uint32_t aoff = (uint32_t)((wm + (lane & 15)) * QPITCH + ((lane >> 4) << 4));
    const uint32_t boff = (uint32_t)((wn + (lane & 15)) * QPITCH + ((lane >> 4) << 4));

    for (int i = 0; i < nk; i++) {
        if (i + 2 <= nk) asm volatile("cp.async.wait_group 1;" ::: "memory");
        else             asm volatile("cp.async.wait_group 0;" ::: "memory");
        __syncthreads();
        if (i + 2 < nk) load_stage((i + 2) % 3, (i + 2) * 128);

        const uint32_t st = base + (i % 3) * QSTAGE;
#pragma unroll
        for (int ks = 0; ks < 4; ks++) {
            const uint32_t kb = ks * 32;
            uint32_t a1f[2][4], a2f[2][4];
#pragma unroll
            for (int mf = 0; mf < 2; mf++) {
                const uint32_t ao = aoff + (uint32_t)(mf * 16 * QPITCH) + kb;
                ldm4(a1f[mf], st + ao);
                ldm4(a2f[mf], st + QTILE + ao);
            }
#pragma unroll
            for (int ng = 0; ng < 4; ng++) {
                uint32_t b1f[4], b2f[4];
                const uint32_t bo = boff + (uint32_t)(ng * 16 * QPITCH) + kb;
                ldm4(b1f, st + 2 * QTILE + bo);
                ldm4(b2f, st + 3 * QTILE + bo);
#pragma unroll
                for (int mf = 0; mf < 2; mf++) {
                    mma_s8(accM[mf][2 * ng + 0], a1f[mf], b1f[0], b1f[2]);
                    mma_s8(accM[mf][2 * ng + 1], a1f[mf], b1f[1], b1f[3]);
                    mma_s8(accC[mf][2 * ng + 0], a1f[mf], b2f[0], b2f[2]);
                    mma_s8(accC[mf][2 * ng + 1], a1f[mf], b2f[1], b2f[3]);
                    mma_s8(accC[mf][2 * ng + 0], a2f[mf], b1f[0], b1f[2]);
                    mma_s8(accC[mf][2 * ng + 1], a2f[mf], b1f[1], b1f[3]);
                }
            }
        }
    }

    // ---- epilogue ----
#pragma unroll
    for (int mf = 0; mf < 2; mf++) {
        const int r0 = m0 + wm + mf * 16 + (lane >> 2);
        const float sa0 = sA[r0], sa1 = sA[r0 + 8];
#pragma unroll
        for (int j = 0; j < 8; j++) {
            const int c = n0 + wn + j * 8 + ((lane & 3) << 1);
            const float sb0 = sB[c], sb1 = sB[c + 1];
            float bb0 = 0.0f, bb1 = 0.0f;
            if (bias) { bb0 = bias[c]; bb1 = bias[c + 1]; }
            float v0 = sa0 * sb0 * ((float)accM[mf][j][0] + (float)accC[mf][j][0] * 0.00390625f) + bb0;
            float v1 = sa0 * sb1 * ((float)accM[mf][j][1] + (float)accC[mf][j][1] * 0.00390625f) + bb1;
            float v2 = sa1 * sb0 * ((float)accM[mf][j][2] + (float)accC[mf][j][2] * 0.00390625f) + bb0;
            float v3 = sa1 * sb1 * ((float)accM[mf][j][3] + (float)accC[mf][j][3] * 0.00390625f) + bb1;
            if (GELU) {
                v0 = 0.5f * v0 * (1.0f + erff(v0 * 0.70710678118654752f));
                v1 = 0.5f * v1 * (1.0f + erff(v1 * 0.70710678118654752f));
                v2 = 0.5f * v2 * (1.0f + erff(v2 * 0.70710678118654752f));
                v3 = 0.5f * v3 * (1.0f + erff(v3 * 0.70710678118654752f));
            }
            *reinterpret_cast<float2*>(&C[(size_t)r0 * ldc + c])       = make_float2(v0, v1);
            *reinterpret_cast<float2*>(&C[(size_t)(r0 + 8) * ldc + c]) = make_float2(v2, v3);
        }
    }
}

// ============================================================================
// bf16x3 mma GEMM (validated R4) — used only for the two 1024^3 combine GEMMs
// ============================================================================
#define MT 256
#define NT 128
#define KC 64
#define STRIDE 72
#define A_TILE (MT*STRIDE*2)
#define B_TILE (NT*STRIDE*2)
#define STAGE  (2*A_TILE + 2*B_TILE)
#define SMEM_TOT (2*STAGE)

__global__ __launch_bounds__(256, 1)
void mma_gemm(const __nv_bfloat16* __restrict__ Ah, const __nv_bfloat16* __restrict__ Al,
              const __nv_bfloat16* __restrict__ Bh, const __nv_bfloat16* __restrict__ Bl,
              float* __restrict__ C, int ldc, int K)
{
    extern __shared__ char smem[];
    const uint32_t base = s2u(smem);
    const int tid  = threadIdx.x;
    const int wid  = tid >> 5;
    const int lane = tid & 31;
    const int m0 = blockIdx.y * MT;
    const int n0 = blockIdx.x * NT;
    const int warp_m0 = (wid & 3) * 64;
    const int warp_n0 = (wid >> 2) * 64;

    float acc[4][8][4];
#pragma unroll
    for (int i = 0; i < 4; i++)
#pragma unroll
        for (int j = 0; j < 8; j++)
#pragma unroll
            for (int q = 0; q < 4; q++) acc[i][j][q] = 0.0f;

    auto load_stage = [&](int s, int k0) {
        const uint32_t stA_h = base + s * STAGE;
        const uint32_t stA_l = stA_h + A_TILE;
        const uint32_t stB_h = stA_h + 2 * A_TILE;
        const uint32_t stB_l = stB_h + B_TILE;
        for (int i = tid; i < MT * 8; i += 256) {
            const int r = i >> 3, seg = i & 7;
            const uint32_t off = (uint32_t)(r * (STRIDE * 2) + seg * 16);
            const size_t gs = (size_t)(m0 + r) * K + k0 + seg * 8;
            cp16(stA_h + off, Ah + gs);
            cp16(stA_l + off, Al + gs);
        }
        for (int i = tid; i < NT * 8; i += 256) {
            const int r = i >> 3, seg = i & 7;
            const uint32_t off = (uint32_t)(r * (STRIDE * 2) + seg * 16);
            const size_t gs = (size_t)(n0 + r) * K + k0 + seg * 8;
            cp16(stB_h + off, Bh + gs);
            cp16(stB_l + off, Bl + gs);
        }
        asm volatile("cp.async.commit_group;" ::: "memory");
    };

    const int nk = K / KC;
    load_stage(0, 0);
    load_stage(1, KC);

    const int a_row = warp_m0 + (lane & 15);
    const int a_col = (lane >> 4) << 3;
    const int b_row = warp_n0 + (lane & 7) + ((lane >> 4) << 3);
    const int b_col = ((lane >> 3) & 1) << 3;

    for (int i = 0; i < nk; i++) {
        if (i + 1 < nk) asm volatile("cp.async.wait_group 1;" ::: "memory");
        else            asm volatile("cp.async.wait_group 0;" ::: "memory");
        __syncthreads();

        const uint32_t stA_h = base + (i & 1) * STAGE;
        const uint32_t stA_l = stA_h + A_TILE;
        const uint32_t stB_h = stA_h + 2 * A_TILE;
        const uint32_t stB_l = stB_h + B_TILE;

#pragma unroll
        for (int ks = 0; ks < 4; ks++) {
            const int k0 = ks * 16;
            uint32_t ah[4][4], al[4][4], bh[4][4], bl[4][4];
#pragma unroll
            for (int mf = 0; mf < 4; mf++) {
                const uint32_t ao = (uint32_t)((a_row + mf * 16) * STRIDE + k0 + a_col) * 2;
                ldm4(ah[mf], stA_h + ao);
                ldm4(al[mf], stA_l + ao);
            }
#pragma unroll
            for (int bp = 0; bp < 4; bp++) {
                const uint32_t bo = (uint32_t)((b_row + bp * 16) * STRIDE + k0 + b_col) * 2;
                ldm4(bh[bp], stB_h + bo);
                ldm4(bl[bp], stB_l + bo);
            }
#pragma unroll
            for (int mf = 0; mf < 4; mf++) {
#pragma unroll
                for (int bp = 0; bp < 4; bp++) {
                    mma16816(acc[mf][2 * bp + 0], ah[mf], &bh[bp][0]);
                    mma16816(acc[mf][2 * bp + 1], ah[mf], &bh[bp][2]);
                    mma16816(acc[mf][2 * bp + 0], ah[mf], &bl[bp][0]);
                    mma16816(acc[mf][2 * bp + 1], ah[mf], &bl[bp][2]);
                    mma16816(acc[mf][2 * bp + 0], al[mf], &bh[bp][0]);
                    mma16816(acc[mf][2 * bp + 1], al[mf], &bh[bp][2]);
                }
            }
        }

        __syncthreads();
        if (i + 2 < nk) load_stage(i & 1, (i + 2) * KC);
    }

    const int r_base = m0 + warp_m0 + (lane >> 2);
    const int c_base = n0 + warp_n0 + ((lane & 3) << 1);
#pragma unroll
    for (int mf = 0; mf < 4; mf++) {
#pragma unroll
        for (int nf = 0; nf < 8; nf++) {
            const int cc = c_base + nf * 8;
            const int row0 = r_base + mf * 16;
            *reinterpret_cast<float2*>(&C[(size_t)row0 * ldc + cc]) =
                make_float2(acc[mf][nf][0], acc[mf][nf][1]);
            *reinterpret_cast<float2*>(&C[(size_t)(row0 + 8) * ldc + cc]) =
                make_float2(acc[mf][nf][2], acc[mf][nf][3]);
        }
    }
}

// ---------------- bf16 split helpers (for combine GEMM inputs) ----------------
__global__ void split_kernel(const float* __restrict__ x,
                             __nv_bfloat16* __restrict__ h, __nv_bfloat16* __restrict__ l,
                             int n4)
{
    int i = blockIdx.x * blockDim.x + threadIdx.x;
    if (i < n4) {
        float4 v = reinterpret_cast<const float4*>(x)[i];
        __nv_bfloat162 h0, h1, l0, l1;
        h0.x = __float2bfloat16_rn(v.x); h0.y = __float2bfloat16_rn(v.y);
        h1.x = __float2bfloat16_rn(v.z); h1.y = __float2bfloat16_rn(v.w);
        l0.x = __float2bfloat16_rn(v.x - __bfloat162float(h0.x));
        l0.y = __float2bfloat16_rn(v.y - __bfloat162float(h0.y));
        l1.x = __float2bfloat16_rn(v.z - __bfloat162float(h1.x));
        l1.y = __float2bfloat16_rn(v.w - __bfloat162float(h1.y));
        reinterpret_cast<__nv_bfloat162*>(h + (size_t)i * 4)[0] = h0;
        reinterpret_cast<__nv_bfloat162*>(h + (size_t)i * 4)[1] = h1;
        reinterpret_cast<__nv_bfloat162*>(l + (size_t)i * 4)[0] = l0;
        reinterpret_cast<__nv_bfloat162*>(l + (size_t)i * 4)[1] = l1;
    }
}

__global__ void tsplit_kernel(const float* __restrict__ in, int R, int Ccols,
                              __nv_bfloat16* __restrict__ h, __nv_bfloat16* __restrict__ l)
{
    __shared__ float t[32][33];
    const int r0 = blockIdx.y * 32, c0 = blockIdx.x * 32;
    const int tx = threadIdx.x, ty = threadIdx.y;  // 32 x 8
#pragma unroll
    for (int i = 0; i < 4; i++)
        t[ty + 8 * i][tx] = in[(size_t)(r0 + ty + 8 * i) * Ccols + c0 + tx];
    __syncthreads();
#pragma unroll
    for (int i = 0; i < 4; i++) {
        const int rr = ty + 8 * i;
        const float v = t[tx][rr];
        const size_t o = (size_t)(c0 + rr) * R + r0 + tx;
        __nv_bfloat16 hh = __float2bfloat16_rn(v);
        h[o] = hh;
        l[o] = __float2bfloat16_rn(v - __bfloat162float(hh));
    }
}

// ---------------- per-row 2-level int8 quantization ----------------
__device__ __forceinline__ float qclamp(float t) {
    return fminf(fmaxf(t, -127.0f), 127.0f);
}

__global__ void quant_rows(const float* __restrict__ X, int K,
                           int8_t* __restrict__ Q1, int8_t* __restrict__ Q2,
                           float* __restrict__ S)
{
    __shared__ float red[8];
    const int row = blockIdx.x;
    const float* x = X + (size_t)row * K;
    const int tid = threadIdx.x;  // 256

    float am = 0.0f;
    for (int j = tid * 4; j < K; j += 1024) {
        float4 v = *reinterpret_cast<const float4*>(x + j);
        am = fmaxf(am, fmaxf(fmaxf(fabsf(v.x), fabsf(v.y)), fmaxf(fabsf(v.z), fabsf(v.w))));
    }
#pragma unroll
    for (int o = 16; o > 0; o >>= 1) am = fmaxf(am, __shfl_xor_sync(0xFFFFFFFFu, am, o));
    if ((tid & 31) == 0) red[tid >> 5] = am;
    __syncthreads();
    am = red[0];
#pragma unroll
    for (int w = 1; w < 8; w++) am = fmaxf(am, red[w]);
    am = fmaxf(am, 1e-20f);

    const float s    = am * (1.0f / 127.0f);
    const float inv  = 127.0f / am;
    const float inv2 = 256.0f / s;
    if (tid == 0) S[row] = s;

    for (int j = tid * 4; j < K; j += 1024) {
        float4 v = *reinterpret_cast<const float4*>(x + j);
        float q1x = qclamp(rintf(v.x * inv));
        float q1y = qclamp(rintf(v.y * inv));
        float q1z = qclamp(rintf(v.z * inv));
        float q1w = qclamp(rintf(v.w * inv));
        char4 a = make_char4((signed char)q1x, (signed char)q1y,
                             (signed char)q1z, (signed char)q1w);
        char4 b;
        b.x = (signed char)qclamp(rintf((v.x - q1x * s) * inv2));
        b.y = (signed char)qclamp(rintf((v.y - q1y * s) * inv2));
        b.z = (signed char)qclamp(rintf((v.z - q1z * s) * inv2));
        b.w = (signed char)qclamp(rintf((v.w - q1w * s) * inv2));
        *reinterpret_cast<char4*>(Q1 + (size_t)row * K + j) = a;
        *reinterpret_cast<char4*>(Q2 + (size_t)row * K + j) = b;
    }
}

// ---------------- combined bias: c[n] = sum_j wo[n,j]*bv[j] + bo[n] ----------------
__global__ void biasc_kernel(const float* __restrict__ wo, const float* __restrict__ bv,
                             const float* __restrict__ bo, float* __restrict__ c)
{
    __shared__ float red[4];
    const int n = blockIdx.x;
    const int tid = threadIdx.x;  // 128
    float s = 0.0f;
    for (int j = tid; j < DIM; j += 128) s += wo[(size_t)n * DIM + j] * bv[j];
#pragma unroll
    for (int o = 16; o > 0; o >>= 1) s += __shfl_xor_sync(0xFFFFFFFFu, s, o);
    if ((tid & 31) == 0) red[tid >> 5] = s;
    __syncthreads();
    if (tid == 0) c[n] = red[0] + red[1] + red[2] + red[3] + bo[n];
}

// ---------------- LayerNorm(2048) with bias add, fused int8 quantization ----------------
__global__ void ln_quant(const float* __restrict__ z,
                         const float* __restrict__ c1, const float* __restrict__ c2,
                         const float* __restrict__ g, const float* __restrict__ b,
                         int8_t* __restrict__ Q1, int8_t* __restrict__ Q2,
                         float* __restrict__ S)
{
    __shared__ float redS[8], redQ[8], redA[8];
    const size_t base = (size_t)blockIdx.x * DIM2;
    const int tid = threadIdx.x;  // 256

    float4 v0 = *reinterpret_cast<const float4*>(&z[base + tid * 4]);
    float4 v1 = *reinterpret_cast<const float4*>(&z[base + 1024 + tid * 4]);
    float4 cb0 = *reinterpret_cast<const float4*>(&c1[tid * 4]);
    float4 cb1 = *reinterpret_cast<const float4*>(&c2[tid * 4]);
    v0.x += cb0.x; v0.y += cb0.y; v0.z += cb0.z; v0.w += cb0.w;
    v1.x += cb1.x; v1.y += cb1.y; v1.z += cb1.z; v1.w += cb1.w;

    float s = v0.x + v0.y + v0.z + v0.w + v1.x + v1.y + v1.z + v1.w;
    float q = v0.x * v0.x + v0.y * v0.y + v0.z * v0.z + v0.w * v0.w
            + v1.x * v1.x + v1.y * v1.y + v1.z * v1.z + v1.w * v1.w;
#pragma unroll
    for (int o = 16; o > 0; o >>= 1) {
        s += __shfl_xor_sync(0xFFFFFFFFu, s, o);
        q += __shfl_xor_sync(0xFFFFFFFFu, q, o);
    }
    if ((tid & 31) == 0) { redS[tid >> 5] = s; redQ[tid >> 5] = q; }
    __syncthreads();
    float Ssum = 0.0f, Qsum = 0.0f;
#pragma unroll
    for (int w = 0; w < 8; w++) { Ssum += redS[w]; Qsum += redQ[w]; }

    const float mu = Ssum * (1.0f / DIM2);
    const float var = Qsum * (1.0f / DIM2) - mu * mu;
    const float rstd = rsqrtf(var + 1e-5f);

    float4 g0 = *reinterpret_cast<const float4*>(&g[tid * 4]);
    float4 g1 = *reinterpret_cast<const float4*>(&g[1024 + tid * 4]);
    float4 b0 = *reinterpret_cast<const float4*>(&b[tid * 4]);
    float4 b1 = *reinterpret_cast<const float4*>(&b[1024 + tid * 4]);

    v0.x = (v0.x - mu) * rstd * g0.x + b0.x;
    v0.y = (v0.y - mu) * rstd * g0.y + b0.y;
    v0.z = (v0.z - mu) * rstd * g0.z + b0.z;
    v0.w = (v0.w - mu) * rstd * g0.w + b0.w;
    v1.x = (v1.x - mu) * rstd * g1.x + b1.x;
    v1.y = (v1.y - mu) * rstd * g1.y + b1.y;
    v1.z = (v1.z - mu) * rstd * g1.z + b1.z;
    v1.w = (v1.w - mu) * rstd * g1.w + b1.w;

    // row amax of normalized values
    float am = fmaxf(fmaxf(fmaxf(fabsf(v0.x), fabsf(v0.y)), fmaxf(fabsf(v0.z), fabsf(v0.w))),
                     fmaxf(fmaxf(fabsf(v1.x), fabsf(v1.y)), fmaxf(fabsf(v1.z), fabsf(v1.w))));
#pragma unroll
    for (int o = 16; o > 0; o >>= 1) am = fmaxf(am, __shfl_xor_sync(0xFFFFFFFFu, am, o));
    if ((tid & 31) == 0) redA[tid >> 5] = am;
    __syncthreads();
    am = redA[0];
#pragma unroll
    for (int w = 1; w < 8; w++) am = fmaxf(am, redA[w]);
    am = fmaxf(am, 1e-20f);

    const float sc   = am * (1.0f / 127.0f);
    const float inv  = 127.0f / am;
    const float inv2 = 256.0f / sc;
    if (tid == 0) S[blockIdx.x] = sc;

    float q1x, q1y, q1z, q1w;
    char4 a, bq;
    // first half
    q1x = qclamp(rintf(v0.x * inv)); q1y = qclamp(rintf(v0.y * inv));
    q1z = qclamp(rintf(v0.z * inv)); q1w = qclamp(rintf(v0.w * inv));
    a = make_char4((signed char)q1x, (signed char)q1y, (signed char)q1z, (signed char)q1w);
    bq.x = (signed char)qclamp(rintf((v0.x - q1x * sc) * inv2));
    bq.y = (signed char)qclamp(rintf((v0.y - q1y * sc) * inv2));
    bq.z = (signed char)qclamp(rintf((v0.z - q1z * sc) * inv2));
    bq.w = (signed char)qclamp(rintf((v0.w - q1w * sc) * inv2));
    *reinterpret_cast<char4*>(Q1 + base + tid * 4) = a;
    *reinterpret_cast<char4*>(Q2 + base + tid * 4) = bq;
    // second half
    q1x = qclamp(rintf(v1.x * inv)); q1y = qclamp(rintf(v1.y * inv));
    q1z = qclamp(rintf(v1.z * inv)); q1w = qclamp(rintf(v1.w * inv));
    a = make_char4((signed char)q1x, (signed char)q1y, (signed char)q1z, (signed char)q1w);
    bq.x = (signed char)qclamp(rintf((v1.x - q1x * sc) * inv2));
    bq.y = (signed char)qclamp(rintf((v1.y - q1y * sc) * inv2));
    bq.z = (signed char)qclamp(rintf((v1.z - q1z * sc) * inv2));
    bq.w = (signed char)qclamp(rintf((v1.w - q1w * sc) * inv2));
    *reinterpret_cast<char4*>(Q1 + base + 1024 + tid * 4) = a;
    *reinterpret_cast<char4*>(Q2 + base + 1024 + tid * 4) = bq;
}

// ---------------- launch ----------------
extern "C" void kernel_launch(void* const* d_in, const int* in_sizes, int n_in,
                              void* d_out, int out_size)
{
    const float* x_u    = (const float*)d_in[0];
    const float* x_m    = (const float*)d_in[1];
    const float* w_qkv1 = (const float*)d_in[2];
    const float* b_qkv1 = (const float*)d_in[3];
    const float* w_o1   = (const float*)d_in[4];
    const float* b_o1   = (const float*)d_in[5];
    const float* w_qkv2 = (const float*)d_in[6];
    const float* b_qkv2 = (const float*)d_in[7];
    const float* w_o2   = (const float*)d_in[8];
    const float* b_o2   = (const float*)d_in[9];
    const float* ln_g   = (const float*)d_in[10];
    const float* ln_b   = (const float*)d_in[11];
    const float* w_proj = (const float*)d_in[12];
    const float* b_proj = (const float*)d_in[13];
    float* out = (float*)d_out;

    const float* wv1 = w_qkv1 + (size_t)2 * DIM * DIM;
    const float* bv1 = b_qkv1 + 2 * DIM;
    const float* wv2 = w_qkv2 + (size_t)2 * DIM * DIM;
    const float* bv2 = b_qkv2 + 2 * DIM;

    int8_t *xu1, *xu2, *xm1, *xm2, *zn1, *zn2, *B1q1, *B1q2, *B2q1, *B2q2, *wp1, *wp2;
    float *sxu, *sxm, *szn, *sB1, *sB2, *swp, *z, *B1t, *B2t, *c1, *c2;
    __nv_bfloat16 *wo1_h, *wo1_l, *wo2_h, *wo2_l, *wv1t_h, *wv1t_l, *wv2t_h, *wv2t_l;

    cudaGetSymbolAddress((void**)&xu1, g_xu1);   cudaGetSymbolAddress((void**)&xu2, g_xu2);
    cudaGetSymbolAddress((void**)&xm1, g_xm1);   cudaGetSymbolAddress((void**)&xm2, g_xm2);
    cudaGetSymbolAddress((void**)&zn1, g_zn1);   cudaGetSymbolAddress((void**)&zn2, g_zn2);
    cudaGetSymbolAddress((void**)&B1q1, g_B1q1); cudaGetSymbolAddress((void**)&B1q2, g_B1q2);
    cudaGetSymbolAddress((void**)&B2q1, g_B2q1); cudaGetSymbolAddress((void**)&B2q2, g_B2q2);
    cudaGetSymbolAddress((void**)&wp1, g_wp1);   cudaGetSymbolAddress((void**)&wp2, g_wp2);
    cudaGetSymbolAddress((void**)&sxu, g_sxu);   cudaGetSymbolAddress((void**)&sxm, g_sxm);
    cudaGetSymbolAddress((void**)&szn, g_szn);
    cudaGetSymbolAddress((void**)&sB1, g_sB1);   cudaGetSymbolAddress((void**)&sB2, g_sB2);
    cudaGetSymbolAddress((void**)&swp, g_swp);
    cudaGetSymbolAddress((void**)&z, g_z);
    cudaGetSymbolAddress((void**)&B1t, g_B1t);   cudaGetSymbolAddress((void**)&B2t, g_B2t);
    cudaGetSymbolAddress((void**)&c1, g_c1);     cudaGetSymbolAddress((void**)&c2, g_c2);
    cudaGetSymbolAddress((void**)&wo1_h, g_wo1_hi);   cudaGetSymbolAddress((void**)&wo1_l, g_wo1_lo);
    cudaGetSymbolAddress((void**)&wo2_h, g_wo2_hi);   cudaGetSymbolAddress((void**)&wo2_l, g_wo2_lo);
    cudaGetSymbolAddress((void**)&wv1t_h, g_wv1t_hi); cudaGetSymbolAddress((void**)&wv1t_l, g_wv1t_lo);
    cudaGetSymbolAddress((void**)&wv2t_h, g_wv2t_hi); cudaGetSymbolAddress((void**)&wv2t_l, g_wv2t_lo);

    cudaFuncSetAttribute(mma_gemm, cudaFuncAttributeMaxDynamicSharedMemorySize, SMEM_TOT);
    cudaFuncSetAttribute(qgemm<false>, cudaFuncAttributeMaxDynamicSharedMemorySize, QSMEM);
    cudaFuncSetAttribute(qgemm<true>,  cudaFuncAttributeMaxDynamicSharedMemorySize, QSMEM);

    const dim3 gridQz(DIM / 128, BATCH / 128);    // (8, 128)
    const dim3 gridW(DIM / NT, DIM / MT);         // (8, 4)

    // ---- path 1 chain (int8 z1 GEMM is launch #6 → profiled by ncu -s 5) ----
    split_kernel<<<(DIM * DIM / 4) / 256, 256>>>(w_o1, wo1_h, wo1_l, DIM * DIM / 4);   // 1
    tsplit_kernel<<<dim3(32, 32), dim3(32, 8)>>>(wv1, DIM, DIM, wv1t_h, wv1t_l);       // 2
    mma_gemm<<<gridW, 256, SMEM_TOT>>>(wo1_h, wo1_l, wv1t_h, wv1t_l, B1t, DIM, DIM);   // 3
    quant_rows<<<DIM, 256>>>(B1t, DIM, B1q1, B1q2, sB1);                               // 4
    quant_rows<<<BATCH, 256>>>(x_u, DIM, xu1, xu2, sxu);                               // 5
    qgemm<false><<<gridQz, 256, QSMEM>>>(xu1, xu2, sxu, B1q1, B1q2, sB1,
                                         z, DIM2, nullptr, DIM);                       // 6

    // ---- path 2 chain ----
    split_kernel<<<(DIM * DIM / 4) / 256, 256>>>(w_o2, wo2_h, wo2_l, DIM * DIM / 4);
    tsplit_kernel<<<dim3(32, 32), dim3(32, 8)>>>(wv2, DIM, DIM, wv2t_h, wv2t_l);
    mma_gemm<<<gridW, 256, SMEM_TOT>>>(wo2_h, wo2_l, wv2t_h, wv2t_l, B2t, DIM, DIM);
    quant_rows<<<DIM, 256>>>(B2t, DIM, B2q1, B2q2, sB2);
    quant_rows<<<BATCH, 256>>>(x_m, DIM, xm1, xm2, sxm);
    qgemm<false><<<gridQz, 256, QSMEM>>>(xm1, xm2, sxm, B2q1, B2q2, sB2,
                                         z + DIM, DIM2, nullptr, DIM);

    // ---- combined biases (added inside LN) ----
    biasc_kernel<<<DIM, 128>>>(w_o1, bv1, b_o1, c1);
    biasc_kernel<<<DIM, 128>>>(w_o2, bv2, b_o2, c2);

    // ---- LayerNorm(+bias) + int8 quantization ----
    ln_quant<<<BATCH, 256>>>(z, c1, c2, ln_g, ln_b, zn1, zn2, szn);

    // ---- proj weights quant + final GEMM with bias + exact GELU ----
    quant_rows<<<DIM, 256>>>(w_proj, DIM2, wp1, wp2, swp);
    qgemm<true><<<gridQz, 256, QSMEM>>>(zn1, zn2, szn, wp1, wp2, swp,
                                        out, DIM, b_proj, DIM2);
}

// round 8
// speedup vs baseline: 1.6336x; 1.6336x over previous
#include <cuda_runtime.h>
#include <cuda_bf16.h>
#include <math.h>
#include <stdint.h>

#define BATCH 16384
#define DIM   1024
#define DIM2  2048

// ---------------- scratch (device globals; no allocs) ----------------
// int8 quantized operands (2-level) + per-row scales
__device__ int8_t g_xu1[(size_t)BATCH*DIM],  g_xu2[(size_t)BATCH*DIM];
__device__ int8_t g_xm1[(size_t)BATCH*DIM],  g_xm2[(size_t)BATCH*DIM];
__device__ int8_t g_zn1[(size_t)BATCH*DIM2], g_zn2[(size_t)BATCH*DIM2];
__device__ int8_t g_B1q1[DIM*DIM], g_B1q2[DIM*DIM];
__device__ int8_t g_B2q1[DIM*DIM], g_B2q2[DIM*DIM];
__device__ int8_t g_wp1[DIM*DIM2], g_wp2[DIM*DIM2];
__device__ float  g_sxu[BATCH], g_sxm[BATCH], g_szn[BATCH];
__device__ float  g_sB1[DIM], g_sB2[DIM], g_swp[DIM];
// fp32 intermediates
__device__ float  g_z[(size_t)BATCH*DIM2];
__device__ float  g_B1t[DIM*DIM], g_B2t[DIM*DIM];
__device__ float  g_c1[DIM], g_c2[DIM];
// bf16 hi/lo for the tiny weight-combine GEMMs
__device__ __nv_bfloat16 g_wo1_hi[DIM*DIM], g_wo1_lo[DIM*DIM];
__device__ __nv_bfloat16 g_wo2_hi[DIM*DIM], g_wo2_lo[DIM*DIM];
__device__ __nv_bfloat16 g_wv1t_hi[DIM*DIM], g_wv1t_lo[DIM*DIM];
__device__ __nv_bfloat16 g_wv2t_hi[DIM*DIM], g_wv2t_lo[DIM*DIM];

// ---------------- low-level helpers (sm_80-baseline PTX only) ----------------
__device__ __forceinline__ uint32_t s2u(const void* p) {
    uint32_t a;
    asm("{ .reg .u64 t; cvta.to.shared.u64 t, %1; cvt.u32.u64 %0, t; }" : "=r"(a) : "l"(p));
    return a;
}
__device__ __forceinline__ void cp16(uint32_t d, const void* s) {
    asm volatile("cp.async.cg.shared.global [%0], [%1], 16;" :: "r"(d), "l"(s));
}
__device__ __forceinline__ void ldm4(uint32_t* r, uint32_t addr) {
    asm volatile("ldmatrix.sync.aligned.m8n8.x4.shared.b16 {%0,%1,%2,%3}, [%4];"
                 : "=r"(r[0]), "=r"(r[1]), "=r"(r[2]), "=r"(r[3]) : "r"(addr));
}
__device__ __forceinline__ void mma16816(float* d, const uint32_t* a, const uint32_t* b) {
    asm volatile(
        "mma.sync.aligned.m16n8k16.row.col.f32.bf16.bf16.f32 "
        "{%0,%1,%2,%3}, {%4,%5,%6,%7}, {%8,%9}, {%0,%1,%2,%3};"
        : "+f"(d[0]), "+f"(d[1]), "+f"(d[2]), "+f"(d[3])
        : "r"(a[0]), "r"(a[1]), "r"(a[2]), "r"(a[3]), "r"(b[0]), "r"(b[1]));
}
__device__ __forceinline__ void mma_s8(int* d, const uint32_t* a, uint32_t b0, uint32_t b1) {
    asm volatile(
        "mma.sync.aligned.m16n8k32.row.col.s32.s8.s8.s32 "
        "{%0,%1,%2,%3}, {%4,%5,%6,%7}, {%8,%9}, {%0,%1,%2,%3};"
        : "+r"(d[0]), "+r"(d[1]), "+r"(d[2]), "+r"(d[3])
        : "r"(a[0]), "r"(a[1]), "r"(a[2]), "r"(a[3]), "r"(b0), "r"(b1));
}

// ============================================================================
// INT8 3-pass GEMM: C[m,n] = sA[m]*sB[n]*( q1A.q1B + (q1A.q2B + q2A.q1B)/256 )
// A: [M,K] int8 (A1, A2), B: [N,K] int8 (B1, B2), both K-major.
// CTA 128x128, K-chunk 128, 3-stage cp.async, 8 warps, warp tile 32x64.
// ============================================================================
#define QPITCH 144
#define QTILE  (128*QPITCH)      // 18432 B per (matrix,level)
#define QSTAGE (4*QTILE)         // 73728 B
#define QSMEM  (3*QSTAGE)        // 221184 B

template <bool GELU>
__global__ __launch_bounds__(256, 1)
void qgemm(const int8_t* __restrict__ A1, const int8_t* __restrict__ A2,
           const float* __restrict__ sA,
           const int8_t* __restrict__ B1, const int8_t* __restrict__ B2,
           const float* __restrict__ sB,
           float* __restrict__ C, int ldc, const float* __restrict__ bias, int K)
{
    extern __shared__ char smem[];
    const uint32_t base = s2u(smem);
    const int tid = threadIdx.x, wid = tid >> 5, lane = tid & 31;
    const int m0 = blockIdx.y * 128, n0 = blockIdx.x * 128;
    const int wm = (wid & 3) * 32;          // warp M offset (4 warps x 32)
    const int wn = (wid >> 2) * 64;         // warp N offset (2 warps x 64)

    int accM[2][8][4], accC[2][8][4];
#pragma unroll
    for (int a = 0; a < 2; a++)
#pragma unroll
        for (int j = 0; j < 8; j++)
#pragma unroll
            for (int q = 0; q < 4; q++) { accM[a][j][q] = 0; accC[a][j][q] = 0; }

    auto load_stage = [&](int s, int k0) {
        const uint32_t st = base + s * QSTAGE;
        for (int i = tid; i < 1024; i += 256) {
            const int r = i >> 3, seg = i & 7;
            const uint32_t off = (uint32_t)(r * QPITCH + seg * 16);
            const size_t ga = (size_t)(m0 + r) * K + k0 + seg * 16;
            const size_t gb = (size_t)(n0 + r) * K + k0 + seg * 16;
            cp16(st + off,              A1 + ga);
            cp16(st + QTILE + off,      A2 + ga);
            cp16(st + 2 * QTILE + off,  B1 + gb);
            cp16(st + 3 * QTILE + off,  B2 + gb);
        }
        asm volatile("cp.async.commit_group;" ::: "memory");
    };

    const int nk = K >> 7;
    load_stage(0, 0);
    load_stage(1, 128);

    const uint32_t aoff = (uint32_t)((wm + (lane & 15)) * QPITCH + ((lane >> 4) << 4));
    const uint32_t boff = (uint32_t)((wn + (lane & 15)) * QPITCH + ((lane >> 4) << 4));

    for (int i = 0; i < nk; i++) {
        if (i + 2 <= nk) asm volatile("cp.async.wait_group 1;" ::: "memory");
        else             asm volatile("cp.async.wait_group 0;" ::: "memory");
        __syncthreads();
        if (i + 2 < nk) load_stage((i + 2) % 3, (i + 2) * 128);

        const uint32_t st = base + (i % 3) * QSTAGE;
#pragma unroll
        for (int ks = 0; ks < 4; ks++) {
            const uint32_t kb = ks * 32;
            uint32_t a1f[2][4], a2f[2][4];
#pragma unroll
            for (int mf = 0; mf < 2; mf++) {
                const uint32_t ao = aoff + (uint32_t)(mf * 16 * QPITCH) + kb;
                ldm4(a1f[mf], st + ao);
                ldm4(a2f[mf], st + QTILE + ao);
            }
#pragma unroll
            for (int ng = 0; ng < 4; ng++) {
                uint32_t b1f[4], b2f[4];
                const uint32_t bo = boff + (uint32_t)(ng * 16 * QPITCH) + kb;
                ldm4(b1f, st + 2 * QTILE + bo);
                ldm4(b2f, st + 3 * QTILE + bo);
#pragma unroll
                for (int mf = 0; mf < 2; mf++) {
                    mma_s8(accM[mf][2 * ng + 0], a1f[mf], b1f[0], b1f[2]);
                    mma_s8(accM[mf][2 * ng + 1], a1f[mf], b1f[1], b1f[3]);
                    mma_s8(accC[mf][2 * ng + 0], a1f[mf], b2f[0], b2f[2]);
                    mma_s8(accC[mf][2 * ng + 1], a1f[mf], b2f[1], b2f[3]);
                    mma_s8(accC[mf][2 * ng + 0], a2f[mf], b1f[0], b1f[2]);
                    mma_s8(accC[mf][2 * ng + 1], a2f[mf], b1f[1], b1f[3]);
                }
            }
        }
    }

    // ---- epilogue ----
#pragma unroll
    for (int mf = 0; mf < 2; mf++) {
        const int r0 = m0 + wm + mf * 16 + (lane >> 2);
        const float sa0 = sA[r0], sa1 = sA[r0 + 8];
#pragma unroll
        for (int j = 0; j < 8; j++) {
            const int c = n0 + wn + j * 8 + ((lane & 3) << 1);
            const float sb0 = sB[c], sb1 = sB[c + 1];
            float bb0 = 0.0f, bb1 = 0.0f;
            if (bias) { bb0 = bias[c]; bb1 = bias[c + 1]; }
            float v0 = sa0 * sb0 * ((float)accM[mf][j][0] + (float)accC[mf][j][0] * 0.00390625f) + bb0;
            float v1 = sa0 * sb1 * ((float)accM[mf][j][1] + (float)accC[mf][j][1] * 0.00390625f) + bb1;
            float v2 = sa1 * sb0 * ((float)accM[mf][j][2] + (float)accC[mf][j][2] * 0.00390625f) + bb0;
            float v3 = sa1 * sb1 * ((float)accM[mf][j][3] + (float)accC[mf][j][3] * 0.00390625f) + bb1;
            if (GELU) {
                v0 = 0.5f * v0 * (1.0f + erff(v0 * 0.70710678118654752f));
                v1 = 0.5f * v1 * (1.0f + erff(v1 * 0.70710678118654752f));
                v2 = 0.5f * v2 * (1.0f + erff(v2 * 0.70710678118654752f));
                v3 = 0.5f * v3 * (1.0f + erff(v3 * 0.70710678118654752f));
            }
            *reinterpret_cast<float2*>(&C[(size_t)r0 * ldc + c])       = make_float2(v0, v1);
            *reinterpret_cast<float2*>(&C[(size_t)(r0 + 8) * ldc + c]) = make_float2(v2, v3);
        }
    }
}

// ============================================================================
// bf16x3 mma GEMM (validated R4) — used only for the two 1024^3 combine GEMMs
// ============================================================================
#define MT 256
#define NT 128
#define KC 64
#define STRIDE 72
#define A_TILE (MT*STRIDE*2)
#define B_TILE (NT*STRIDE*2)
#define STAGE  (2*A_TILE + 2*B_TILE)
#define SMEM_TOT (2*STAGE)

__global__ __launch_bounds__(256, 1)
void mma_gemm(const __nv_bfloat16* __restrict__ Ah, const __nv_bfloat16* __restrict__ Al,
              const __nv_bfloat16* __restrict__ Bh, const __nv_bfloat16* __restrict__ Bl,
              float* __restrict__ C, int ldc, int K)
{
    extern __shared__ char smem[];
    const uint32_t base = s2u(smem);
    const int tid  = threadIdx.x;
    const int wid  = tid >> 5;
    const int lane = tid & 31;
    const int m0 = blockIdx.y * MT;
    const int n0 = blockIdx.x * NT;
    const int warp_m0 = (wid & 3) * 64;
    const int warp_n0 = (wid >> 2) * 64;

    float acc[4][8][4];
#pragma unroll
    for (int i = 0; i < 4; i++)
#pragma unroll
        for (int j = 0; j < 8; j++)
#pragma unroll
            for (int q = 0; q < 4; q++) acc[i][j][q] = 0.0f;

    auto load_stage = [&](int s, int k0) {
        const uint32_t stA_h = base + s * STAGE;
        const uint32_t stA_l = stA_h + A_TILE;
        const uint32_t stB_h = stA_h + 2 * A_TILE;
        const uint32_t stB_l = stB_h + B_TILE;
        for (int i = tid; i < MT * 8; i += 256) {
            const int r = i >> 3, seg = i & 7;
            const uint32_t off = (uint32_t)(r * (STRIDE * 2) + seg * 16);
            const size_t gs = (size_t)(m0 + r) * K + k0 + seg * 8;
            cp16(stA_h + off, Ah + gs);
            cp16(stA_l + off, Al + gs);
        }
        for (int i = tid; i < NT * 8; i += 256) {
            const int r = i >> 3, seg = i & 7;
            const uint32_t off = (uint32_t)(r * (STRIDE * 2) + seg * 16);
            const size_t gs = (size_t)(n0 + r) * K + k0 + seg * 8;
            cp16(stB_h + off, Bh + gs);
            cp16(stB_l + off, Bl + gs);
        }
        asm volatile("cp.async.commit_group;" ::: "memory");
    };

    const int nk = K / KC;
    load_stage(0, 0);
    load_stage(1, KC);

    const int a_row = warp_m0 + (lane & 15);
    const int a_col = (lane >> 4) << 3;
    const int b_row = warp_n0 + (lane & 7) + ((lane >> 4) << 3);
    const int b_col = ((lane >> 3) & 1) << 3;

    for (int i = 0; i < nk; i++) {
        if (i + 1 < nk) asm volatile("cp.async.wait_group 1;" ::: "memory");
        else            asm volatile("cp.async.wait_group 0;" ::: "memory");
        __syncthreads();

        const uint32_t stA_h = base + (i & 1) * STAGE;
        const uint32_t stA_l = stA_h + A_TILE;
        const uint32_t stB_h = stA_h + 2 * A_TILE;
        const uint32_t stB_l = stB_h + B_TILE;

#pragma unroll
        for (int ks = 0; ks < 4; ks++) {
            const int k0 = ks * 16;
            uint32_t ah[4][4], al[4][4], bh[4][4], bl[4][4];
#pragma unroll
            for (int mf = 0; mf < 4; mf++) {
                const uint32_t ao = (uint32_t)((a_row + mf * 16) * STRIDE + k0 + a_col) * 2;
                ldm4(ah[mf], stA_h + ao);
                ldm4(al[mf], stA_l + ao);
            }
#pragma unroll
            for (int bp = 0; bp < 4; bp++) {
                const uint32_t bo = (uint32_t)((b_row + bp * 16) * STRIDE + k0 + b_col) * 2;
                ldm4(bh[bp], stB_h + bo);
                ldm4(bl[bp], stB_l + bo);
            }
#pragma unroll
            for (int mf = 0; mf < 4; mf++) {
#pragma unroll
                for (int bp = 0; bp < 4; bp++) {
                    mma16816(acc[mf][2 * bp + 0], ah[mf], &bh[bp][0]);
                    mma16816(acc[mf][2 * bp + 1], ah[mf], &bh[bp][2]);
                    mma16816(acc[mf][2 * bp + 0], ah[mf], &bl[bp][0]);
                    mma16816(acc[mf][2 * bp + 1], ah[mf], &bl[bp][2]);
                    mma16816(acc[mf][2 * bp + 0], al[mf], &bh[bp][0]);
                    mma16816(acc[mf][2 * bp + 1], al[mf], &bh[bp][2]);
                }
            }
        }

        __syncthreads();
        if (i + 2 < nk) load_stage(i & 1, (i + 2) * KC);
    }

    const int r_base = m0 + warp_m0 + (lane >> 2);
    const int c_base = n0 + warp_n0 + ((lane & 3) << 1);
#pragma unroll
    for (int mf = 0; mf < 4; mf++) {
#pragma unroll
        for (int nf = 0; nf < 8; nf++) {
            const int cc = c_base + nf * 8;
            const int row0 = r_base + mf * 16;
            *reinterpret_cast<float2*>(&C[(size_t)row0 * ldc + cc]) =
                make_float2(acc[mf][nf][0], acc[mf][nf][1]);
            *reinterpret_cast<float2*>(&C[(size_t)(row0 + 8) * ldc + cc]) =
                make_float2(acc[mf][nf][2], acc[mf][nf][3]);
        }
    }
}

// ---------------- bf16 split helpers (for combine GEMM inputs) ----------------
__global__ void split_kernel(const float* __restrict__ x,
                             __nv_bfloat16* __restrict__ h, __nv_bfloat16* __restrict__ l,
                             int n4)
{
    int i = blockIdx.x * blockDim.x + threadIdx.x;
    if (i < n4) {
        float4 v = reinterpret_cast<const float4*>(x)[i];
        __nv_bfloat162 h0, h1, l0, l1;
        h0.x = __float2bfloat16_rn(v.x); h0.y = __float2bfloat16_rn(v.y);
        h1.x = __float2bfloat16_rn(v.z); h1.y = __float2bfloat16_rn(v.w);
        l0.x = __float2bfloat16_rn(v.x - __bfloat162float(h0.x));
        l0.y = __float2bfloat16_rn(v.y - __bfloat162float(h0.y));
        l1.x = __float2bfloat16_rn(v.z - __bfloat162float(h1.x));
        l1.y = __float2bfloat16_rn(v.w - __bfloat162float(h1.y));
        reinterpret_cast<__nv_bfloat162*>(h + (size_t)i * 4)[0] = h0;
        reinterpret_cast<__nv_bfloat162*>(h + (size_t)i * 4)[1] = h1;
        reinterpret_cast<__nv_bfloat162*>(l + (size_t)i * 4)[0] = l0;
        reinterpret_cast<__nv_bfloat162*>(l + (size_t)i * 4)[1] = l1;
    }
}

__global__ void tsplit_kernel(const float* __restrict__ in, int R, int Ccols,
                              __nv_bfloat16* __restrict__ h, __nv_bfloat16* __restrict__ l)
{
    __shared__ float t[32][33];
    const int r0 = blockIdx.y * 32, c0 = blockIdx.x * 32;
    const int tx = threadIdx.x, ty = threadIdx.y;  // 32 x 8
#pragma unroll
    for (int i = 0; i < 4; i++)
        t[ty + 8 * i][tx] = in[(size_t)(r0 + ty + 8 * i) * Ccols + c0 + tx];
    __syncthreads();
#pragma unroll
    for (int i = 0; i < 4; i++) {
        const int rr = ty + 8 * i;
        const float v = t[tx][rr];
        const size_t o = (size_t)(c0 + rr) * R + r0 + tx;
        __nv_bfloat16 hh = __float2bfloat16_rn(v);
        h[o] = hh;
        l[o] = __float2bfloat16_rn(v - __bfloat162float(hh));
    }
}

// ---------------- per-row 2-level int8 quantization ----------------
__device__ __forceinline__ float qclamp(float t) {
    return fminf(fmaxf(t, -127.0f), 127.0f);
}

__global__ void quant_rows(const float* __restrict__ X, int K,
                           int8_t* __restrict__ Q1, int8_t* __restrict__ Q2,
                           float* __restrict__ S)
{
    __shared__ float red[8];
    const int row = blockIdx.x;
    const float* x = X + (size_t)row * K;
    const int tid = threadIdx.x;  // 256

    float am = 0.0f;
    for (int j = tid * 4; j < K; j += 1024) {
        float4 v = *reinterpret_cast<const float4*>(x + j);
        am = fmaxf(am, fmaxf(fmaxf(fabsf(v.x), fabsf(v.y)), fmaxf(fabsf(v.z), fabsf(v.w))));
    }
#pragma unroll
    for (int o = 16; o > 0; o >>= 1) am = fmaxf(am, __shfl_xor_sync(0xFFFFFFFFu, am, o));
    if ((tid & 31) == 0) red[tid >> 5] = am;
    __syncthreads();
    am = red[0];
#pragma unroll
    for (int w = 1; w < 8; w++) am = fmaxf(am, red[w]);
    am = fmaxf(am, 1e-20f);

    const float s    = am * (1.0f / 127.0f);
    const float inv  = 127.0f / am;
    const float inv2 = 256.0f / s;
    if (tid == 0) S[row] = s;

    for (int j = tid * 4; j < K; j += 1024) {
        float4 v = *reinterpret_cast<const float4*>(x + j);
        float q1x = qclamp(rintf(v.x * inv));
        float q1y = qclamp(rintf(v.y * inv));
        float q1z = qclamp(rintf(v.z * inv));
        float q1w = qclamp(rintf(v.w * inv));
        char4 a = make_char4((signed char)q1x, (signed char)q1y,
                             (signed char)q1z, (signed char)q1w);
        char4 b;
        b.x = (signed char)qclamp(rintf((v.x - q1x * s) * inv2));
        b.y = (signed char)qclamp(rintf((v.y - q1y * s) * inv2));
        b.z = (signed char)qclamp(rintf((v.z - q1z * s) * inv2));
        b.w = (signed char)qclamp(rintf((v.w - q1w * s) * inv2));
        *reinterpret_cast<char4*>(Q1 + (size_t)row * K + j) = a;
        *reinterpret_cast<char4*>(Q2 + (size_t)row * K + j) = b;
    }
}

// ---------------- combined bias: c[n] = sum_j wo[n,j]*bv[j] + bo[n] ----------------
__global__ void biasc_kernel(const float* __restrict__ wo, const float* __restrict__ bv,
                             const float* __restrict__ bo, float* __restrict__ c)
{
    __shared__ float red[4];
    const int n = blockIdx.x;
    const int tid = threadIdx.x;  // 128
    float s = 0.0f;
    for (int j = tid; j < DIM; j += 128) s += wo[(size_t)n * DIM + j] * bv[j];
#pragma unroll
    for (int o = 16; o > 0; o >>= 1) s += __shfl_xor_sync(0xFFFFFFFFu, s, o);
    if ((tid & 31) == 0) red[tid >> 5] = s;
    __syncthreads();
    if (tid == 0) c[n] = red[0] + red[1] + red[2] + red[3] + bo[n];
}

// ---------------- LayerNorm(2048) with bias add, fused int8 quantization ----------------
__global__ void ln_quant(const float* __restrict__ z,
                         const float* __restrict__ c1, const float* __restrict__ c2,
                         const float* __restrict__ g, const float* __restrict__ b,
                         int8_t* __restrict__ Q1, int8_t* __restrict__ Q2,
                         float* __restrict__ S)
{
    __shared__ float redS[8], redQ[8], redA[8];
    const size_t base = (size_t)blockIdx.x * DIM2;
    const int tid = threadIdx.x;  // 256

    float4 v0 = *reinterpret_cast<const float4*>(&z[base + tid * 4]);
    float4 v1 = *reinterpret_cast<const float4*>(&z[base + 1024 + tid * 4]);
    float4 cb0 = *reinterpret_cast<const float4*>(&c1[tid * 4]);
    float4 cb1 = *reinterpret_cast<const float4*>(&c2[tid * 4]);
    v0.x += cb0.x; v0.y += cb0.y; v0.z += cb0.z; v0.w += cb0.w;
    v1.x += cb1.x; v1.y += cb1.y; v1.z += cb1.z; v1.w += cb1.w;

    float s = v0.x + v0.y + v0.z + v0.w + v1.x + v1.y + v1.z + v1.w;
    float q = v0.x * v0.x + v0.y * v0.y + v0.z * v0.z + v0.w * v0.w
            + v1.x * v1.x + v1.y * v1.y + v1.z * v1.z + v1.w * v1.w;
#pragma unroll
    for (int o = 16; o > 0; o >>= 1) {
        s += __shfl_xor_sync(0xFFFFFFFFu, s, o);
        q += __shfl_xor_sync(0xFFFFFFFFu, q, o);
    }
    if ((tid & 31) == 0) { redS[tid >> 5] = s; redQ[tid >> 5] = q; }
    __syncthreads();
    float Ssum = 0.0f, Qsum = 0.0f;
#pragma unroll
    for (int w = 0; w < 8; w++) { Ssum += redS[w]; Qsum += redQ[w]; }

    const float mu = Ssum * (1.0f / DIM2);
    const float var = Qsum * (1.0f / DIM2) - mu * mu;
    const float rstd = rsqrtf(var + 1e-5f);

    float4 g0 = *reinterpret_cast<const float4*>(&g[tid * 4]);
    float4 g1 = *reinterpret_cast<const float4*>(&g[1024 + tid * 4]);
    float4 b0 = *reinterpret_cast<const float4*>(&b[tid * 4]);
    float4 b1 = *reinterpret_cast<const float4*>(&b[1024 + tid * 4]);

    v0.x = (v0.x - mu) * rstd * g0.x + b0.x;
    v0.y = (v0.y - mu) * rstd * g0.y + b0.y;
    v0.z = (v0.z - mu) * rstd * g0.z + b0.z;
    v0.w = (v0.w - mu) * rstd * g0.w + b0.w;
    v1.x = (v1.x - mu) * rstd * g1.x + b1.x;
    v1.y = (v1.y - mu) * rstd * g1.y + b1.y;
    v1.z = (v1.z - mu) * rstd * g1.z + b1.z;
    v1.w = (v1.w - mu) * rstd * g1.w + b1.w;

    // row amax of normalized values
    float am = fmaxf(fmaxf(fmaxf(fabsf(v0.x), fabsf(v0.y)), fmaxf(fabsf(v0.z), fabsf(v0.w))),
                     fmaxf(fmaxf(fabsf(v1.x), fabsf(v1.y)), fmaxf(fabsf(v1.z), fabsf(v1.w))));
#pragma unroll
    for (int o = 16; o > 0; o >>= 1) am = fmaxf(am, __shfl_xor_sync(0xFFFFFFFFu, am, o));
    if ((tid & 31) == 0) redA[tid >> 5] = am;
    __syncthreads();
    am = redA[0];
#pragma unroll
    for (int w = 1; w < 8; w++) am = fmaxf(am, redA[w]);
    am = fmaxf(am, 1e-20f);

    const float sc   = am * (1.0f / 127.0f);
    const float inv  = 127.0f / am;
    const float inv2 = 256.0f / sc;
    if (tid == 0) S[blockIdx.x] = sc;

    float q1x, q1y, q1z, q1w;
    char4 a, bq;
    // first half
    q1x = qclamp(rintf(v0.x * inv)); q1y = qclamp(rintf(v0.y * inv));
    q1z = qclamp(rintf(v0.z * inv)); q1w = qclamp(rintf(v0.w * inv));
    a = make_char4((signed char)q1x, (signed char)q1y, (signed char)q1z, (signed char)q1w);
    bq.x = (signed char)qclamp(rintf((v0.x - q1x * sc) * inv2));
    bq.y = (signed char)qclamp(rintf((v0.y - q1y * sc) * inv2));
    bq.z = (signed char)qclamp(rintf((v0.z - q1z * sc) * inv2));
    bq.w = (signed char)qclamp(rintf((v0.w - q1w * sc) * inv2));
    *reinterpret_cast<char4*>(Q1 + base + tid * 4) = a;
    *reinterpret_cast<char4*>(Q2 + base + tid * 4) = bq;
    // second half
    q1x = qclamp(rintf(v1.x * inv)); q1y = qclamp(rintf(v1.y * inv));
    q1z = qclamp(rintf(v1.z * inv)); q1w = qclamp(rintf(v1.w * inv));
    a = make_char4((signed char)q1x, (signed char)q1y, (signed char)q1z, (signed char)q1w);
    bq.x = (signed char)qclamp(rintf((v1.x - q1x * sc) * inv2));
    bq.y = (signed char)qclamp(rintf((v1.y - q1y * sc) * inv2));
    bq.z = (signed char)qclamp(rintf((v1.z - q1z * sc) * inv2));
    bq.w = (signed char)qclamp(rintf((v1.w - q1w * sc) * inv2));
    *reinterpret_cast<char4*>(Q1 + base + 1024 + tid * 4) = a;
    *reinterpret_cast<char4*>(Q2 + base + 1024 + tid * 4) = bq;
}

// ---------------- launch ----------------
extern "C" void kernel_launch(void* const* d_in, const int* in_sizes, int n_in,
                              void* d_out, int out_size)
{
    const float* x_u    = (const float*)d_in[0];
    const float* x_m    = (const float*)d_in[1];
    const float* w_qkv1 = (const float*)d_in[2];
    const float* b_qkv1 = (const float*)d_in[3];
    const float* w_o1   = (const float*)d_in[4];
    const float* b_o1   = (const float*)d_in[5];
    const float* w_qkv2 = (const float*)d_in[6];
    const float* b_qkv2 = (const float*)d_in[7];
    const float* w_o2   = (const float*)d_in[8];
    const float* b_o2   = (const float*)d_in[9];
    const float* ln_g   = (const float*)d_in[10];
    const float* ln_b   = (const float*)d_in[11];
    const float* w_proj = (const float*)d_in[12];
    const float* b_proj = (const float*)d_in[13];
    float* out = (float*)d_out;

    const float* wv1 = w_qkv1 + (size_t)2 * DIM * DIM;
    const float* bv1 = b_qkv1 + 2 * DIM;
    const float* wv2 = w_qkv2 + (size_t)2 * DIM * DIM;
    const float* bv2 = b_qkv2 + 2 * DIM;

    int8_t *xu1, *xu2, *xm1, *xm2, *zn1, *zn2, *B1q1, *B1q2, *B2q1, *B2q2, *wp1, *wp2;
    float *sxu, *sxm, *szn, *sB1, *sB2, *swp, *z, *B1t, *B2t, *c1, *c2;
    __nv_bfloat16 *wo1_h, *wo1_l, *wo2_h, *wo2_l, *wv1t_h, *wv1t_l, *wv2t_h, *wv2t_l;

    cudaGetSymbolAddress((void**)&xu1, g_xu1);   cudaGetSymbolAddress((void**)&xu2, g_xu2);
    cudaGetSymbolAddress((void**)&xm1, g_xm1);   cudaGetSymbolAddress((void**)&xm2, g_xm2);
    cudaGetSymbolAddress((void**)&zn1, g_zn1);   cudaGetSymbolAddress((void**)&zn2, g_zn2);
    cudaGetSymbolAddress((void**)&B1q1, g_B1q1); cudaGetSymbolAddress((void**)&B1q2, g_B1q2);
    cudaGetSymbolAddress((void**)&B2q1, g_B2q1); cudaGetSymbolAddress((void**)&B2q2, g_B2q2);
    cudaGetSymbolAddress((void**)&wp1, g_wp1);   cudaGetSymbolAddress((void**)&wp2, g_wp2);
    cudaGetSymbolAddress((void**)&sxu, g_sxu);   cudaGetSymbolAddress((void**)&sxm, g_sxm);
    cudaGetSymbolAddress((void**)&szn, g_szn);
    cudaGetSymbolAddress((void**)&sB1, g_sB1);   cudaGetSymbolAddress((void**)&sB2, g_sB2);
    cudaGetSymbolAddress((void**)&swp, g_swp);
    cudaGetSymbolAddress((void**)&z, g_z);
    cudaGetSymbolAddress((void**)&B1t, g_B1t);   cudaGetSymbolAddress((void**)&B2t, g_B2t);
    cudaGetSymbolAddress((void**)&c1, g_c1);     cudaGetSymbolAddress((void**)&c2, g_c2);
    cudaGetSymbolAddress((void**)&wo1_h, g_wo1_hi);   cudaGetSymbolAddress((void**)&wo1_l, g_wo1_lo);
    cudaGetSymbolAddress((void**)&wo2_h, g_wo2_hi);   cudaGetSymbolAddress((void**)&wo2_l, g_wo2_lo);
    cudaGetSymbolAddress((void**)&wv1t_h, g_wv1t_hi); cudaGetSymbolAddress((void**)&wv1t_l, g_wv1t_lo);
    cudaGetSymbolAddress((void**)&wv2t_h, g_wv2t_hi); cudaGetSymbolAddress((void**)&wv2t_l, g_wv2t_lo);

    cudaFuncSetAttribute(mma_gemm, cudaFuncAttributeMaxDynamicSharedMemorySize, SMEM_TOT);
    cudaFuncSetAttribute(qgemm<false>, cudaFuncAttributeMaxDynamicSharedMemorySize, QSMEM);
    cudaFuncSetAttribute(qgemm<true>,  cudaFuncAttributeMaxDynamicSharedMemorySize, QSMEM);

    const dim3 gridQz(DIM / 128, BATCH / 128);    // (8, 128)
    const dim3 gridW(DIM / NT, DIM / MT);         // (8, 4)

    // ---- path 1 chain (int8 z1 GEMM is launch #6 → profiled by ncu -s 5) ----
    split_kernel<<<(DIM * DIM / 4) / 256, 256>>>(w_o1, wo1_h, wo1_l, DIM * DIM / 4);   // 1
    tsplit_kernel<<<dim3(32, 32), dim3(32, 8)>>>(wv1, DIM, DIM, wv1t_h, wv1t_l);       // 2
    mma_gemm<<<gridW, 256, SMEM_TOT>>>(wo1_h, wo1_l, wv1t_h, wv1t_l, B1t, DIM, DIM);   // 3
    quant_rows<<<DIM, 256>>>(B1t, DIM, B1q1, B1q2, sB1);                               // 4
    quant_rows<<<BATCH, 256>>>(x_u, DIM, xu1, xu2, sxu);                               // 5
    qgemm<false><<<gridQz, 256, QSMEM>>>(xu1, xu2, sxu, B1q1, B1q2, sB1,
                                         z, DIM2, nullptr, DIM);                       // 6

    // ---- path 2 chain ----
    split_kernel<<<(DIM * DIM / 4) / 256, 256>>>(w_o2, wo2_h, wo2_l, DIM * DIM / 4);
    tsplit_kernel<<<dim3(32, 32), dim3(32, 8)>>>(wv2, DIM, DIM, wv2t_h, wv2t_l);
    mma_gemm<<<gridW, 256, SMEM_TOT>>>(wo2_h, wo2_l, wv2t_h, wv2t_l, B2t, DIM, DIM);
    quant_rows<<<DIM, 256>>>(B2t, DIM, B2q1, B2q2, sB2);
    quant_rows<<<BATCH, 256>>>(x_m, DIM, xm1, xm2, sxm);
    qgemm<false><<<gridQz, 256, QSMEM>>>(xm1, xm2, sxm, B2q1, B2q2, sB2,
                                         z + DIM, DIM2, nullptr, DIM);

    // ---- combined biases (added inside LN) ----
    biasc_kernel<<<DIM, 128>>>(w_o1, bv1, b_o1, c1);
    biasc_kernel<<<DIM, 128>>>(w_o2, bv2, b_o2, c2);

    // ---- LayerNorm(+bias) + int8 quantization ----
    ln_quant<<<BATCH, 256>>>(z, c1, c2, ln_g, ln_b, zn1, zn2, szn);

    // ---- proj weights quant + final GEMM with bias + exact GELU ----
    quant_rows<<<DIM, 256>>>(w_proj, DIM2, wp1, wp2, swp);
    qgemm<true><<<gridQz, 256, QSMEM>>>(zn1, zn2, szn, wp1, wp2, swp,
                                        out, DIM, b_proj, DIM2);
}

// round 9
// speedup vs baseline: 1.6346x; 1.0006x over previous
#include <cuda_runtime.h>
#include <cuda_bf16.h>
#include <math.h>
#include <stdint.h>

#define BATCH 16384
#define DIM   1024
#define DIM2  2048

// ---------------- scratch (device globals; no allocs) ----------------
// int8 quantized operands (2-level) + per-row scales
__device__ int8_t g_xu1[(size_t)BATCH*DIM],  g_xu2[(size_t)BATCH*DIM];
__device__ int8_t g_xm1[(size_t)BATCH*DIM],  g_xm2[(size_t)BATCH*DIM];
__device__ int8_t g_zn1[(size_t)BATCH*DIM2], g_zn2[(size_t)BATCH*DIM2];
__device__ int8_t g_B1q1[DIM*DIM], g_B1q2[DIM*DIM];
__device__ int8_t g_B2q1[DIM*DIM], g_B2q2[DIM*DIM];
__device__ int8_t g_wp1[DIM*DIM2], g_wp2[DIM*DIM2];
__device__ float  g_sxu[BATCH], g_sxm[BATCH], g_szn[BATCH];
__device__ float  g_sB1[DIM], g_sB2[DIM], g_swp[DIM];
// fp32 intermediates
__device__ float  g_z[(size_t)BATCH*DIM2];
__device__ float  g_B1t[DIM*DIM], g_B2t[DIM*DIM];
__device__ float  g_c1[DIM], g_c2[DIM];
// bf16 hi/lo for the tiny weight-combine GEMMs
__device__ __nv_bfloat16 g_wo1_hi[DIM*DIM], g_wo1_lo[DIM*DIM];
__device__ __nv_bfloat16 g_wo2_hi[DIM*DIM], g_wo2_lo[DIM*DIM];
__device__ __nv_bfloat16 g_wv1t_hi[DIM*DIM], g_wv1t_lo[DIM*DIM];
__device__ __nv_bfloat16 g_wv2t_hi[DIM*DIM], g_wv2t_lo[DIM*DIM];

// ---------------- low-level helpers (sm_80-baseline PTX only) ----------------
__device__ __forceinline__ uint32_t s2u(const void* p) {
    uint32_t a;
    asm("{ .reg .u64 t; cvta.to.shared.u64 t, %1; cvt.u32.u64 %0, t; }" : "=r"(a) : "l"(p));
    return a;
}
__device__ __forceinline__ void cp16(uint32_t d, const void* s) {
    asm volatile("cp.async.cg.shared.global [%0], [%1], 16;" :: "r"(d), "l"(s));
}
__device__ __forceinline__ void ldm4(uint32_t* r, uint32_t addr) {
    asm volatile("ldmatrix.sync.aligned.m8n8.x4.shared.b16 {%0,%1,%2,%3}, [%4];"
                 : "=r"(r[0]), "=r"(r[1]), "=r"(r[2]), "=r"(r[3]) : "r"(addr));
}
__device__ __forceinline__ void mma16816(float* d, const uint32_t* a, const uint32_t* b) {
    asm volatile(
        "mma.sync.aligned.m16n8k16.row.col.f32.bf16.bf16.f32 "
        "{%0,%1,%2,%3}, {%4,%5,%6,%7}, {%8,%9}, {%0,%1,%2,%3};"
        : "+f"(d[0]), "+f"(d[1]), "+f"(d[2]), "+f"(d[3])
        : "r"(a[0]), "r"(a[1]), "r"(a[2]), "r"(a[3]), "r"(b[0]), "r"(b[1]));
}
__device__ __forceinline__ void mma_s8(int* d, const uint32_t* a, uint32_t b0, uint32_t b1) {
    asm volatile(
        "mma.sync.aligned.m16n8k32.row.col.s32.s8.s8.s32 "
        "{%0,%1,%2,%3}, {%4,%5,%6,%7}, {%8,%9}, {%0,%1,%2,%3};"
        : "+r"(d[0]), "+r"(d[1]), "+r"(d[2]), "+r"(d[3])
        : "r"(a[0]), "r"(a[1]), "r"(a[2]), "r"(a[3]), "r"(b0), "r"(b1));
}

// ============================================================================
// INT8 3-pass GEMM: C[m,n] = sA[m]*sB[n]*( q1A.q1B + (q1A.q2B + q2A.q1B)/256 )
// A: [M,K] int8 (A1, A2), B: [N,K] int8 (B1, B2), both K-major.
// CTA 128x128, K-chunk 128, 3-stage cp.async, 8 warps, warp tile 32x64.
// ============================================================================
#define QPITCH 144
#define QTILE  (128*QPITCH)      // 18432 B per (matrix,level)
#define QSTAGE (4*QTILE)         // 73728 B
#define QSMEM  (3*QSTAGE)        // 221184 B

template <bool GELU>
__global__ __launch_bounds__(256, 1)
void qgemm(const int8_t* __restrict__ A1, const int8_t* __restrict__ A2,
           const float* __restrict__ sA,
           const int8_t* __restrict__ B1, const int8_t* __restrict__ B2,
           const float* __restrict__ sB,
           float* __restrict__ C, int ldc, const float* __restrict__ bias, int K)
{
    extern __shared__ char smem[];
    const uint32_t base = s2u(smem);
    const int tid = threadIdx.x, wid = tid >> 5, lane = tid & 31;
    const int m0 = blockIdx.y * 128, n0 = blockIdx.x * 128;
    const int wm = (wid & 3) * 32;          // warp M offset (4 warps x 32)
    const int wn = (wid >> 2) * 64;         // warp N offset (2 warps x 64)

    int accM[2][8][4], accC[2][8][4];
#pragma unroll
    for (int a = 0; a < 2; a++)
#pragma unroll
        for (int j = 0; j < 8; j++)
#pragma unroll
            for (int q = 0; q < 4; q++) { accM[a][j][q] = 0; accC[a][j][q] = 0; }

    auto load_stage = [&](int s, int k0) {
        const uint32_t st = base + s * QSTAGE;
        for (int i = tid; i < 1024; i += 256) {
            const int r = i >> 3, seg = i & 7;
            const uint32_t off = (uint32_t)(r * QPITCH + seg * 16);
            const size_t ga = (size_t)(m0 + r) * K + k0 + seg * 16;
            const size_t gb = (size_t)(n0 + r) * K + k0 + seg * 16;
            cp16(st + off,              A1 + ga);
            cp16(st + QTILE + off,      A2 + ga);
            cp16(st + 2 * QTILE + off,  B1 + gb);
            cp16(st + 3 * QTILE + off,  B2 + gb);
        }
        asm volatile("cp.async.commit_group;" ::: "memory");
    };

    const int nk = K >> 7;
    load_stage(0, 0);
    load_stage(1, 128);

    const uint32_t aoff = (uint32_t)((wm + (lane & 15)) * QPITCH + ((lane >> 4) << 4));
    const uint32_t boff = (uint32_t)((wn + (lane & 15)) * QPITCH + ((lane >> 4) << 4));

    for (int i = 0; i < nk; i++) {
        if (i + 2 <= nk) asm volatile("cp.async.wait_group 1;" ::: "memory");
        else             asm volatile("cp.async.wait_group 0;" ::: "memory");
        __syncthreads();
        if (i + 2 < nk) load_stage((i + 2) % 3, (i + 2) * 128);

        const uint32_t st = base + (i % 3) * QSTAGE;
#pragma unroll
        for (int ks = 0; ks < 4; ks++) {
            const uint32_t kb = ks * 32;
            uint32_t a1f[2][4], a2f[2][4];
#pragma unroll
            for (int mf = 0; mf < 2; mf++) {
                const uint32_t ao = aoff + (uint32_t)(mf * 16 * QPITCH) + kb;
                ldm4(a1f[mf], st + ao);
                ldm4(a2f[mf], st + QTILE + ao);
            }
#pragma unroll
            for (int ng = 0; ng < 4; ng++) {
                uint32_t b1f[4], b2f[4];
                const uint32_t bo = boff + (uint32_t)(ng * 16 * QPITCH) + kb;
                ldm4(b1f, st + 2 * QTILE + bo);
                ldm4(b2f, st + 3 * QTILE + bo);
#pragma unroll
                for (int mf = 0; mf < 2; mf++) {
                    mma_s8(accM[mf][2 * ng + 0], a1f[mf], b1f[0], b1f[2]);
                    mma_s8(accM[mf][2 * ng + 1], a1f[mf], b1f[1], b1f[3]);
                    mma_s8(accC[mf][2 * ng + 0], a1f[mf], b2f[0], b2f[2]);
                    mma_s8(accC[mf][2 * ng + 1], a1f[mf], b2f[1], b2f[3]);
                    mma_s8(accC[mf][2 * ng + 0], a2f[mf], b1f[0], b1f[2]);
                    mma_s8(accC[mf][2 * ng + 1], a2f[mf], b1f[1], b1f[3]);
                }
            }
        }
    }

    // ---- epilogue ----
#pragma unroll
    for (int mf = 0; mf < 2; mf++) {
        const int r0 = m0 + wm + mf * 16 + (lane >> 2);
        const float sa0 = sA[r0], sa1 = sA[r0 + 8];
#pragma unroll
        for (int j = 0; j < 8; j++) {
            const int c = n0 + wn + j * 8 + ((lane & 3) << 1);
            const float sb0 = sB[c], sb1 = sB[c + 1];
            float bb0 = 0.0f, bb1 = 0.0f;
            if (bias) { bb0 = bias[c]; bb1 = bias[c + 1]; }
            float v0 = sa0 * sb0 * ((float)accM[mf][j][0] + (float)accC[mf][j][0] * 0.00390625f) + bb0;
            float v1 = sa0 * sb1 * ((float)accM[mf][j][1] + (float)accC[mf][j][1] * 0.00390625f) + bb1;
            float v2 = sa1 * sb0 * ((float)accM[mf][j][2] + (float)accC[mf][j][2] * 0.00390625f) + bb0;
            float v3 = sa1 * sb1 * ((float)accM[mf][j][3] + (float)accC[mf][j][3] * 0.00390625f) + bb1;
            if (GELU) {
                v0 = 0.5f * v0 * (1.0f + erff(v0 * 0.70710678118654752f));
                v1 = 0.5f * v1 * (1.0f + erff(v1 * 0.70710678118654752f));
                v2 = 0.5f * v2 * (1.0f + erff(v2 * 0.70710678118654752f));
                v3 = 0.5f * v3 * (1.0f + erff(v3 * 0.70710678118654752f));
            }
            *reinterpret_cast<float2*>(&C[(size_t)r0 * ldc + c])       = make_float2(v0, v1);
            *reinterpret_cast<float2*>(&C[(size_t)(r0 + 8) * ldc + c]) = make_float2(v2, v3);
        }
    }
}

// ============================================================================
// bf16x3 mma GEMM (validated R4) — used only for the two 1024^3 combine GEMMs
// ============================================================================
#define MT 256
#define NT 128
#define KC 64
#define STRIDE 72
#define A_TILE (MT*STRIDE*2)
#define B_TILE (NT*STRIDE*2)
#define STAGE  (2*A_TILE + 2*B_TILE)
#define SMEM_TOT (2*STAGE)

__global__ __launch_bounds__(256, 1)
void mma_gemm(const __nv_bfloat16* __restrict__ Ah, const __nv_bfloat16* __restrict__ Al,
              const __nv_bfloat16* __restrict__ Bh, const __nv_bfloat16* __restrict__ Bl,
              float* __restrict__ C, int ldc, int K)
{
    extern __shared__ char smem[];
    const uint32_t base = s2u(smem);
    const int tid  = threadIdx.x;
    const int wid  = tid >> 5;
    const int lane = tid & 31;
    const int m0 = blockIdx.y * MT;
    const int n0 = blockIdx.x * NT;
    const int warp_m0 = (wid & 3) * 64;
    const int warp_n0 = (wid >> 2) * 64;

    float acc[4][8][4];
#pragma unroll
    for (int i = 0; i < 4; i++)
#pragma unroll
        for (int j = 0; j < 8; j++)
#pragma unroll
            for (int q = 0; q < 4; q++) acc[i][j][q] = 0.0f;

    auto load_stage = [&](int s, int k0) {
        const uint32_t stA_h = base + s * STAGE;
        const uint32_t stA_l = stA_h + A_TILE;
        const uint32_t stB_h = stA_h + 2 * A_TILE;
        const uint32_t stB_l = stB_h + B_TILE;
        for (int i = tid; i < MT * 8; i += 256) {
            const int r = i >> 3, seg = i & 7;
            const uint32_t off = (uint32_t)(r * (STRIDE * 2) + seg * 16);
            const size_t gs = (size_t)(m0 + r) * K + k0 + seg * 8;
            cp16(stA_h + off, Ah + gs);
            cp16(stA_l + off, Al + gs);
        }
        for (int i = tid; i < NT * 8; i += 256) {
            const int r = i >> 3, seg = i & 7;
            const uint32_t off = (uint32_t)(r * (STRIDE * 2) + seg * 16);
            const size_t gs = (size_t)(n0 + r) * K + k0 + seg * 8;
            cp16(stB_h + off, Bh + gs);
            cp16(stB_l + off, Bl + gs);
        }
        asm volatile("cp.async.commit_group;" ::: "memory");
    };

    const int nk = K / KC;
    load_stage(0, 0);
    load_stage(1, KC);

    const int a_row = warp_m0 + (lane & 15);
    const int a_col = (lane >> 4) << 3;
    const int b_row = warp_n0 + (lane & 7) + ((lane >> 4) << 3);
    const int b_col = ((lane >> 3) & 1) << 3;

    for (int i = 0; i < nk; i++) {
        if (i + 1 < nk) asm volatile("cp.async.wait_group 1;" ::: "memory");
        else            asm volatile("cp.async.wait_group 0;" ::: "memory");
        __syncthreads();

        const uint32_t stA_h = base + (i & 1) * STAGE;
        const uint32_t stA_l = stA_h + A_TILE;
        const uint32_t stB_h = stA_h + 2 * A_TILE;
        const uint32_t stB_l = stB_h + B_TILE;

#pragma unroll
        for (int ks = 0; ks < 4; ks++) {
            const int k0 = ks * 16;
            uint32_t ah[4][4], al[4][4], bh[4][4], bl[4][4];
#pragma unroll
            for (int mf = 0; mf < 4; mf++) {
                const uint32_t ao = (uint32_t)((a_row + mf * 16) * STRIDE + k0 + a_col) * 2;
                ldm4(ah[mf], stA_h + ao);
                ldm4(al[mf], stA_l + ao);
            }
#pragma unroll
            for (int bp = 0; bp < 4; bp++) {
                const uint32_t bo = (uint32_t)((b_row + bp * 16) * STRIDE + k0 + b_col) * 2;
                ldm4(bh[bp], stB_h + bo);
                ldm4(bl[bp], stB_l + bo);
            }
#pragma unroll
            for (int mf = 0; mf < 4; mf++) {
#pragma unroll
                for (int bp = 0; bp < 4; bp++) {
                    mma16816(acc[mf][2 * bp + 0], ah[mf], &bh[bp][0]);
                    mma16816(acc[mf][2 * bp + 1], ah[mf], &bh[bp][2]);
                    mma16816(acc[mf][2 * bp + 0], ah[mf], &bl[bp][0]);
                    mma16816(acc[mf][2 * bp + 1], ah[mf], &bl[bp][2]);
                    mma16816(acc[mf][2 * bp + 0], al[mf], &bh[bp][0]);
                    mma16816(acc[mf][2 * bp + 1], al[mf], &bh[bp][2]);
                }
            }
        }

        __syncthreads();
        if (i + 2 < nk) load_stage(i & 1, (i + 2) * KC);
    }

    const int r_base = m0 + warp_m0 + (lane >> 2);
    const int c_base = n0 + warp_n0 + ((lane & 3) << 1);
#pragma unroll
    for (int mf = 0; mf < 4; mf++) {
#pragma unroll
        for (int nf = 0; nf < 8; nf++) {
            const int cc = c_base + nf * 8;
            const int row0 = r_base + mf * 16;
            *reinterpret_cast<float2*>(&C[(size_t)row0 * ldc + cc]) =
                make_float2(acc[mf][nf][0], acc[mf][nf][1]);
            *reinterpret_cast<float2*>(&C[(size_t)(row0 + 8) * ldc + cc]) =
                make_float2(acc[mf][nf][2], acc[mf][nf][3]);
        }
    }
}

// ---------------- bf16 split helpers (for combine GEMM inputs) ----------------
__global__ void split_kernel(const float* __restrict__ x,
                             __nv_bfloat16* __restrict__ h, __nv_bfloat16* __restrict__ l,
                             int n4)
{
    int i = blockIdx.x * blockDim.x + threadIdx.x;
    if (i < n4) {
        float4 v = reinterpret_cast<const float4*>(x)[i];
        __nv_bfloat162 h0, h1, l0, l1;
        h0.x = __float2bfloat16_rn(v.x); h0.y = __float2bfloat16_rn(v.y);
        h1.x = __float2bfloat16_rn(v.z); h1.y = __float2bfloat16_rn(v.w);
        l0.x = __float2bfloat16_rn(v.x - __bfloat162float(h0.x));
        l0.y = __float2bfloat16_rn(v.y - __bfloat162float(h0.y));
        l1.x = __float2bfloat16_rn(v.z - __bfloat162float(h1.x));
        l1.y = __float2bfloat16_rn(v.w - __bfloat162float(h1.y));
        reinterpret_cast<__nv_bfloat162*>(h + (size_t)i * 4)[0] = h0;
        reinterpret_cast<__nv_bfloat162*>(h + (size_t)i * 4)[1] = h1;
        reinterpret_cast<__nv_bfloat162*>(l + (size_t)i * 4)[0] = l0;
        reinterpret_cast<__nv_bfloat162*>(l + (size_t)i * 4)[1] = l1;
    }
}

__global__ void tsplit_kernel(const float* __restrict__ in, int R, int Ccols,
                              __nv_bfloat16* __restrict__ h, __nv_bfloat16* __restrict__ l)
{
    __shared__ float t[32][33];
    const int r0 = blockIdx.y * 32, c0 = blockIdx.x * 32;
    const int tx = threadIdx.x, ty = threadIdx.y;  // 32 x 8
#pragma unroll
    for (int i = 0; i < 4; i++)
        t[ty + 8 * i][tx] = in[(size_t)(r0 + ty + 8 * i) * Ccols + c0 + tx];
    __syncthreads();
#pragma unroll
    for (int i = 0; i < 4; i++) {
        const int rr = ty + 8 * i;
        const float v = t[tx][rr];
        const size_t o = (size_t)(c0 + rr) * R + r0 + tx;
        __nv_bfloat16 hh = __float2bfloat16_rn(v);
        h[o] = hh;
        l[o] = __float2bfloat16_rn(v - __bfloat162float(hh));
    }
}

// ---------------- per-row 2-level int8 quantization ----------------
__device__ __forceinline__ float qclamp(float t) {
    return fminf(fmaxf(t, -127.0f), 127.0f);
}

__global__ void quant_rows(const float* __restrict__ X, int K,
                           int8_t* __restrict__ Q1, int8_t* __restrict__ Q2,
                           float* __restrict__ S)
{
    __shared__ float red[8];
    const int row = blockIdx.x;
    const float* x = X + (size_t)row * K;
    const int tid = threadIdx.x;  // 256

    float am = 0.0f;
    for (int j = tid * 4; j < K; j += 1024) {
        float4 v = *reinterpret_cast<const float4*>(x + j);
        am = fmaxf(am, fmaxf(fmaxf(fabsf(v.x), fabsf(v.y)), fmaxf(fabsf(v.z), fabsf(v.w))));
    }
#pragma unroll
    for (int o = 16; o > 0; o >>= 1) am = fmaxf(am, __shfl_xor_sync(0xFFFFFFFFu, am, o));
    if ((tid & 31) == 0) red[tid >> 5] = am;
    __syncthreads();
    am = red[0];
#pragma unroll
    for (int w = 1; w < 8; w++) am = fmaxf(am, red[w]);
    am = fmaxf(am, 1e-20f);

    const float s    = am * (1.0f / 127.0f);
    const float inv  = 127.0f / am;
    const float inv2 = 256.0f / s;
    if (tid == 0) S[row] = s;

    for (int j = tid * 4; j < K; j += 1024) {
        float4 v = *reinterpret_cast<const float4*>(x + j);
        float q1x = qclamp(rintf(v.x * inv));
        float q1y = qclamp(rintf(v.y * inv));
        float q1z = qclamp(rintf(v.z * inv));
        float q1w = qclamp(rintf(v.w * inv));
        char4 a = make_char4((signed char)q1x, (signed char)q1y,
                             (signed char)q1z, (signed char)q1w);
        char4 b;
        b.x = (signed char)qclamp(rintf((v.x - q1x * s) * inv2));
        b.y = (signed char)qclamp(rintf((v.y - q1y * s) * inv2));
        b.z = (signed char)qclamp(rintf((v.z - q1z * s) * inv2));
        b.w = (signed char)qclamp(rintf((v.w - q1w * s) * inv2));
        *reinterpret_cast<char4*>(Q1 + (size_t)row * K + j) = a;
        *reinterpret_cast<char4*>(Q2 + (size_t)row * K + j) = b;
    }
}

// ---------------- combined bias: c[n] = sum_j wo[n,j]*bv[j] + bo[n] ----------------
__global__ void biasc_kernel(const float* __restrict__ wo, const float* __restrict__ bv,
                             const float* __restrict__ bo, float* __restrict__ c)
{
    __shared__ float red[4];
    const int n = blockIdx.x;
    const int tid = threadIdx.x;  // 128
    float s = 0.0f;
    for (int j = tid; j < DIM; j += 128) s += wo[(size_t)n * DIM + j] * bv[j];
#pragma unroll
    for (int o = 16; o > 0; o >>= 1) s += __shfl_xor_sync(0xFFFFFFFFu, s, o);
    if ((tid & 31) == 0) red[tid >> 5] = s;
    __syncthreads();
    if (tid == 0) c[n] = red[0] + red[1] + red[2] + red[3] + bo[n];
}

// ---------------- LayerNorm(2048) with bias add, fused int8 quantization ----------------
__global__ void ln_quant(const float* __restrict__ z,
                         const float* __restrict__ c1, const float* __restrict__ c2,
                         const float* __restrict__ g, const float* __restrict__ b,
                         int8_t* __restrict__ Q1, int8_t* __restrict__ Q2,
                         float* __restrict__ S)
{
    __shared__ float redS[8], redQ[8], redA[8];
    const size_t base = (size_t)blockIdx.x * DIM2;
    const int tid = threadIdx.x;  // 256

    float4 v0 = *reinterpret_cast<const float4*>(&z[base + tid * 4]);
    float4 v1 = *reinterpret_cast<const float4*>(&z[base + 1024 + tid * 4]);
    float4 cb0 = *reinterpret_cast<const float4*>(&c1[tid * 4]);
    float4 cb1 = *reinterpret_cast<const float4*>(&c2[tid * 4]);
    v0.x += cb0.x; v0.y += cb0.y; v0.z += cb0.z; v0.w += cb0.w;
    v1.x += cb1.x; v1.y += cb1.y; v1.z += cb1.z; v1.w += cb1.w;

    float s = v0.x + v0.y + v0.z + v0.w + v1.x + v1.y + v1.z + v1.w;
    float q = v0.x * v0.x + v0.y * v0.y + v0.z * v0.z + v0.w * v0.w
            + v1.x * v1.x + v1.y * v1.y + v1.z * v1.z + v1.w * v1.w;
#pragma unroll
    for (int o = 16; o > 0; o >>= 1) {
        s += __shfl_xor_sync(0xFFFFFFFFu, s, o);
        q += __shfl_xor_sync(0xFFFFFFFFu, q, o);
    }
    if ((tid & 31) == 0) { redS[tid >> 5] = s; redQ[tid >> 5] = q; }
    __syncthreads();
    float Ssum = 0.0f, Qsum = 0.0f;
#pragma unroll
    for (int w = 0; w < 8; w++) { Ssum += redS[w]; Qsum += redQ[w]; }

    const float mu = Ssum * (1.0f / DIM2);
    const float var = Qsum * (1.0f / DIM2) - mu * mu;
    const float rstd = rsqrtf(var + 1e-5f);

    float4 g0 = *reinterpret_cast<const float4*>(&g[tid * 4]);
    float4 g1 = *reinterpret_cast<const float4*>(&g[1024 + tid * 4]);
    float4 b0 = *reinterpret_cast<const float4*>(&b[tid * 4]);
    float4 b1 = *reinterpret_cast<const float4*>(&b[1024 + tid * 4]);

    v0.x = (v0.x - mu) * rstd * g0.x + b0.x;
    v0.y = (v0.y - mu) * rstd * g0.y + b0.y;
    v0.z = (v0.z - mu) * rstd * g0.z + b0.z;
    v0.w = (v0.w - mu) * rstd * g0.w + b0.w;
    v1.x = (v1.x - mu) * rstd * g1.x + b1.x;
    v1.y = (v1.y - mu) * rstd * g1.y + b1.y;
    v1.z = (v1.z - mu) * rstd * g1.z + b1.z;
    v1.w = (v1.w - mu) * rstd * g1.w + b1.w;

    // row amax of normalized values
    float am = fmaxf(fmaxf(fmaxf(fabsf(v0.x), fabsf(v0.y)), fmaxf(fabsf(v0.z), fabsf(v0.w))),
                     fmaxf(fmaxf(fabsf(v1.x), fabsf(v1.y)), fmaxf(fabsf(v1.z), fabsf(v1.w))));
#pragma unroll
    for (int o = 16; o > 0; o >>= 1) am = fmaxf(am, __shfl_xor_sync(0xFFFFFFFFu, am, o));
    if ((tid & 31) == 0) redA[tid >> 5] = am;
    __syncthreads();
    am = redA[0];
#pragma unroll
    for (int w = 1; w < 8; w++) am = fmaxf(am, redA[w]);
    am = fmaxf(am, 1e-20f);

    const float sc   = am * (1.0f / 127.0f);
    const float inv  = 127.0f / am;
    const float inv2 = 256.0f / sc;
    if (tid == 0) S[blockIdx.x] = sc;

    float q1x, q1y, q1z, q1w;
    char4 a, bq;
    // first half
    q1x = qclamp(rintf(v0.x * inv)); q1y = qclamp(rintf(v0.y * inv));
    q1z = qclamp(rintf(v0.z * inv)); q1w = qclamp(rintf(v0.w * inv));
    a = make_char4((signed char)q1x, (signed char)q1y, (signed char)q1z, (signed char)q1w);
    bq.x = (signed char)qclamp(rintf((v0.x - q1x * sc) * inv2));
    bq.y = (signed char)qclamp(rintf((v0.y - q1y * sc) * inv2));
    bq.z = (signed char)qclamp(rintf((v0.z - q1z * sc) * inv2));
    bq.w = (signed char)qclamp(rintf((v0.w - q1w * sc) * inv2));
    *reinterpret_cast<char4*>(Q1 + base + tid * 4) = a;
    *reinterpret_cast<char4*>(Q2 + base + tid * 4) = bq;
    // second half
    q1x = qclamp(rintf(v1.x * inv)); q1y = qclamp(rintf(v1.y * inv));
    q1z = qclamp(rintf(v1.z * inv)); q1w = qclamp(rintf(v1.w * inv));
    a = make_char4((signed char)q1x, (signed char)q1y, (signed char)q1z, (signed char)q1w);
    bq.x = (signed char)qclamp(rintf((v1.x - q1x * sc) * inv2));
    bq.y = (signed char)qclamp(rintf((v1.y - q1y * sc) * inv2));
    bq.z = (signed char)qclamp(rintf((v1.z - q1z * sc) * inv2));
    bq.w = (signed char)qclamp(rintf((v1.w - q1w * sc) * inv2));
    *reinterpret_cast<char4*>(Q1 + base + 1024 + tid * 4) = a;
    *reinterpret_cast<char4*>(Q2 + base + 1024 + tid * 4) = bq;
}

// ---------------- launch ----------------
extern "C" void kernel_launch(void* const* d_in, const int* in_sizes, int n_in,
                              void* d_out, int out_size)
{
    const float* x_u    = (const float*)d_in[0];
    const float* x_m    = (const float*)d_in[1];
    const float* w_qkv1 = (const float*)d_in[2];
    const float* b_qkv1 = (const float*)d_in[3];
    const float* w_o1   = (const float*)d_in[4];
    const float* b_o1   = (const float*)d_in[5];
    const float* w_qkv2 = (const float*)d_in[6];
    const float* b_qkv2 = (const float*)d_in[7];
    const float* w_o2   = (const float*)d_in[8];
    const float* b_o2   = (const float*)d_in[9];
    const float* ln_g   = (const float*)d_in[10];
    const float* ln_b   = (const float*)d_in[11];
    const float* w_proj = (const float*)d_in[12];
    const float* b_proj = (const float*)d_in[13];
    float* out = (float*)d_out;

    const float* wv1 = w_qkv1 + (size_t)2 * DIM * DIM;
    const float* bv1 = b_qkv1 + 2 * DIM;
    const float* wv2 = w_qkv2 + (size_t)2 * DIM * DIM;
    const float* bv2 = b_qkv2 + 2 * DIM;

    int8_t *xu1, *xu2, *xm1, *xm2, *zn1, *zn2, *B1q1, *B1q2, *B2q1, *B2q2, *wp1, *wp2;
    float *sxu, *sxm, *szn, *sB1, *sB2, *swp, *z, *B1t, *B2t, *c1, *c2;
    __nv_bfloat16 *wo1_h, *wo1_l, *wo2_h, *wo2_l, *wv1t_h, *wv1t_l, *wv2t_h, *wv2t_l;

    cudaGetSymbolAddress((void**)&xu1, g_xu1);   cudaGetSymbolAddress((void**)&xu2, g_xu2);
    cudaGetSymbolAddress((void**)&xm1, g_xm1);   cudaGetSymbolAddress((void**)&xm2, g_xm2);
    cudaGetSymbolAddress((void**)&zn1, g_zn1);   cudaGetSymbolAddress((void**)&zn2, g_zn2);
    cudaGetSymbolAddress((void**)&B1q1, g_B1q1); cudaGetSymbolAddress((void**)&B1q2, g_B1q2);
    cudaGetSymbolAddress((void**)&B2q1, g_B2q1); cudaGetSymbolAddress((void**)&B2q2, g_B2q2);
    cudaGetSymbolAddress((void**)&wp1, g_wp1);   cudaGetSymbolAddress((void**)&wp2, g_wp2);
    cudaGetSymbolAddress((void**)&sxu, g_sxu);   cudaGetSymbolAddress((void**)&sxm, g_sxm);
    cudaGetSymbolAddress((void**)&szn, g_szn);
    cudaGetSymbolAddress((void**)&sB1, g_sB1);   cudaGetSymbolAddress((void**)&sB2, g_sB2);
    cudaGetSymbolAddress((void**)&swp, g_swp);
    cudaGetSymbolAddress((void**)&z, g_z);
    cudaGetSymbolAddress((void**)&B1t, g_B1t);   cudaGetSymbolAddress((void**)&B2t, g_B2t);
    cudaGetSymbolAddress((void**)&c1, g_c1);     cudaGetSymbolAddress((void**)&c2, g_c2);
    cudaGetSymbolAddress((void**)&wo1_h, g_wo1_hi);   cudaGetSymbolAddress((void**)&wo1_l, g_wo1_lo);
    cudaGetSymbolAddress((void**)&wo2_h, g_wo2_hi);   cudaGetSymbolAddress((void**)&wo2_l, g_wo2_lo);
    cudaGetSymbolAddress((void**)&wv1t_h, g_wv1t_hi); cudaGetSymbolAddress((void**)&wv1t_l, g_wv1t_lo);
    cudaGetSymbolAddress((void**)&wv2t_h, g_wv2t_hi); cudaGetSymbolAddress((void**)&wv2t_l, g_wv2t_lo);

    cudaFuncSetAttribute(mma_gemm, cudaFuncAttributeMaxDynamicSharedMemorySize, SMEM_TOT);
    cudaFuncSetAttribute(qgemm<false>, cudaFuncAttributeMaxDynamicSharedMemorySize, QSMEM);
    cudaFuncSetAttribute(qgemm<true>,  cudaFuncAttributeMaxDynamicSharedMemorySize, QSMEM);

    const dim3 gridQz(DIM / 128, BATCH / 128);    // (8, 128)
    const dim3 gridW(DIM / NT, DIM / MT);         // (8, 4)

    // ---- path 1 chain (int8 z1 GEMM is launch #6 → profiled by ncu -s 5) ----
    split_kernel<<<(DIM * DIM / 4) / 256, 256>>>(w_o1, wo1_h, wo1_l, DIM * DIM / 4);   // 1
    tsplit_kernel<<<dim3(32, 32), dim3(32, 8)>>>(wv1, DIM, DIM, wv1t_h, wv1t_l);       // 2
    mma_gemm<<<gridW, 256, SMEM_TOT>>>(wo1_h, wo1_l, wv1t_h, wv1t_l, B1t, DIM, DIM);   // 3
    quant_rows<<<DIM, 256>>>(B1t, DIM, B1q1, B1q2, sB1);                               // 4
    quant_rows<<<BATCH, 256>>>(x_u, DIM, xu1, xu2, sxu);                               // 5
    qgemm<false><<<gridQz, 256, QSMEM>>>(xu1, xu2, sxu, B1q1, B1q2, sB1,
                                         z, DIM2, nullptr, DIM);                       // 6

    // ---- path 2 chain ----
    split_kernel<<<(DIM * DIM / 4) / 256, 256>>>(w_o2, wo2_h, wo2_l, DIM * DIM / 4);
    tsplit_kernel<<<dim3(32, 32), dim3(32, 8)>>>(wv2, DIM, DIM, wv2t_h, wv2t_l);
    mma_gemm<<<gridW, 256, SMEM_TOT>>>(wo2_h, wo2_l, wv2t_h, wv2t_l, B2t, DIM, DIM);
    quant_rows<<<DIM, 256>>>(B2t, DIM, B2q1, B2q2, sB2);
    quant_rows<<<BATCH, 256>>>(x_m, DIM, xm1, xm2, sxm);
    qgemm<false><<<gridQz, 256, QSMEM>>>(xm1, xm2, sxm, B2q1, B2q2, sB2,
                                         z + DIM, DIM2, nullptr, DIM);

    // ---- combined biases (added inside LN) ----
    biasc_kernel<<<DIM, 128>>>(w_o1, bv1, b_o1, c1);
    biasc_kernel<<<DIM, 128>>>(w_o2, bv2, b_o2, c2);

    // ---- LayerNorm(+bias) + int8 quantization ----
    ln_quant<<<BATCH, 256>>>(z, c1, c2, ln_g, ln_b, zn1, zn2, szn);

    // ---- proj weights quant + final GEMM with bias + exact GELU ----
    quant_rows<<<DIM, 256>>>(w_proj, DIM2, wp1, wp2, swp);
    qgemm<true><<<gridQz, 256, QSMEM>>>(zn1, zn2, szn, wp1, wp2, swp,
                                        out, DIM, b_proj, DIM2);
}

// round 10
// speedup vs baseline: 6.9400x; 4.2457x over previous
#include <cuda_runtime.h>
#include <cuda_bf16.h>
#include <cuda_fp16.h>
#include <math.h>
#include <stdint.h>

#define BATCH 16384
#define DIM   1024
#define DIM2  2048

// ---------------- scratch (device globals; no allocs) ----------------
__device__ __half  g_xuh[(size_t)BATCH*DIM];
__device__ __half  g_xmh[(size_t)BATCH*DIM];
__device__ __half  g_znh[(size_t)BATCH*DIM2];
__device__ __half  g_B1h[DIM*DIM], g_B2h[DIM*DIM];
__device__ __half  g_wph[DIM*DIM2];
__device__ float   g_z[(size_t)BATCH*DIM2];
__device__ float   g_B1t[DIM*DIM], g_B2t[DIM*DIM];
__device__ float   g_c1[DIM], g_c2[DIM];
__device__ __nv_bfloat16 g_wo1_hi[DIM*DIM], g_wo1_lo[DIM*DIM];
__device__ __nv_bfloat16 g_wo2_hi[DIM*DIM], g_wo2_lo[DIM*DIM];
__device__ __nv_bfloat16 g_wv1t_hi[DIM*DIM], g_wv1t_lo[DIM*DIM];
__device__ __nv_bfloat16 g_wv2t_hi[DIM*DIM], g_wv2t_lo[DIM*DIM];

// ---------------- low-level helpers (sm_80-baseline PTX only) ----------------
__device__ __forceinline__ uint32_t s2u(const void* p) {
    uint32_t a;
    asm("{ .reg .u64 t; cvta.to.shared.u64 t, %1; cvt.u32.u64 %0, t; }" : "=r"(a) : "l"(p));
    return a;
}
__device__ __forceinline__ void cp16(uint32_t d, const void* s) {
    asm volatile("cp.async.cg.shared.global [%0], [%1], 16;" :: "r"(d), "l"(s));
}
__device__ __forceinline__ void ldm4(uint32_t* r, uint32_t addr) {
    asm volatile("ldmatrix.sync.aligned.m8n8.x4.shared.b16 {%0,%1,%2,%3}, [%4];"
                 : "=r"(r[0]), "=r"(r[1]), "=r"(r[2]), "=r"(r[3]) : "r"(addr));
}
__device__ __forceinline__ void mma_bf16(float* d, const uint32_t* a, const uint32_t* b) {
    asm volatile(
        "mma.sync.aligned.m16n8k16.row.col.f32.bf16.bf16.f32 "
        "{%0,%1,%2,%3}, {%4,%5,%6,%7}, {%8,%9}, {%0,%1,%2,%3};"
        : "+f"(d[0]), "+f"(d[1]), "+f"(d[2]), "+f"(d[3])
        : "r"(a[0]), "r"(a[1]), "r"(a[2]), "r"(a[3]), "r"(b[0]), "r"(b[1]));
}
__device__ __forceinline__ void mma_f16(float* d, const uint32_t* a, uint32_t b0, uint32_t b1) {
    asm volatile(
        "mma.sync.aligned.m16n8k16.row.col.f32.f16.f16.f32 "
        "{%0,%1,%2,%3}, {%4,%5,%6,%7}, {%8,%9}, {%0,%1,%2,%3};"
        : "+f"(d[0]), "+f"(d[1]), "+f"(d[2]), "+f"(d[3])
        : "r"(a[0]), "r"(a[1]), "r"(a[2]), "r"(a[3]), "r"(b0), "r"(b1));
}

// ============================================================================
// fp16 single-pass GEMM: C[m,n] = A[m,:].B[n,:] (+bias[n], optional exact GELU)
// A: [M,K] fp16 row-major, B: [N,K] fp16 row-major.
// CTA tile 256x128x64, 8 warps (4m x 2n), warp tile 64x64, 3-stage cp.async.
// ============================================================================
#define HSTR 72                         // smem row pitch in halves (144 B)
#define HA_TILE (256*HSTR*2)            // 36864 B
#define HB_TILE (128*HSTR*2)            // 18432 B
#define HSTAGE  (HA_TILE + HB_TILE)     // 55296 B
#define HSMEM   (3*HSTAGE)              // 165888 B

template <bool GELU>
__global__ __launch_bounds__(256, 1)
void hgemm(const __half* __restrict__ A, const __half* __restrict__ B,
           float* __restrict__ C, int ldc, const float* __restrict__ bias, int K)
{
    extern __shared__ char smem[];
    const uint32_t base = s2u(smem);
    const int tid  = threadIdx.x;
    const int wid  = tid >> 5;
    const int lane = tid & 31;
    const int m0 = blockIdx.y * 256;
    const int n0 = blockIdx.x * 128;
    const int warp_m0 = (wid & 3) * 64;
    const int warp_n0 = (wid >> 2) * 64;

    float acc[4][8][4];
#pragma unroll
    for (int i = 0; i < 4; i++)
#pragma unroll
        for (int j = 0; j < 8; j++)
#pragma unroll
            for (int q = 0; q < 4; q++) acc[i][j][q] = 0.0f;

    auto load_stage = [&](int s, int k0) {
        const uint32_t stA = base + s * HSTAGE;
        const uint32_t stB = stA + HA_TILE;
        for (int i = tid; i < 256 * 8; i += 256) {        // A: 256 rows x 8 segs of 16B
            const int r = i >> 3, seg = i & 7;
            cp16(stA + (uint32_t)(r * (HSTR * 2) + seg * 16),
                 A + (size_t)(m0 + r) * K + k0 + seg * 8);
        }
        for (int i = tid; i < 128 * 8; i += 256) {        // B: 128 rows x 8 segs
            const int r = i >> 3, seg = i & 7;
            cp16(stB + (uint32_t)(r * (HSTR * 2) + seg * 16),
                 B + (size_t)(n0 + r) * K + k0 + seg * 8);
        }
        asm volatile("cp.async.commit_group;" ::: "memory");
    };

    const int nk = K >> 6;
    load_stage(0, 0);
    load_stage(1, 64);

    const int a_row = warp_m0 + (lane & 15);
    const int a_col = (lane >> 4) << 3;
    const int b_row = warp_n0 + (lane & 7) + ((lane >> 4) << 3);
    const int b_col = ((lane >> 3) & 1) << 3;

    for (int i = 0; i < nk; i++) {
        if (i + 2 <= nk) asm volatile("cp.async.wait_group 1;" ::: "memory");
        else             asm volatile("cp.async.wait_group 0;" ::: "memory");
        __syncthreads();
        if (i + 2 < nk) load_stage((i + 2) % 3, (i + 2) * 64);

        const uint32_t stA = base + (i % 3) * HSTAGE;
        const uint32_t stB = stA + HA_TILE;

#pragma unroll
        for (int ks = 0; ks < 4; ks++) {
            const int k0 = ks * 16;
            uint32_t af[4][4], bf[4][4];
#pragma unroll
            for (int mf = 0; mf < 4; mf++)
                ldm4(af[mf], stA + (uint32_t)((a_row + mf * 16) * HSTR + k0 + a_col) * 2);
#pragma unroll
            for (int bp = 0; bp < 4; bp++)
                ldm4(bf[bp], stB + (uint32_t)((b_row + bp * 16) * HSTR + k0 + b_col) * 2);
#pragma unroll
            for (int mf = 0; mf < 4; mf++)
#pragma unroll
                for (int bp = 0; bp < 4; bp++) {
                    mma_f16(acc[mf][2 * bp + 0], af[mf], bf[bp][0], bf[bp][1]);
                    mma_f16(acc[mf][2 * bp + 1], af[mf], bf[bp][2], bf[bp][3]);
                }
        }
    }

    // ---- epilogue ----
    const int r_base = m0 + warp_m0 + (lane >> 2);
    const int c_base = n0 + warp_n0 + ((lane & 3) << 1);
#pragma unroll
    for (int mf = 0; mf < 4; mf++) {
        const int row0 = r_base + mf * 16;
#pragma unroll
        for (int nf = 0; nf < 8; nf++) {
            const int cc = c_base + nf * 8;
            float b0 = 0.0f, b1 = 0.0f;
            if (bias) { b0 = bias[cc]; b1 = bias[cc + 1]; }
            float v0 = acc[mf][nf][0] + b0;
            float v1 = acc[mf][nf][1] + b1;
            float v2 = acc[mf][nf][2] + b0;
            float v3 = acc[mf][nf][3] + b1;
            if (GELU) {
                v0 = 0.5f * v0 * (1.0f + erff(v0 * 0.70710678118654752f));
                v1 = 0.5f * v1 * (1.0f + erff(v1 * 0.70710678118654752f));
                v2 = 0.5f * v2 * (1.0f + erff(v2 * 0.70710678118654752f));
                v3 = 0.5f * v3 * (1.0f + erff(v3 * 0.70710678118654752f));
            }
            *reinterpret_cast<float2*>(&C[(size_t)row0 * ldc + cc])       = make_float2(v0, v1);
            *reinterpret_cast<float2*>(&C[(size_t)(row0 + 8) * ldc + cc]) = make_float2(v2, v3);
        }
    }
}

// ============================================================================
// bf16x3 mma GEMM (validated R4) — only for the two 1024^3 weight combines
// ============================================================================
#define MT 256
#define NT 128
#define KC 64
#define STRIDE 72
#define A_TILE (MT*STRIDE*2)
#define B_TILE (NT*STRIDE*2)
#define STAGE  (2*A_TILE + 2*B_TILE)
#define SMEM_TOT (2*STAGE)

__global__ __launch_bounds__(256, 1)
void mma_gemm(const __nv_bfloat16* __restrict__ Ah, const __nv_bfloat16* __restrict__ Al,
              const __nv_bfloat16* __restrict__ Bh, const __nv_bfloat16* __restrict__ Bl,
              float* __restrict__ C, int ldc, int K)
{
    extern __shared__ char smem[];
    const uint32_t base = s2u(smem);
    const int tid  = threadIdx.x;
    const int wid  = tid >> 5;
    const int lane = tid & 31;
    const int m0 = blockIdx.y * MT;
    const int n0 = blockIdx.x * NT;
    const int warp_m0 = (wid & 3) * 64;
    const int warp_n0 = (wid >> 2) * 64;

    float acc[4][8][4];
#pragma unroll
    for (int i = 0; i < 4; i++)
#pragma unroll
        for (int j = 0; j < 8; j++)
#pragma unroll
            for (int q = 0; q < 4; q++) acc[i][j][q] = 0.0f;

    auto load_stage = [&](int s, int k0) {
        const uint32_t stA_h = base + s * STAGE;
        const uint32_t stA_l = stA_h + A_TILE;
        const uint32_t stB_h = stA_h + 2 * A_TILE;
        const uint32_t stB_l = stB_h + B_TILE;
        for (int i = tid; i < MT * 8; i += 256) {
            const int r = i >> 3, seg = i & 7;
            const uint32_t off = (uint32_t)(r * (STRIDE * 2) + seg * 16);
            const size_t gs = (size_t)(m0 + r) * K + k0 + seg * 8;
            cp16(stA_h + off, Ah + gs);
            cp16(stA_l + off, Al + gs);
        }
        for (int i = tid; i < NT * 8; i += 256) {
            const int r = i >> 3, seg = i & 7;
            const uint32_t off = (uint32_t)(r * (STRIDE * 2) + seg * 16);
            const size_t gs = (size_t)(n0 + r) * K + k0 + seg * 8;
            cp16(stB_h + off, Bh + gs);
            cp16(stB_l + off, Bl + gs);
        }
        asm volatile("cp.async.commit_group;" ::: "memory");
    };

    const int nk = K / KC;
    load_stage(0, 0);
    load_stage(1, KC);

    const int a_row = warp_m0 + (lane & 15);
    const int a_col = (lane >> 4) << 3;
    const int b_row = warp_n0 + (lane & 7) + ((lane >> 4) << 3);
    const int b_col = ((lane >> 3) & 1) << 3;

    for (int i = 0; i < nk; i++) {
        if (i + 1 < nk) asm volatile("cp.async.wait_group 1;" ::: "memory");
        else            asm volatile("cp.async.wait_group 0;" ::: "memory");
        __syncthreads();

        const uint32_t stA_h = base + (i & 1) * STAGE;
        const uint32_t stA_l = stA_h + A_TILE;
        const uint32_t stB_h = stA_h + 2 * A_TILE;
        const uint32_t stB_l = stB_h + B_TILE;

#pragma unroll
        for (int ks = 0; ks < 4; ks++) {
            const int k0 = ks * 16;
            uint32_t ah[4][4], al[4][4], bh[4][4], bl[4][4];
#pragma unroll
            for (int mf = 0; mf < 4; mf++) {
                const uint32_t ao = (uint32_t)((a_row + mf * 16) * STRIDE + k0 + a_col) * 2;
                ldm4(ah[mf], stA_h + ao);
                ldm4(al[mf], stA_l + ao);
            }
#pragma unroll
            for (int bp = 0; bp < 4; bp++) {
                const uint32_t bo = (uint32_t)((b_row + bp * 16) * STRIDE + k0 + b_col) * 2;
                ldm4(bh[bp], stB_h + bo);
                ldm4(bl[bp], stB_l + bo);
            }
#pragma unroll
            for (int mf = 0; mf < 4; mf++)
#pragma unroll
                for (int bp = 0; bp < 4; bp++) {
                    mma_bf16(acc[mf][2 * bp + 0], ah[mf], &bh[bp][0]);
                    mma_bf16(acc[mf][2 * bp + 1], ah[mf], &bh[bp][2]);
                    mma_bf16(acc[mf][2 * bp + 0], ah[mf], &bl[bp][0]);
                    mma_bf16(acc[mf][2 * bp + 1], ah[mf], &bl[bp][2]);
                    mma_bf16(acc[mf][2 * bp + 0], al[mf], &bh[bp][0]);
                    mma_bf16(acc[mf][2 * bp + 1], al[mf], &bh[bp][2]);
                }
        }

        __syncthreads();
        if (i + 2 < nk) load_stage(i & 1, (i + 2) * KC);
    }

    const int r_base = m0 + warp_m0 + (lane >> 2);
    const int c_base = n0 + warp_n0 + ((lane & 3) << 1);
#pragma unroll
    for (int mf = 0; mf < 4; mf++)
#pragma unroll
        for (int nf = 0; nf < 8; nf++) {
            const int cc = c_base + nf * 8;
            const int row0 = r_base + mf * 16;
            *reinterpret_cast<float2*>(&C[(size_t)row0 * ldc + cc]) =
                make_float2(acc[mf][nf][0], acc[mf][nf][1]);
            *reinterpret_cast<float2*>(&C[(size_t)(row0 + 8) * ldc + cc]) =
                make_float2(acc[mf][nf][2], acc[mf][nf][3]);
        }
}

// ---------------- bf16 split helpers (combine GEMM inputs) ----------------
__global__ void split_kernel(const float* __restrict__ x,
                             __nv_bfloat16* __restrict__ h, __nv_bfloat16* __restrict__ l,
                             int n4)
{
    int i = blockIdx.x * blockDim.x + threadIdx.x;
    if (i < n4) {
        float4 v = reinterpret_cast<const float4*>(x)[i];
        __nv_bfloat162 h0, h1, l0, l1;
        h0.x = __float2bfloat16_rn(v.x); h0.y = __float2bfloat16_rn(v.y);
        h1.x = __float2bfloat16_rn(v.z); h1.y = __float2bfloat16_rn(v.w);
        l0.x = __float2bfloat16_rn(v.x - __bfloat162float(h0.x));
        l0.y = __float2bfloat16_rn(v.y - __bfloat162float(h0.y));
        l1.x = __float2bfloat16_rn(v.z - __bfloat162float(h1.x));
        l1.y = __float2bfloat16_rn(v.w - __bfloat162float(h1.y));
        reinterpret_cast<__nv_bfloat162*>(h + (size_t)i * 4)[0] = h0;
        reinterpret_cast<__nv_bfloat162*>(h + (size_t)i * 4)[1] = h1;
        reinterpret_cast<__nv_bfloat162*>(l + (size_t)i * 4)[0] = l0;
        reinterpret_cast<__nv_bfloat162*>(l + (size_t)i * 4)[1] = l1;
    }
}

__global__ void tsplit_kernel(const float* __restrict__ in, int R, int Ccols,
                              __nv_bfloat16* __restrict__ h, __nv_bfloat16* __restrict__ l)
{
    __shared__ float t[32][33];
    const int r0 = blockIdx.y * 32, c0 = blockIdx.x * 32;
    const int tx = threadIdx.x, ty = threadIdx.y;  // 32 x 8
#pragma unroll
    for (int i = 0; i < 4; i++)
        t[ty + 8 * i][tx] = in[(size_t)(r0 + ty + 8 * i) * Ccols + c0 + tx];
    __syncthreads();
#pragma unroll
    for (int i = 0; i < 4; i++) {
        const int rr = ty + 8 * i;
        const float v = t[tx][rr];
        const size_t o = (size_t)(c0 + rr) * R + r0 + tx;
        __nv_bfloat16 hh = __float2bfloat16_rn(v);
        h[o] = hh;
        l[o] = __float2bfloat16_rn(v - __bfloat162float(hh));
    }
}

// ---------------- fp32 -> fp16 convert ----------------
__global__ void cvt_half(const float* __restrict__ x, __half* __restrict__ y, int n4)
{
    int i = blockIdx.x * blockDim.x + threadIdx.x;
    if (i < n4) {
        float4 v = reinterpret_cast<const float4*>(x)[i];
        __half2 a = __floats2half2_rn(v.x, v.y);
        __half2 b = __floats2half2_rn(v.z, v.w);
        reinterpret_cast<__half2*>(y + (size_t)i * 4)[0] = a;
        reinterpret_cast<__half2*>(y + (size_t)i * 4)[1] = b;
    }
}

// ---------------- combined bias: c[n] = sum_j wo[n,j]*bv[j] + bo[n] ----------------
__global__ void biasc_kernel(const float* __restrict__ wo, const float* __restrict__ bv,
                             const float* __restrict__ bo, float* __restrict__ c)
{
    __shared__ float red[4];
    const int n = blockIdx.x;
    const int tid = threadIdx.x;  // 128
    float s = 0.0f;
    for (int j = tid; j < DIM; j += 128) s += wo[(size_t)n * DIM + j] * bv[j];
#pragma unroll
    for (int o = 16; o > 0; o >>= 1) s += __shfl_xor_sync(0xFFFFFFFFu, s, o);
    if ((tid & 31) == 0) red[tid >> 5] = s;
    __syncthreads();
    if (tid == 0) c[n] = red[0] + red[1] + red[2] + red[3] + bo[n];
}

// ---------------- LayerNorm(2048) with bias add -> fp16 ----------------
__global__ void ln_half(const float* __restrict__ z,
                        const float* __restrict__ c1, const float* __restrict__ c2,
                        const float* __restrict__ g, const float* __restrict__ b,
                        __half* __restrict__ zn)
{
    __shared__ float redS[8], redQ[8];
    const size_t base = (size_t)blockIdx.x * DIM2;
    const int tid = threadIdx.x;  // 256

    float4 v0 = *reinterpret_cast<const float4*>(&z[base + tid * 4]);
    float4 v1 = *reinterpret_cast<const float4*>(&z[base + 1024 + tid * 4]);
    float4 cb0 = *reinterpret_cast<const float4*>(&c1[tid * 4]);
    float4 cb1 = *reinterpret_cast<const float4*>(&c2[tid * 4]);
    v0.x += cb0.x; v0.y += cb0.y; v0.z += cb0.z; v0.w += cb0.w;
    v1.x += cb1.x; v1.y += cb1.y; v1.z += cb1.z; v1.w += cb1.w;

    float s = v0.x + v0.y + v0.z + v0.w + v1.x + v1.y + v1.z + v1.w;
    float q = v0.x * v0.x + v0.y * v0.y + v0.z * v0.z + v0.w * v0.w
            + v1.x * v1.x + v1.y * v1.y + v1.z * v1.z + v1.w * v1.w;
#pragma unroll
    for (int o = 16; o > 0; o >>= 1) {
        s += __shfl_xor_sync(0xFFFFFFFFu, s, o);
        q += __shfl_xor_sync(0xFFFFFFFFu, q, o);
    }
    if ((tid & 31) == 0) { redS[tid >> 5] = s; redQ[tid >> 5] = q; }
    __syncthreads();
    float S = 0.0f, Q = 0.0f;
#pragma unroll
    for (int w = 0; w < 8; w++) { S += redS[w]; Q += redQ[w]; }

    const float mu = S * (1.0f / DIM2);
    const float var = Q * (1.0f / DIM2) - mu * mu;
    const float rstd = rsqrtf(var + 1e-5f);

    float4 g0 = *reinterpret_cast<const float4*>(&g[tid * 4]);
    float4 g1 = *reinterpret_cast<const float4*>(&g[1024 + tid * 4]);
    float4 b0 = *reinterpret_cast<const float4*>(&b[tid * 4]);
    float4 b1 = *reinterpret_cast<const float4*>(&b[1024 + tid * 4]);

    v0.x = (v0.x - mu) * rstd * g0.x + b0.x;
    v0.y = (v0.y - mu) * rstd * g0.y + b0.y;
    v0.z = (v0.z - mu) * rstd * g0.z + b0.z;
    v0.w = (v0.w - mu) * rstd * g0.w + b0.w;
    v1.x = (v1.x - mu) * rstd * g1.x + b1.x;
    v1.y = (v1.y - mu) * rstd * g1.y + b1.y;
    v1.z = (v1.z - mu) * rstd * g1.z + b1.z;
    v1.w = (v1.w - mu) * rstd * g1.w + b1.w;

    reinterpret_cast<__half2*>(zn + base + tid * 4)[0] = __floats2half2_rn(v0.x, v0.y);
    reinterpret_cast<__half2*>(zn + base + tid * 4)[1] = __floats2half2_rn(v0.z, v0.w);
    reinterpret_cast<__half2*>(zn + base + 1024 + tid * 4)[0] = __floats2half2_rn(v1.x, v1.y);
    reinterpret_cast<__half2*>(zn + base + 1024 + tid * 4)[1] = __floats2half2_rn(v1.z, v1.w);
}

// ---------------- launch ----------------
extern "C" void kernel_launch(void* const* d_in, const int* in_sizes, int n_in,
                              void* d_out, int out_size)
{
    const float* x_u    = (const float*)d_in[0];
    const float* x_m    = (const float*)d_in[1];
    const float* w_qkv1 = (const float*)d_in[2];
    const float* b_qkv1 = (const float*)d_in[3];
    const float* w_o1   = (const float*)d_in[4];
    const float* b_o1   = (const float*)d_in[5];
    const float* w_qkv2 = (const float*)d_in[6];
    const float* b_qkv2 = (const float*)d_in[7];
    const float* w_o2   = (const float*)d_in[8];
    const float* b_o2   = (const float*)d_in[9];
    const float* ln_g   = (const float*)d_in[10];
    const float* ln_b   = (const float*)d_in[11];
    const float* w_proj = (const float*)d_in[12];
    const float* b_proj = (const float*)d_in[13];
    float* out = (float*)d_out;

    const float* wv1 = w_qkv1 + (size_t)2 * DIM * DIM;
    const float* bv1 = b_qkv1 + 2 * DIM;
    const float* wv2 = w_qkv2 + (size_t)2 * DIM * DIM;
    const float* bv2 = b_qkv2 + 2 * DIM;

    __half *xuh, *xmh, *znh, *B1h, *B2h, *wph;
    float *z, *B1t, *B2t, *c1, *c2;
    __nv_bfloat16 *wo1_h, *wo1_l, *wo2_h, *wo2_l, *wv1t_h, *wv1t_l, *wv2t_h, *wv2t_l;

    cudaGetSymbolAddress((void**)&xuh, g_xuh);
    cudaGetSymbolAddress((void**)&xmh, g_xmh);
    cudaGetSymbolAddress((void**)&znh, g_znh);
    cudaGetSymbolAddress((void**)&B1h, g_B1h);
    cudaGetSymbolAddress((void**)&B2h, g_B2h);
    cudaGetSymbolAddress((void**)&wph, g_wph);
    cudaGetSymbolAddress((void**)&z, g_z);
    cudaGetSymbolAddress((void**)&B1t, g_B1t);
    cudaGetSymbolAddress((void**)&B2t, g_B2t);
    cudaGetSymbolAddress((void**)&c1, g_c1);
    cudaGetSymbolAddress((void**)&c2, g_c2);
    cudaGetSymbolAddress((void**)&wo1_h, g_wo1_hi);   cudaGetSymbolAddress((void**)&wo1_l, g_wo1_lo);
    cudaGetSymbolAddress((void**)&wo2_h, g_wo2_hi);   cudaGetSymbolAddress((void**)&wo2_l, g_wo2_lo);
    cudaGetSymbolAddress((void**)&wv1t_h, g_wv1t_hi); cudaGetSymbolAddress((void**)&wv1t_l, g_wv1t_lo);
    cudaGetSymbolAddress((void**)&wv2t_h, g_wv2t_hi); cudaGetSymbolAddress((void**)&wv2t_l, g_wv2t_lo);

    cudaFuncSetAttribute(mma_gemm, cudaFuncAttributeMaxDynamicSharedMemorySize, SMEM_TOT);
    cudaFuncSetAttribute(hgemm<false>, cudaFuncAttributeMaxDynamicSharedMemorySize, HSMEM);
    cudaFuncSetAttribute(hgemm<true>,  cudaFuncAttributeMaxDynamicSharedMemorySize, HSMEM);

    const dim3 gridZ(DIM / 128, BATCH / 256);     // (8, 64)
    const dim3 gridW(DIM / NT, DIM / MT);         // (8, 4)

    // ---- path 1 (z1 hgemm is launch #6 -> profiled by ncu -s 5) ----
    split_kernel<<<(DIM * DIM / 4) / 256, 256>>>(w_o1, wo1_h, wo1_l, DIM * DIM / 4);   // 1
    tsplit_kernel<<<dim3(32, 32), dim3(32, 8)>>>(wv1, DIM, DIM, wv1t_h, wv1t_l);       // 2
    mma_gemm<<<gridW, 256, SMEM_TOT>>>(wo1_h, wo1_l, wv1t_h, wv1t_l, B1t, DIM, DIM);   // 3
    cvt_half<<<(DIM * DIM / 4) / 256, 256>>>(B1t, B1h, DIM * DIM / 4);                 // 4
    cvt_half<<<(BATCH * DIM / 4) / 256, 256>>>(x_u, xuh, BATCH * DIM / 4);             // 5
    hgemm<false><<<gridZ, 256, HSMEM>>>(xuh, B1h, z, DIM2, nullptr, DIM);              // 6

    // ---- path 2 ----
    split_kernel<<<(DIM * DIM / 4) / 256, 256>>>(w_o2, wo2_h, wo2_l, DIM * DIM / 4);
    tsplit_kernel<<<dim3(32, 32), dim3(32, 8)>>>(wv2, DIM, DIM, wv2t_h, wv2t_l);
    mma_gemm<<<gridW, 256, SMEM_TOT>>>(wo2_h, wo2_l, wv2t_h, wv2t_l, B2t, DIM, DIM);
    cvt_half<<<(DIM * DIM / 4) / 256, 256>>>(B2t, B2h, DIM * DIM / 4);
    cvt_half<<<(BATCH * DIM / 4) / 256, 256>>>(x_m, xmh, BATCH * DIM / 4);
    hgemm<false><<<gridZ, 256, HSMEM>>>(xmh, B2h, z + DIM, DIM2, nullptr, DIM);

    // ---- combined biases (added inside LN) ----
    biasc_kernel<<<DIM, 128>>>(w_o1, bv1, b_o1, c1);
    biasc_kernel<<<DIM, 128>>>(w_o2, bv2, b_o2, c2);

    // ---- LayerNorm(+bias) -> fp16 ----
    ln_half<<<BATCH, 256>>>(z, c1, c2, ln_g, ln_b, znh);

    // ---- proj: out = GELU(zn @ w_proj^T + b_proj) ----
    cvt_half<<<(DIM * DIM2 / 4) / 256, 256>>>(w_proj, wph, DIM * DIM2 / 4);
    hgemm<true><<<gridZ, 256, HSMEM>>>(znh, wph, out, DIM, b_proj, DIM2);
}

// round 11
// speedup vs baseline: 7.9676x; 1.1481x over previous
#include <cuda_runtime.h>
#include <cuda_bf16.h>
#include <cuda_fp16.h>
#include <math.h>
#include <stdint.h>

#define BATCH 16384
#define DIM   1024
#define DIM2  2048

// ---------------- scratch (device globals; no allocs) ----------------
__device__ __half  g_xuh[(size_t)BATCH*DIM];
__device__ __half  g_xmh[(size_t)BATCH*DIM];
__device__ __half  g_zh[(size_t)BATCH*DIM2];     // z1|z2 in fp16
__device__ __half  g_znh[(size_t)BATCH*DIM2];
__device__ __half  g_B1h[DIM*DIM], g_B2h[DIM*DIM];
__device__ __half  g_wph[DIM*DIM2];
__device__ float   g_part[8*DIM*DIM];            // split-K partials (32 MB)
__device__ float   g_c1[DIM], g_c2[DIM];
__device__ __nv_bfloat16 g_wo1_hi[DIM*DIM], g_wo1_lo[DIM*DIM];
__device__ __nv_bfloat16 g_wo2_hi[DIM*DIM], g_wo2_lo[DIM*DIM];
__device__ __nv_bfloat16 g_wv1t_hi[DIM*DIM], g_wv1t_lo[DIM*DIM];
__device__ __nv_bfloat16 g_wv2t_hi[DIM*DIM], g_wv2t_lo[DIM*DIM];

// ---------------- low-level helpers (sm_80-baseline PTX only) ----------------
__device__ __forceinline__ uint32_t s2u(const void* p) {
    uint32_t a;
    asm("{ .reg .u64 t; cvta.to.shared.u64 t, %1; cvt.u32.u64 %0, t; }" : "=r"(a) : "l"(p));
    return a;
}
__device__ __forceinline__ void cp16(uint32_t d, const void* s) {
    asm volatile("cp.async.cg.shared.global [%0], [%1], 16;" :: "r"(d), "l"(s));
}
__device__ __forceinline__ void ldm4(uint32_t* r, uint32_t addr) {
    asm volatile("ldmatrix.sync.aligned.m8n8.x4.shared.b16 {%0,%1,%2,%3}, [%4];"
                 : "=r"(r[0]), "=r"(r[1]), "=r"(r[2]), "=r"(r[3]) : "r"(addr));
}
__device__ __forceinline__ void mma_bf16(float* d, const uint32_t* a, const uint32_t* b) {
    asm volatile(
        "mma.sync.aligned.m16n8k16.row.col.f32.bf16.bf16.f32 "
        "{%0,%1,%2,%3}, {%4,%5,%6,%7}, {%8,%9}, {%0,%1,%2,%3};"
        : "+f"(d[0]), "+f"(d[1]), "+f"(d[2]), "+f"(d[3])
        : "r"(a[0]), "r"(a[1]), "r"(a[2]), "r"(a[3]), "r"(b[0]), "r"(b[1]));
}
__device__ __forceinline__ void mma_f16(float* d, const uint32_t* a, uint32_t b0, uint32_t b1) {
    asm volatile(
        "mma.sync.aligned.m16n8k16.row.col.f32.f16.f16.f32 "
        "{%0,%1,%2,%3}, {%4,%5,%6,%7}, {%8,%9}, {%0,%1,%2,%3};"
        : "+f"(d[0]), "+f"(d[1]), "+f"(d[2]), "+f"(d[3])
        : "r"(a[0]), "r"(a[1]), "r"(a[2]), "r"(a[3]), "r"(b0), "r"(b1));
}

// ============================================================================
// fp16 single-pass GEMM. A: [M,K] fp16 row-major, B: [N,K] fp16 row-major.
// CTA tile 256x128x64, 8 warps (4m x 2n), warp tile 64x64, 3-stage cp.async.
// OT = float or __half output.
// ============================================================================
#define HSTR 72
#define HA_TILE (256*HSTR*2)
#define HB_TILE (128*HSTR*2)
#define HSTAGE  (HA_TILE + HB_TILE)
#define HSMEM   (3*HSTAGE)

template <bool GELU, typename OT>
__global__ __launch_bounds__(256, 1)
void hgemm(const __half* __restrict__ A, const __half* __restrict__ B,
           OT* __restrict__ C, int ldc, const float* __restrict__ bias, int K)
{
    extern __shared__ char smem[];
    const uint32_t base = s2u(smem);
    const int tid  = threadIdx.x;
    const int wid  = tid >> 5;
    const int lane = tid & 31;
    const int m0 = blockIdx.y * 256;
    const int n0 = blockIdx.x * 128;
    const int warp_m0 = (wid & 3) * 64;
    const int warp_n0 = (wid >> 2) * 64;

    float acc[4][8][4];
#pragma unroll
    for (int i = 0; i < 4; i++)
#pragma unroll
        for (int j = 0; j < 8; j++)
#pragma unroll
            for (int q = 0; q < 4; q++) acc[i][j][q] = 0.0f;

    auto load_stage = [&](int s, int k0) {
        const uint32_t stA = base + s * HSTAGE;
        const uint32_t stB = stA + HA_TILE;
        for (int i = tid; i < 256 * 8; i += 256) {
            const int r = i >> 3, seg = i & 7;
            cp16(stA + (uint32_t)(r * (HSTR * 2) + seg * 16),
                 A + (size_t)(m0 + r) * K + k0 + seg * 8);
        }
        for (int i = tid; i < 128 * 8; i += 256) {
            const int r = i >> 3, seg = i & 7;
            cp16(stB + (uint32_t)(r * (HSTR * 2) + seg * 16),
                 B + (size_t)(n0 + r) * K + k0 + seg * 8);
        }
        asm volatile("cp.async.commit_group;" ::: "memory");
    };

    const int nk = K >> 6;
    load_stage(0, 0);
    load_stage(1, 64);

    const int a_row = warp_m0 + (lane & 15);
    const int a_col = (lane >> 4) << 3;
    const int b_row = warp_n0 + (lane & 7) + ((lane >> 4) << 3);
    const int b_col = ((lane >> 3) & 1) << 3;

    for (int i = 0; i < nk; i++) {
        if (i + 2 <= nk) asm volatile("cp.async.wait_group 1;" ::: "memory");
        else             asm volatile("cp.async.wait_group 0;" ::: "memory");
        __syncthreads();
        if (i + 2 < nk) load_stage((i + 2) % 3, (i + 2) * 64);

        const uint32_t stA = base + (i % 3) * HSTAGE;
        const uint32_t stB = stA + HA_TILE;

#pragma unroll
        for (int ks = 0; ks < 4; ks++) {
            const int k0 = ks * 16;
            uint32_t af[4][4], bf[4][4];
#pragma unroll
            for (int mf = 0; mf < 4; mf++)
                ldm4(af[mf], stA + (uint32_t)((a_row + mf * 16) * HSTR + k0 + a_col) * 2);
#pragma unroll
            for (int bp = 0; bp < 4; bp++)
                ldm4(bf[bp], stB + (uint32_t)((b_row + bp * 16) * HSTR + k0 + b_col) * 2);
#pragma unroll
            for (int mf = 0; mf < 4; mf++)
#pragma unroll
                for (int bp = 0; bp < 4; bp++) {
                    mma_f16(acc[mf][2 * bp + 0], af[mf], bf[bp][0], bf[bp][1]);
                    mma_f16(acc[mf][2 * bp + 1], af[mf], bf[bp][2], bf[bp][3]);
                }
        }
    }

    // ---- epilogue ----
    const int r_base = m0 + warp_m0 + (lane >> 2);
    const int c_base = n0 + warp_n0 + ((lane & 3) << 1);
#pragma unroll
    for (int mf = 0; mf < 4; mf++) {
        const int row0 = r_base + mf * 16;
#pragma unroll
        for (int nf = 0; nf < 8; nf++) {
            const int cc = c_base + nf * 8;
            float b0 = 0.0f, b1 = 0.0f;
            if (bias) { b0 = bias[cc]; b1 = bias[cc + 1]; }
            float v0 = acc[mf][nf][0] + b0;
            float v1 = acc[mf][nf][1] + b1;
            float v2 = acc[mf][nf][2] + b0;
            float v3 = acc[mf][nf][3] + b1;
            if (GELU) {
                v0 = 0.5f * v0 * (1.0f + erff(v0 * 0.70710678118654752f));
                v1 = 0.5f * v1 * (1.0f + erff(v1 * 0.70710678118654752f));
                v2 = 0.5f * v2 * (1.0f + erff(v2 * 0.70710678118654752f));
                v3 = 0.5f * v3 * (1.0f + erff(v3 * 0.70710678118654752f));
            }
            if (sizeof(OT) == 4) {
                *reinterpret_cast<float2*>((float*)C + (size_t)row0 * ldc + cc) = make_float2(v0, v1);
                *reinterpret_cast<float2*>((float*)C + (size_t)(row0 + 8) * ldc + cc) = make_float2(v2, v3);
            } else {
                *reinterpret_cast<__half2*>((__half*)C + (size_t)row0 * ldc + cc) = __floats2half2_rn(v0, v1);
                *reinterpret_cast<__half2*>((__half*)C + (size_t)(row0 + 8) * ldc + cc) = __floats2half2_rn(v2, v3);
            }
        }
    }
}

// ============================================================================
// bf16x3 split-K GEMM for the 1024^3 weight combines.
// blockIdx.z = K-slice (8 slices of 128). Each slice writes its own fp32 partial.
// ============================================================================
#define MT 256
#define NT 128
#define KC 64
#define KSLICE 128
#define STRIDE 72
#define A_TILE (MT*STRIDE*2)
#define B_TILE (NT*STRIDE*2)
#define STAGE  (2*A_TILE + 2*B_TILE)
#define SMEM_TOT (2*STAGE)

__global__ __launch_bounds__(256, 1)
void mma_gemm_sk(const __nv_bfloat16* __restrict__ Ah, const __nv_bfloat16* __restrict__ Al,
                 const __nv_bfloat16* __restrict__ Bh, const __nv_bfloat16* __restrict__ Bl,
                 float* __restrict__ Cpart, int lda)
{
    extern __shared__ char smem[];
    const uint32_t base = s2u(smem);
    const int tid  = threadIdx.x;
    const int wid  = tid >> 5;
    const int lane = tid & 31;
    const int m0 = blockIdx.y * MT;
    const int n0 = blockIdx.x * NT;
    const int koff = blockIdx.z * KSLICE;
    float* Cp = Cpart + (size_t)blockIdx.z * DIM * DIM;
    const int warp_m0 = (wid & 3) * 64;
    const int warp_n0 = (wid >> 2) * 64;

    float acc[4][8][4];
#pragma unroll
    for (int i = 0; i < 4; i++)
#pragma unroll
        for (int j = 0; j < 8; j++)
#pragma unroll
            for (int q = 0; q < 4; q++) acc[i][j][q] = 0.0f;

    auto load_stage = [&](int s, int k0) {
        const uint32_t stA_h = base + s * STAGE;
        const uint32_t stA_l = stA_h + A_TILE;
        const uint32_t stB_h = stA_h + 2 * A_TILE;
        const uint32_t stB_l = stB_h + B_TILE;
        for (int i = tid; i < MT * 8; i += 256) {
            const int r = i >> 3, seg = i & 7;
            const uint32_t off = (uint32_t)(r * (STRIDE * 2) + seg * 16);
            const size_t gs = (size_t)(m0 + r) * lda + k0 + seg * 8;
            cp16(stA_h + off, Ah + gs);
            cp16(stA_l + off, Al + gs);
        }
        for (int i = tid; i < NT * 8; i += 256) {
            const int r = i >> 3, seg = i & 7;
            const uint32_t off = (uint32_t)(r * (STRIDE * 2) + seg * 16);
            const size_t gs = (size_t)(n0 + r) * lda + k0 + seg * 8;
            cp16(stB_h + off, Bh + gs);
            cp16(stB_l + off, Bl + gs);
        }
        asm volatile("cp.async.commit_group;" ::: "memory");
    };

    const int nk = KSLICE / KC;   // 2
    load_stage(0, koff);
    load_stage(1, koff + KC);

    const int a_row = warp_m0 + (lane & 15);
    const int a_col = (lane >> 4) << 3;
    const int b_row = warp_n0 + (lane & 7) + ((lane >> 4) << 3);
    const int b_col = ((lane >> 3) & 1) << 3;

    for (int i = 0; i < nk; i++) {
        if (i + 1 < nk) asm volatile("cp.async.wait_group 1;" ::: "memory");
        else            asm volatile("cp.async.wait_group 0;" ::: "memory");
        __syncthreads();

        const uint32_t stA_h = base + (i & 1) * STAGE;
        const uint32_t stA_l = stA_h + A_TILE;
        const uint32_t stB_h = stA_h + 2 * A_TILE;
        const uint32_t stB_l = stB_h + B_TILE;

#pragma unroll
        for (int ks = 0; ks < 4; ks++) {
            const int k0 = ks * 16;
            uint32_t ah[4][4], al[4][4], bh[4][4], bl[4][4];
#pragma unroll
            for (int mf = 0; mf < 4; mf++) {
                const uint32_t ao = (uint32_t)((a_row + mf * 16) * STRIDE + k0 + a_col) * 2;
                ldm4(ah[mf], stA_h + ao);
                ldm4(al[mf], stA_l + ao);
            }
#pragma unroll
            for (int bp = 0; bp < 4; bp++) {
                const uint32_t bo = (uint32_t)((b_row + bp * 16) * STRIDE + k0 + b_col) * 2;
                ldm4(bh[bp], stB_h + bo);
                ldm4(bl[bp], stB_l + bo);
            }
#pragma unroll
            for (int mf = 0; mf < 4; mf++)
#pragma unroll
                for (int bp = 0; bp < 4; bp++) {
                    mma_bf16(acc[mf][2 * bp + 0], ah[mf], &bh[bp][0]);
                    mma_bf16(acc[mf][2 * bp + 1], ah[mf], &bh[bp][2]);
                    mma_bf16(acc[mf][2 * bp + 0], ah[mf], &bl[bp][0]);
                    mma_bf16(acc[mf][2 * bp + 1], ah[mf], &bl[bp][2]);
                    mma_bf16(acc[mf][2 * bp + 0], al[mf], &bh[bp][0]);
                    mma_bf16(acc[mf][2 * bp + 1], al[mf], &bh[bp][2]);
                }
        }
        __syncthreads();
    }

    const int r_base = m0 + warp_m0 + (lane >> 2);
    const int c_base = n0 + warp_n0 + ((lane & 3) << 1);
#pragma unroll
    for (int mf = 0; mf < 4; mf++)
#pragma unroll
        for (int nf = 0; nf < 8; nf++) {
            const int cc = c_base + nf * 8;
            const int row0 = r_base + mf * 16;
            *reinterpret_cast<float2*>(&Cp[(size_t)row0 * DIM + cc]) =
                make_float2(acc[mf][nf][0], acc[mf][nf][1]);
            *reinterpret_cast<float2*>(&Cp[(size_t)(row0 + 8) * DIM + cc]) =
                make_float2(acc[mf][nf][2], acc[mf][nf][3]);
        }
}

// ---------------- reduce 8 fp32 partials -> fp16 ----------------
__global__ void reduce8_half(const float* __restrict__ p, __half* __restrict__ o, int n4)
{
    int i = blockIdx.x * blockDim.x + threadIdx.x;
    if (i < n4) {
        float4 s = reinterpret_cast<const float4*>(p)[i];
#pragma unroll
        for (int j = 1; j < 8; j++) {
            float4 v = reinterpret_cast<const float4*>(p + (size_t)j * n4 * 4)[i];
            s.x += v.x; s.y += v.y; s.z += v.z; s.w += v.w;
        }
        reinterpret_cast<__half2*>(o + (size_t)i * 4)[0] = __floats2half2_rn(s.x, s.y);
        reinterpret_cast<__half2*>(o + (size_t)i * 4)[1] = __floats2half2_rn(s.z, s.w);
    }
}

// ---------------- bf16 split helpers (combine GEMM inputs) ----------------
__global__ void split_kernel(const float* __restrict__ x,
                             __nv_bfloat16* __restrict__ h, __nv_bfloat16* __restrict__ l,
                             int n4)
{
    int i = blockIdx.x * blockDim.x + threadIdx.x;
    if (i < n4) {
        float4 v = reinterpret_cast<const float4*>(x)[i];
        __nv_bfloat162 h0, h1, l0, l1;
        h0.x = __float2bfloat16_rn(v.x); h0.y = __float2bfloat16_rn(v.y);
        h1.x = __float2bfloat16_rn(v.z); h1.y = __float2bfloat16_rn(v.w);
        l0.x = __float2bfloat16_rn(v.x - __bfloat162float(h0.x));
        l0.y = __float2bfloat16_rn(v.y - __bfloat162float(h0.y));
        l1.x = __float2bfloat16_rn(v.z - __bfloat162float(h1.x));
        l1.y = __float2bfloat16_rn(v.w - __bfloat162float(h1.y));
        reinterpret_cast<__nv_bfloat162*>(h + (size_t)i * 4)[0] = h0;
        reinterpret_cast<__nv_bfloat162*>(h + (size_t)i * 4)[1] = h1;
        reinterpret_cast<__nv_bfloat162*>(l + (size_t)i * 4)[0] = l0;
        reinterpret_cast<__nv_bfloat162*>(l + (size_t)i * 4)[1] = l1;
    }
}

__global__ void tsplit_kernel(const float* __restrict__ in, int R, int Ccols,
                              __nv_bfloat16* __restrict__ h, __nv_bfloat16* __restrict__ l)
{
    __shared__ float t[32][33];
    const int r0 = blockIdx.y * 32, c0 = blockIdx.x * 32;
    const int tx = threadIdx.x, ty = threadIdx.y;  // 32 x 8
#pragma unroll
    for (int i = 0; i < 4; i++)
        t[ty + 8 * i][tx] = in[(size_t)(r0 + ty + 8 * i) * Ccols + c0 + tx];
    __syncthreads();
#pragma unroll
    for (int i = 0; i < 4; i++) {
        const int rr = ty + 8 * i;
        const float v = t[tx][rr];
        const size_t o = (size_t)(c0 + rr) * R + r0 + tx;
        __nv_bfloat16 hh = __float2bfloat16_rn(v);
        h[o] = hh;
        l[o] = __float2bfloat16_rn(v - __bfloat162float(hh));
    }
}

// ---------------- fp32 -> fp16 convert ----------------
__global__ void cvt_half(const float* __restrict__ x, __half* __restrict__ y, int n4)
{
    int i = blockIdx.x * blockDim.x + threadIdx.x;
    if (i < n4) {
        float4 v = reinterpret_cast<const float4*>(x)[i];
        reinterpret_cast<__half2*>(y + (size_t)i * 4)[0] = __floats2half2_rn(v.x, v.y);
        reinterpret_cast<__half2*>(y + (size_t)i * 4)[1] = __floats2half2_rn(v.z, v.w);
    }
}

// ---------------- combined bias: c[n] = sum_j wo[n,j]*bv[j] + bo[n] ----------------
__global__ void biasc_kernel(const float* __restrict__ wo, const float* __restrict__ bv,
                             const float* __restrict__ bo, float* __restrict__ c)
{
    __shared__ float red[4];
    const int n = blockIdx.x;
    const int tid = threadIdx.x;  // 128
    float s = 0.0f;
    for (int j = tid; j < DIM; j += 128) s += wo[(size_t)n * DIM + j] * bv[j];
#pragma unroll
    for (int o = 16; o > 0; o >>= 1) s += __shfl_xor_sync(0xFFFFFFFFu, s, o);
    if ((tid & 31) == 0) red[tid >> 5] = s;
    __syncthreads();
    if (tid == 0) c[n] = red[0] + red[1] + red[2] + red[3] + bo[n];
}

// ---------------- LayerNorm(2048) with bias add, fp16 in -> fp16 out ----------------
__global__ void ln_half(const __half* __restrict__ z,
                        const float* __restrict__ c1, const float* __restrict__ c2,
                        const float* __restrict__ g, const float* __restrict__ b,
                        __half* __restrict__ zn)
{
    __shared__ float redS[8], redQ[8];
    const size_t base = (size_t)blockIdx.x * DIM2;
    const int tid = threadIdx.x;  // 256

    __half2 z0a = reinterpret_cast<const __half2*>(z + base + tid * 4)[0];
    __half2 z0b = reinterpret_cast<const __half2*>(z + base + tid * 4)[1];
    __half2 z1a = reinterpret_cast<const __half2*>(z + base + 1024 + tid * 4)[0];
    __half2 z1b = reinterpret_cast<const __half2*>(z + base + 1024 + tid * 4)[1];
    float4 v0, v1;
    { float2 t = __half22float2(z0a); v0.x = t.x; v0.y = t.y; }
    { float2 t = __half22float2(z0b); v0.z = t.x; v0.w = t.y; }
    { float2 t = __half22float2(z1a); v1.x = t.x; v1.y = t.y; }
    { float2 t = __half22float2(z1b); v1.z = t.x; v1.w = t.y; }

    float4 cb0 = *reinterpret_cast<const float4*>(&c1[tid * 4]);
    float4 cb1 = *reinterpret_cast<const float4*>(&c2[tid * 4]);
    v0.x += cb0.x; v0.y += cb0.y; v0.z += cb0.z; v0.w += cb0.w;
    v1.x += cb1.x; v1.y += cb1.y; v1.z += cb1.z; v1.w += cb1.w;

    float s = v0.x + v0.y + v0.z + v0.w + v1.x + v1.y + v1.z + v1.w;
    float q = v0.x * v0.x + v0.y * v0.y + v0.z * v0.z + v0.w * v0.w
            + v1.x * v1.x + v1.y * v1.y + v1.z * v1.z + v1.w * v1.w;
#pragma unroll
    for (int o = 16; o > 0; o >>= 1) {
        s += __shfl_xor_sync(0xFFFFFFFFu, s, o);
        q += __shfl_xor_sync(0xFFFFFFFFu, q, o);
    }
    if ((tid & 31) == 0) { redS[tid >> 5] = s; redQ[tid >> 5] = q; }
    __syncthreads();
    float S = 0.0f, Q = 0.0f;
#pragma unroll
    for (int w = 0; w < 8; w++) { S += redS[w]; Q += redQ[w]; }

    const float mu = S * (1.0f / DIM2);
    const float var = Q * (1.0f / DIM2) - mu * mu;
    const float rstd = rsqrtf(var + 1e-5f);

    float4 g0 = *reinterpret_cast<const float4*>(&g[tid * 4]);
    float4 g1 = *reinterpret_cast<const float4*>(&g[1024 + tid * 4]);
    float4 b0 = *reinterpret_cast<const float4*>(&b[tid * 4]);
    float4 b1 = *reinterpret_cast<const float4*>(&b[1024 + tid * 4]);

    v0.x = (v0.x - mu) * rstd * g0.x + b0.x;
    v0.y = (v0.y - mu) * rstd * g0.y + b0.y;
    v0.z = (v0.z - mu) * rstd * g0.z + b0.z;
    v0.w = (v0.w - mu) * rstd * g0.w + b0.w;
    v1.x = (v1.x - mu) * rstd * g1.x + b1.x;
    v1.y = (v1.y - mu) * rstd * g1.y + b1.y;
    v1.z = (v1.z - mu) * rstd * g1.z + b1.z;
    v1.w = (v1.w - mu) * rstd * g1.w + b1.w;

    reinterpret_cast<__half2*>(zn + base + tid * 4)[0] = __floats2half2_rn(v0.x, v0.y);
    reinterpret_cast<__half2*>(zn + base + tid * 4)[1] = __floats2half2_rn(v0.z, v0.w);
    reinterpret_cast<__half2*>(zn + base + 1024 + tid * 4)[0] = __floats2half2_rn(v1.x, v1.y);
    reinterpret_cast<__half2*>(zn + base + 1024 + tid * 4)[1] = __floats2half2_rn(v1.z, v1.w);
}

// ---------------- launch ----------------
extern "C" void kernel_launch(void* const* d_in, const int* in_sizes, int n_in,
                              void* d_out, int out_size)
{
    const float* x_u    = (const float*)d_in[0];
    const float* x_m    = (const float*)d_in[1];
    const float* w_qkv1 = (const float*)d_in[2];
    const float* b_qkv1 = (const float*)d_in[3];
    const float* w_o1   = (const float*)d_in[4];
    const float* b_o1   = (const float*)d_in[5];
    const float* w_qkv2 = (const float*)d_in[6];
    const float* b_qkv2 = (const float*)d_in[7];
    const float* w_o2   = (const float*)d_in[8];
    const float* b_o2   = (const float*)d_in[9];
    const float* ln_g   = (const float*)d_in[10];
    const float* ln_b   = (const float*)d_in[11];
    const float* w_proj = (const float*)d_in[12];
    const float* b_proj = (const float*)d_in[13];
    float* out = (float*)d_out;

    const float* wv1 = w_qkv1 + (size_t)2 * DIM * DIM;
    const float* bv1 = b_qkv1 + 2 * DIM;
    const float* wv2 = w_qkv2 + (size_t)2 * DIM * DIM;
    const float* bv2 = b_qkv2 + 2 * DIM;

    __half *xuh, *xmh, *zh, *znh, *B1h, *B2h, *wph;
    float *part, *c1, *c2;
    __nv_bfloat16 *wo1_h, *wo1_l, *wo2_h, *wo2_l, *wv1t_h, *wv1t_l, *wv2t_h, *wv2t_l;

    cudaGetSymbolAddress((void**)&xuh, g_xuh);
    cudaGetSymbolAddress((void**)&xmh, g_xmh);
    cudaGetSymbolAddress((void**)&zh, g_zh);
    cudaGetSymbolAddress((void**)&znh, g_znh);
    cudaGetSymbolAddress((void**)&B1h, g_B1h);
    cudaGetSymbolAddress((void**)&B2h, g_B2h);
    cudaGetSymbolAddress((void**)&wph, g_wph);
    cudaGetSymbolAddress((void**)&part, g_part);
    cudaGetSymbolAddress((void**)&c1, g_c1);
    cudaGetSymbolAddress((void**)&c2, g_c2);
    cudaGetSymbolAddress((void**)&wo1_h, g_wo1_hi);   cudaGetSymbolAddress((void**)&wo1_l, g_wo1_lo);
    cudaGetSymbolAddress((void**)&wo2_h, g_wo2_hi);   cudaGetSymbolAddress((void**)&wo2_l, g_wo2_lo);
    cudaGetSymbolAddress((void**)&wv1t_h, g_wv1t_hi); cudaGetSymbolAddress((void**)&wv1t_l, g_wv1t_lo);
    cudaGetSymbolAddress((void**)&wv2t_h, g_wv2t_hi); cudaGetSymbolAddress((void**)&wv2t_l, g_wv2t_lo);

    cudaFuncSetAttribute(mma_gemm_sk, cudaFuncAttributeMaxDynamicSharedMemorySize, SMEM_TOT);
    cudaFuncSetAttribute(hgemm<false, __half>, cudaFuncAttributeMaxDynamicSharedMemorySize, HSMEM);
    cudaFuncSetAttribute(hgemm<true, float>,   cudaFuncAttributeMaxDynamicSharedMemorySize, HSMEM);

    const dim3 gridZ(DIM / 128, BATCH / 256);       // (8, 64)
    const dim3 gridWsk(DIM / NT, DIM / MT, 8);      // (8, 4, 8) split-K

    // ---- path 1 (z1 hgemm is launch #6 -> profiled by ncu -s 5) ----
    split_kernel<<<(DIM * DIM / 4) / 256, 256>>>(w_o1, wo1_h, wo1_l, DIM * DIM / 4);     // 1
    tsplit_kernel<<<dim3(32, 32), dim3(32, 8)>>>(wv1, DIM, DIM, wv1t_h, wv1t_l);         // 2
    mma_gemm_sk<<<gridWsk, 256, SMEM_TOT>>>(wo1_h, wo1_l, wv1t_h, wv1t_l, part, DIM);    // 3
    reduce8_half<<<(DIM * DIM / 4) / 256, 256>>>(part, B1h, DIM * DIM / 4);              // 4
    cvt_half<<<(BATCH * DIM / 4) / 256, 256>>>(x_u, xuh, BATCH * DIM / 4);               // 5
    hgemm<false, __half><<<gridZ, 256, HSMEM>>>(xuh, B1h, zh, DIM2, nullptr, DIM);       // 6

    // ---- path 2 ----
    split_kernel<<<(DIM * DIM / 4) / 256, 256>>>(w_o2, wo2_h, wo2_l, DIM * DIM / 4);
    tsplit_kernel<<<dim3(32, 32), dim3(32, 8)>>>(wv2, DIM, DIM, wv2t_h, wv2t_l);
    mma_gemm_sk<<<gridWsk, 256, SMEM_TOT>>>(wo2_h, wo2_l, wv2t_h, wv2t_l, part, DIM);
    reduce8_half<<<(DIM * DIM / 4) / 256, 256>>>(part, B2h, DIM * DIM / 4);
    cvt_half<<<(BATCH * DIM / 4) / 256, 256>>>(x_m, xmh, BATCH * DIM / 4);
    hgemm<false, __half><<<gridZ, 256, HSMEM>>>(xmh, B2h, zh + DIM, DIM2, nullptr, DIM);

    // ---- combined biases (added inside LN) ----
    biasc_kernel<<<DIM, 128>>>(w_o1, bv1, b_o1, c1);
    biasc_kernel<<<DIM, 128>>>(w_o2, bv2, b_o2, c2);

    // ---- LayerNorm(+bias) fp16 -> fp16 ----
    ln_half<<<BATCH, 256>>>(zh, c1, c2, ln_g, ln_b, znh);

    // ---- proj: out = GELU(zn @ w_proj^T + b_proj) ----
    cvt_half<<<(DIM * DIM2 / 4) / 256, 256>>>(w_proj, wph, DIM * DIM2 / 4);
    hgemm<true, float><<<gridZ, 256, HSMEM>>>(znh, wph, out, DIM, b_proj, DIM2);
}

// round 13
// speedup vs baseline: 8.2185x; 1.0315x over previous
#include <cuda_runtime.h>
#include <cuda_bf16.h>
#include <cuda_fp16.h>
#include <math.h>
#include <stdint.h>

#define BATCH 16384
#define DIM   1024
#define DIM2  2048

// ---------------- scratch (device globals; no allocs) ----------------
__device__ __half  g_xuh[(size_t)BATCH*DIM];
__device__ __half  g_xmh[(size_t)BATCH*DIM];
__device__ __half  g_zh[(size_t)BATCH*DIM2];
__device__ __half  g_znh[(size_t)BATCH*DIM2];
__device__ __half  g_B1h[DIM*DIM], g_B2h[DIM*DIM];
__device__ __half  g_wph[DIM*DIM2];
__device__ float   g_part[8*DIM*DIM];
__device__ float   g_c1[DIM], g_c2[DIM];
__device__ __nv_bfloat16 g_wo_hi[DIM*DIM], g_wo_lo[DIM*DIM];
__device__ __nv_bfloat16 g_wvt_hi[DIM*DIM], g_wvt_lo[DIM*DIM];

// ---------------- low-level helpers (sm_80-baseline PTX only) ----------------
__device__ __forceinline__ uint32_t s2u(const void* p) {
    uint32_t a;
    asm("{ .reg .u64 t; cvta.to.shared.u64 t, %1; cvt.u32.u64 %0, t; }" : "=r"(a) : "l"(p));
    return a;
}
__device__ __forceinline__ void cp16(uint32_t d, const void* s) {
    asm volatile("cp.async.cg.shared.global [%0], [%1], 16;" :: "r"(d), "l"(s));
}
__device__ __forceinline__ void ldm4(uint32_t* r, uint32_t addr) {
    asm volatile("ldmatrix.sync.aligned.m8n8.x4.shared.b16 {%0,%1,%2,%3}, [%4];"
                 : "=r"(r[0]), "=r"(r[1]), "=r"(r[2]), "=r"(r[3]) : "r"(addr));
}
__device__ __forceinline__ void mma_bf16(float* d, const uint32_t* a, const uint32_t* b) {
    asm volatile(
        "mma.sync.aligned.m16n8k16.row.col.f32.bf16.bf16.f32 "
        "{%0,%1,%2,%3}, {%4,%5,%6,%7}, {%8,%9}, {%0,%1,%2,%3};"
        : "+f"(d[0]), "+f"(d[1]), "+f"(d[2]), "+f"(d[3])
        : "r"(a[0]), "r"(a[1]), "r"(a[2]), "r"(a[3]), "r"(b[0]), "r"(b[1]));
}
__device__ __forceinline__ void mma_f16(float* d, const uint32_t* a, uint32_t b0, uint32_t b1) {
    asm volatile(
        "mma.sync.aligned.m16n8k16.row.col.f32.f16.f16.f32 "
        "{%0,%1,%2,%3}, {%4,%5,%6,%7}, {%8,%9}, {%0,%1,%2,%3};"
        : "+f"(d[0]), "+f"(d[1]), "+f"(d[2]), "+f"(d[3])
        : "r"(a[0]), "r"(a[1]), "r"(a[2]), "r"(a[3]), "r"(b0), "r"(b1));
}

// ============================================================================
// fp16 single-pass GEMM (CTA 256x128x64, 8 warps 4m x 2n, 3-stage cp.async)
// ============================================================================
#define HSTR 72
#define HA_TILE (256*HSTR*2)
#define HB_TILE (128*HSTR*2)
#define HSTAGE  (HA_TILE + HB_TILE)
#define HSMEM   (3*HSTAGE)

template <bool GELU, typename OT>
__global__ __launch_bounds__(256, 1)
void hgemm(const __half* __restrict__ A, const __half* __restrict__ B,
           OT* __restrict__ C, int ldc, const float* __restrict__ bias, int K)
{
    extern __shared__ char smem[];
    const uint32_t base = s2u(smem);
    const int tid  = threadIdx.x;
    const int wid  = tid >> 5;
    const int lane = tid & 31;
    const int m0 = blockIdx.y * 256;
    const int n0 = blockIdx.x * 128;
    const int warp_m0 = (wid & 3) * 64;
    const int warp_n0 = (wid >> 2) * 64;

    float acc[4][8][4];
#pragma unroll
    for (int i = 0; i < 4; i++)
#pragma unroll
        for (int j = 0; j < 8; j++)
#pragma unroll
            for (int q = 0; q < 4; q++) acc[i][j][q] = 0.0f;

    auto load_stage = [&](int s, int k0) {
        const uint32_t stA = base + s * HSTAGE;
        const uint32_t stB = stA + HA_TILE;
        for (int i = tid; i < 256 * 8; i += 256) {
            const int r = i >> 3, seg = i & 7;
            cp16(stA + (uint32_t)(r * (HSTR * 2) + seg * 16),
                 A + (size_t)(m0 + r) * K + k0 + seg * 8);
        }
        for (int i = tid; i < 128 * 8; i += 256) {
            const int r = i >> 3, seg = i & 7;
            cp16(stB + (uint32_t)(r * (HSTR * 2) + seg * 16),
                 B + (size_t)(n0 + r) * K + k0 + seg * 8);
        }
        asm volatile("cp.async.commit_group;" ::: "memory");
    };

    const int nk = K >> 6;
    load_stage(0, 0);
    load_stage(1, 64);

    const int a_row = warp_m0 + (lane & 15);
    const int a_col = (lane >> 4) << 3;
    const int b_row = warp_n0 + (lane & 7) + ((lane >> 4) << 3);
    const int b_col = ((lane >> 3) & 1) << 3;

    for (int i = 0; i < nk; i++) {
        if (i + 2 <= nk) asm volatile("cp.async.wait_group 1;" ::: "memory");
        else             asm volatile("cp.async.wait_group 0;" ::: "memory");
        __syncthreads();
        if (i + 2 < nk) load_stage((i + 2) % 3, (i + 2) * 64);

        const uint32_t stA = base + (i % 3) * HSTAGE;
        const uint32_t stB = stA + HA_TILE;

#pragma unroll
        for (int ks = 0; ks < 4; ks++) {
            const int k0 = ks * 16;
            uint32_t af[4][4], bf[4][4];
#pragma unroll
            for (int mf = 0; mf < 4; mf++)
                ldm4(af[mf], stA + (uint32_t)((a_row + mf * 16) * HSTR + k0 + a_col) * 2);
#pragma unroll
            for (int bp = 0; bp < 4; bp++)
                ldm4(bf[bp], stB + (uint32_t)((b_row + bp * 16) * HSTR + k0 + b_col) * 2);
#pragma unroll
            for (int mf = 0; mf < 4; mf++)
#pragma unroll
                for (int bp = 0; bp < 4; bp++) {
                    mma_f16(acc[mf][2 * bp + 0], af[mf], bf[bp][0], bf[bp][1]);
                    mma_f16(acc[mf][2 * bp + 1], af[mf], bf[bp][2], bf[bp][3]);
                }
        }
    }

    const int r_base = m0 + warp_m0 + (lane >> 2);
    const int c_base = n0 + warp_n0 + ((lane & 3) << 1);
#pragma unroll
    for (int mf = 0; mf < 4; mf++) {
        const int row0 = r_base + mf * 16;
#pragma unroll
        for (int nf = 0; nf < 8; nf++) {
            const int cc = c_base + nf * 8;
            float b0 = 0.0f, b1 = 0.0f;
            if (bias) { b0 = bias[cc]; b1 = bias[cc + 1]; }
            float v0 = acc[mf][nf][0] + b0;
            float v1 = acc[mf][nf][1] + b1;
            float v2 = acc[mf][nf][2] + b0;
            float v3 = acc[mf][nf][3] + b1;
            if (GELU) {
                v0 = 0.5f * v0 * (1.0f + erff(v0 * 0.70710678118654752f));
                v1 = 0.5f * v1 * (1.0f + erff(v1 * 0.70710678118654752f));
                v2 = 0.5f * v2 * (1.0f + erff(v2 * 0.70710678118654752f));
                v3 = 0.5f * v3 * (1.0f + erff(v3 * 0.70710678118654752f));
            }
            if (sizeof(OT) == 4) {
                *reinterpret_cast<float2*>((float*)C + (size_t)row0 * ldc + cc) = make_float2(v0, v1);
                *reinterpret_cast<float2*>((float*)C + (size_t)(row0 + 8) * ldc + cc) = make_float2(v2, v3);
            } else {
                *reinterpret_cast<__half2*>((__half*)C + (size_t)row0 * ldc + cc) = __floats2half2_rn(v0, v1);
                *reinterpret_cast<__half2*>((__half*)C + (size_t)(row0 + 8) * ldc + cc) = __floats2half2_rn(v2, v3);
            }
        }
    }
}

// ============================================================================
// bf16x3 split-K GEMM for the 1024^3 weight combines (blockIdx.z = K-slice of 128)
// ============================================================================
#define MT 256
#define NT 128
#define KC 64
#define KSLICE 128
#define STRIDE 72
#define A_TILE (MT*STRIDE*2)
#define B_TILE (NT*STRIDE*2)
#define STAGE  (2*A_TILE + 2*B_TILE)
#define SMEM_TOT (2*STAGE)

__global__ __launch_bounds__(256, 1)
void mma_gemm_sk(const __nv_bfloat16* __restrict__ Ah, const __nv_bfloat16* __restrict__ Al,
                 const __nv_bfloat16* __restrict__ Bh, const __nv_bfloat16* __restrict__ Bl,
                 float* __restrict__ Cpart, int lda)
{
    extern __shared__ char smem[];
    const uint32_t base = s2u(smem);
    const int tid  = threadIdx.x;
    const int wid  = tid >> 5;
    const int lane = tid & 31;
    const int m0 = blockIdx.y * MT;
    const int n0 = blockIdx.x * NT;
    const int koff = blockIdx.z * KSLICE;
    float* Cp = Cpart + (size_t)blockIdx.z * DIM * DIM;
    const int warp_m0 = (wid & 3) * 64;
    const int warp_n0 = (wid >> 2) * 64;

    float acc[4][8][4];
#pragma unroll
    for (int i = 0; i < 4; i++)
#pragma unroll
        for (int j = 0; j < 8; j++)
#pragma unroll
            for (int q = 0; q < 4; q++) acc[i][j][q] = 0.0f;

    auto load_stage = [&](int s, int k0) {
        const uint32_t stA_h = base + s * STAGE;
        const uint32_t stA_l = stA_h + A_TILE;
        const uint32_t stB_h = stA_h + 2 * A_TILE;
        const uint32_t stB_l = stB_h + B_TILE;
        for (int i = tid; i < MT * 8; i += 256) {
            const int r = i >> 3, seg = i & 7;
            const uint32_t off = (uint32_t)(r * (STRIDE * 2) + seg * 16);
            const size_t gs = (size_t)(m0 + r) * lda + k0 + seg * 8;
            cp16(stA_h + off, Ah + gs);
            cp16(stA_l + off, Al + gs);
        }
        for (int i = tid; i < NT * 8; i += 256) {
            const int r = i >> 3, seg = i & 7;
            const uint32_t off = (uint32_t)(r * (STRIDE * 2) + seg * 16);
            const size_t gs = (size_t)(n0 + r) * lda + k0 + seg * 8;
            cp16(stB_h + off, Bh + gs);
            cp16(stB_l + off, Bl + gs);
        }
        asm volatile("cp.async.commit_group;" ::: "memory");
    };

    const int nk = KSLICE / KC;
    load_stage(0, koff);
    load_stage(1, koff + KC);

    const int a_row = warp_m0 + (lane & 15);
    const int a_col = (lane >> 4) << 3;
    const int b_row = warp_n0 + (lane & 7) + ((lane >> 4) << 3);
    const int b_col = ((lane >> 3) & 1) << 3;

    for (int i = 0; i < nk; i++) {
        if (i + 1 < nk) asm volatile("cp.async.wait_group 1;" ::: "memory");
        else            asm volatile("cp.async.wait_group 0;" ::: "memory");
        __syncthreads();

        const uint32_t stA_h = base + (i & 1) * STAGE;
        const uint32_t stA_l = stA_h + A_TILE;
        const uint32_t stB_h = stA_h + 2 * A_TILE;
        const uint32_t stB_l = stB_h + B_TILE;

#pragma unroll
        for (int ks = 0; ks < 4; ks++) {
            const int k0 = ks * 16;
            uint32_t ah[4][4], al[4][4], bh[4][4], bl[4][4];
#pragma unroll
            for (int mf = 0; mf < 4; mf++) {
                const uint32_t ao = (uint32_t)((a_row + mf * 16) * STRIDE + k0 + a_col) * 2;
                ldm4(ah[mf], stA_h + ao);
                ldm4(al[mf], stA_l + ao);
            }
#pragma unroll
            for (int bp = 0; bp < 4; bp++) {
                const uint32_t bo = (uint32_t)((b_row + bp * 16) * STRIDE + k0 + b_col) * 2;
                ldm4(bh[bp], stB_h + bo);
                ldm4(bl[bp], stB_l + bo);
            }
#pragma unroll
            for (int mf = 0; mf < 4; mf++)
#pragma unroll
                for (int bp = 0; bp < 4; bp++) {
                    mma_bf16(acc[mf][2 * bp + 0], ah[mf], &bh[bp][0]);
                    mma_bf16(acc[mf][2 * bp + 1], ah[mf], &bh[bp][2]);
                    mma_bf16(acc[mf][2 * bp + 0], ah[mf], &bl[bp][0]);
                    mma_bf16(acc[mf][2 * bp + 1], ah[mf], &bl[bp][2]);
                    mma_bf16(acc[mf][2 * bp + 0], al[mf], &bh[bp][0]);
                    mma_bf16(acc[mf][2 * bp + 1], al[mf], &bh[bp][2]);
                }
        }
        __syncthreads();
    }

    const int r_base = m0 + warp_m0 + (lane >> 2);
    const int c_base = n0 + warp_n0 + ((lane & 3) << 1);
#pragma unroll
    for (int mf = 0; mf < 4; mf++)
#pragma unroll
        for (int nf = 0; nf < 8; nf++) {
            const int cc = c_base + nf * 8;
            const int row0 = r_base + mf * 16;
            *reinterpret_cast<float2*>(&Cp[(size_t)row0 * DIM + cc]) =
                make_float2(acc[mf][nf][0], acc[mf][nf][1]);
            *reinterpret_cast<float2*>(&Cp[(size_t)(row0 + 8) * DIM + cc]) =
                make_float2(acc[mf][nf][2], acc[mf][nf][3]);
        }
}

// ---------------- reduce 8 fp32 partials -> fp16 (grid-stride) ----------------
__global__ void reduce8_half(const float* __restrict__ p, __half* __restrict__ o, int n4)
{
    const int stride = gridDim.x * blockDim.x;
    for (int i = blockIdx.x * blockDim.x + threadIdx.x; i < n4; i += stride) {
        float4 s = reinterpret_cast<const float4*>(p)[i];
#pragma unroll
        for (int j = 1; j < 8; j++) {
            float4 v = reinterpret_cast<const float4*>(p + (size_t)j * n4 * 4)[i];
            s.x += v.x; s.y += v.y; s.z += v.z; s.w += v.w;
        }
        reinterpret_cast<__half2*>(o + (size_t)i * 4)[0] = __floats2half2_rn(s.x, s.y);
        reinterpret_cast<__half2*>(o + (size_t)i * 4)[1] = __floats2half2_rn(s.z, s.w);
    }
}

// ============================================================================
// fused prep kernel. Block roles (all 256 threads, 4096 floats per cvt block):
//   [0, NCVT)                      : cvt x fp32->fp16          (x: 16.7M floats)
//   [NCVT, +NSPL)                  : split wo -> bf16 hi/lo    (wo: 1.05M)
//   [+, +NTSP)                     : transpose-split wv        (wv: 1024x1024)
//   [+, +NBIA)                     : combined bias             (1024 outputs)
//   [+, +NWPJ)                     : cvt wproj fp32->fp16      (wproj: 2.1M)
// ============================================================================
#define NCVT   4096     // 4096 blk x 4096 floats = 16,777,216 ✓
#define NSPL   256      // 256  blk x 4096        = 1,048,576  ✓
#define NTSP   1024     // 32x32 tiles of 1024^2  ✓
#define NBIA   1024
#define NWPJ   512      // 512  blk x 4096        = 2,097,152  ✓
#define PREP_GRID_1 (NCVT + NSPL + NTSP + NBIA)
#define PREP_GRID_2 (NCVT + NSPL + NTSP + NBIA + NWPJ)

__global__ __launch_bounds__(256)
void prep(const float* __restrict__ x, __half* __restrict__ xh,
          const float* __restrict__ wo,
          __nv_bfloat16* __restrict__ wo_h, __nv_bfloat16* __restrict__ wo_l,
          const float* __restrict__ wv,
          __nv_bfloat16* __restrict__ wvt_h, __nv_bfloat16* __restrict__ wvt_l,
          const float* __restrict__ bv, const float* __restrict__ bo,
          float* __restrict__ c,
          const float* __restrict__ wp, __half* __restrict__ wph)
{
    const int bx = blockIdx.x;
    const int tid = threadIdx.x;

    if (bx < NCVT) {
        const int base = bx * 4096 + tid * 4;
#pragma unroll
        for (int k = 0; k < 4; k++) {
            const int idx = base + k * 1024;
            float4 v = *reinterpret_cast<const float4*>(x + idx);
            reinterpret_cast<__half2*>(xh + idx)[0] = __floats2half2_rn(v.x, v.y);
            reinterpret_cast<__half2*>(xh + idx)[1] = __floats2half2_rn(v.z, v.w);
        }
        return;
    }
    if (bx < NCVT + NSPL) {
        const int base = (bx - NCVT) * 4096 + tid * 4;
#pragma unroll
        for (int k = 0; k < 4; k++) {
            const int idx = base + k * 1024;
            float4 v = *reinterpret_cast<const float4*>(wo + idx);
            __nv_bfloat162 h0, h1, l0, l1;
            h0.x = __float2bfloat16_rn(v.x); h0.y = __float2bfloat16_rn(v.y);
            h1.x = __float2bfloat16_rn(v.z); h1.y = __float2bfloat16_rn(v.w);
            l0.x = __float2bfloat16_rn(v.x - __bfloat162float(h0.x));
            l0.y = __float2bfloat16_rn(v.y - __bfloat162float(h0.y));
            l1.x = __float2bfloat16_rn(v.z - __bfloat162float(h1.x));
            l1.y = __float2bfloat16_rn(v.w - __bfloat162float(h1.y));
            reinterpret_cast<__nv_bfloat162*>(wo_h + idx)[0] = h0;
            reinterpret_cast<__nv_bfloat162*>(wo_h + idx)[1] = h1;
            reinterpret_cast<__nv_bfloat162*>(wo_l + idx)[0] = l0;
            reinterpret_cast<__nv_bfloat162*>(wo_l + idx)[1] = l1;
        }
        return;
    }
    if (bx < NCVT + NSPL + NTSP) {
        __shared__ float t[32][33];
        const int bi = bx - NCVT - NSPL;
        const int r0 = (bi >> 5) * 32, c0 = (bi & 31) * 32;
        const int tx = tid & 31, ty = tid >> 5;  // 32 x 8
#pragma unroll
        for (int i = 0; i < 4; i++)
            t[ty + 8 * i][tx] = wv[(size_t)(r0 + ty + 8 * i) * DIM + c0 + tx];
        __syncthreads();
#pragma unroll
        for (int i = 0; i < 4; i++) {
            const int rr = ty + 8 * i;
            const float v = t[tx][rr];
            const size_t o = (size_t)(c0 + rr) * DIM + r0 + tx;
            __nv_bfloat16 hh = __float2bfloat16_rn(v);
            wvt_h[o] = hh;
            wvt_l[o] = __float2bfloat16_rn(v - __bfloat162float(hh));
        }
        return;
    }
    if (bx < NCVT + NSPL + NTSP + NBIA) {
        __shared__ float red[8];
        const int n = bx - NCVT - NSPL - NTSP;
        float s = 0.0f;
        for (int j = tid; j < DIM; j += 256) s += wo[(size_t)n * DIM + j] * bv[j];
#pragma unroll
        for (int o = 16; o > 0; o >>= 1) s += __shfl_xor_sync(0xFFFFFFFFu, s, o);
        if ((tid & 31) == 0) red[tid >> 5] = s;
        __syncthreads();
        if (tid == 0) {
            float t2 = bo[n];
#pragma unroll
            for (int w = 0; w < 8; w++) t2 += red[w];
            c[n] = t2;
        }
        return;
    }
    {
        const int base = (bx - NCVT - NSPL - NTSP - NBIA) * 4096 + tid * 4;
#pragma unroll
        for (int k = 0; k < 4; k++) {
            const int idx = base + k * 1024;
            float4 v = *reinterpret_cast<const float4*>(wp + idx);
            reinterpret_cast<__half2*>(wph + idx)[0] = __floats2half2_rn(v.x, v.y);
            reinterpret_cast<__half2*>(wph + idx)[1] = __floats2half2_rn(v.z, v.w);
        }
    }
}

// ---------------- LayerNorm(2048)+bias, fp16 in -> fp16 out (16B/thread) ----------------
__global__ __launch_bounds__(256)
void ln_half(const __half* __restrict__ z,
             const float* __restrict__ c1, const float* __restrict__ c2,
             const float* __restrict__ g, const float* __restrict__ b,
             __half* __restrict__ zn)
{
    __shared__ float redS[8], redQ[8];
    const size_t base = (size_t)blockIdx.x * DIM2;
    const int tid = threadIdx.x;       // 256
    const int col = tid * 8;

    uint4 zr = *reinterpret_cast<const uint4*>(z + base + col);
    float f[8];
    {
        float2 t0 = __half22float2(*reinterpret_cast<__half2*>(&zr.x));
        float2 t1 = __half22float2(*reinterpret_cast<__half2*>(&zr.y));
        float2 t2 = __half22float2(*reinterpret_cast<__half2*>(&zr.z));
        float2 t3 = __half22float2(*reinterpret_cast<__half2*>(&zr.w));
        f[0] = t0.x; f[1] = t0.y; f[2] = t1.x; f[3] = t1.y;
        f[4] = t2.x; f[5] = t2.y; f[6] = t3.x; f[7] = t3.y;
    }
    const float* cb = (col < DIM) ? (c1 + col) : (c2 + col - DIM);
    float4 cb0 = *reinterpret_cast<const float4*>(cb);
    float4 cb1 = *reinterpret_cast<const float4*>(cb + 4);
    f[0] += cb0.x; f[1] += cb0.y; f[2] += cb0.z; f[3] += cb0.w;
    f[4] += cb1.x; f[5] += cb1.y; f[6] += cb1.z; f[7] += cb1.w;

    float s = 0.0f, q = 0.0f;
#pragma unroll
    for (int i = 0; i < 8; i++) { s += f[i]; q += f[i] * f[i]; }
#pragma unroll
    for (int o = 16; o > 0; o >>= 1) {
        s += __shfl_xor_sync(0xFFFFFFFFu, s, o);
        q += __shfl_xor_sync(0xFFFFFFFFu, q, o);
    }
    if ((tid & 31) == 0) { redS[tid >> 5] = s; redQ[tid >> 5] = q; }
    __syncthreads();
    float S = 0.0f, Q = 0.0f;
#pragma unroll
    for (int w = 0; w < 8; w++) { S += redS[w]; Q += redQ[w]; }

    const float mu = S * (1.0f / DIM2);
    const float var = Q * (1.0f / DIM2) - mu * mu;
    const float rstd = rsqrtf(var + 1e-5f);

    float4 g0 = *reinterpret_cast<const float4*>(g + col);
    float4 g1 = *reinterpret_cast<const float4*>(g + col + 4);
    float4 b0 = *reinterpret_cast<const float4*>(b + col);
    float4 b1 = *reinterpret_cast<const float4*>(b + col + 4);

    f[0] = (f[0] - mu) * rstd * g0.x + b0.x;
    f[1] = (f[1] - mu) * rstd * g0.y + b0.y;
    f[2] = (f[2] - mu) * rstd * g0.z + b0.z;
    f[3] = (f[3] - mu) * rstd * g0.w + b0.w;
    f[4] = (f[4] - mu) * rstd * g1.x + b1.x;
    f[5] = (f[5] - mu) * rstd * g1.y + b1.y;
    f[6] = (f[6] - mu) * rstd * g1.z + b1.z;
    f[7] = (f[7] - mu) * rstd * g1.w + b1.w;

    uint4 outv;
    *reinterpret_cast<__half2*>(&outv.x) = __floats2half2_rn(f[0], f[1]);
    *reinterpret_cast<__half2*>(&outv.y) = __floats2half2_rn(f[2], f[3]);
    *reinterpret_cast<__half2*>(&outv.z) = __floats2half2_rn(f[4], f[5]);
    *reinterpret_cast<__half2*>(&outv.w) = __floats2half2_rn(f[6], f[7]);
    *reinterpret_cast<uint4*>(zn + base + col) = outv;
}

// ---------------- launch ----------------
extern "C" void kernel_launch(void* const* d_in, const int* in_sizes, int n_in,
                              void* d_out, int out_size)
{
    const float* x_u    = (const float*)d_in[0];
    const float* x_m    = (const float*)d_in[1];
    const float* w_qkv1 = (const float*)d_in[2];
    const float* b_qkv1 = (const float*)d_in[3];
    const float* w_o1   = (const float*)d_in[4];
    const float* b_o1   = (const float*)d_in[5];
    const float* w_qkv2 = (const float*)d_in[6];
    const float* b_qkv2 = (const float*)d_in[7];
    const float* w_o2   = (const float*)d_in[8];
    const float* b_o2   = (const float*)d_in[9];
    const float* ln_g   = (const float*)d_in[10];
    const float* ln_b   = (const float*)d_in[11];
    const float* w_proj = (const float*)d_in[12];
    const float* b_proj = (const float*)d_in[13];
    float* out = (float*)d_out;

    const float* wv1 = w_qkv1 + (size_t)2 * DIM * DIM;
    const float* bv1 = b_qkv1 + 2 * DIM;
    const float* wv2 = w_qkv2 + (size_t)2 * DIM * DIM;
    const float* bv2 = b_qkv2 + 2 * DIM;

    __half *xuh, *xmh, *zh, *znh, *B1h, *B2h, *wph;
    float *part, *c1, *c2;
    __nv_bfloat16 *wo_h, *wo_l, *wvt_h, *wvt_l;

    cudaGetSymbolAddress((void**)&xuh, g_xuh);
    cudaGetSymbolAddress((void**)&xmh, g_xmh);
    cudaGetSymbolAddress((void**)&zh, g_zh);
    cudaGetSymbolAddress((void**)&znh, g_znh);
    cudaGetSymbolAddress((void**)&B1h, g_B1h);
    cudaGetSymbolAddress((void**)&B2h, g_B2h);
    cudaGetSymbolAddress((void**)&wph, g_wph);
    cudaGetSymbolAddress((void**)&part, g_part);
    cudaGetSymbolAddress((void**)&c1, g_c1);
    cudaGetSymbolAddress((void**)&c2, g_c2);
    cudaGetSymbolAddress((void**)&wo_h, g_wo_hi);   cudaGetSymbolAddress((void**)&wo_l, g_wo_lo);
    cudaGetSymbolAddress((void**)&wvt_h, g_wvt_hi); cudaGetSymbolAddress((void**)&wvt_l, g_wvt_lo);

    cudaFuncSetAttribute(mma_gemm_sk, cudaFuncAttributeMaxDynamicSharedMemorySize, SMEM_TOT);
    cudaFuncSetAttribute(hgemm<false, __half>, cudaFuncAttributeMaxDynamicSharedMemorySize, HSMEM);
    cudaFuncSetAttribute(hgemm<true, float>,   cudaFuncAttributeMaxDynamicSharedMemorySize, HSMEM);

    const dim3 gridZ(DIM / 128, BATCH / 256);       // (8, 64)
    const dim3 gridWsk(DIM / NT, DIM / MT, 8);      // (8, 4, 8) split-K

    // ---- path 1: prep(1), combine(2), reduce(3), z1-hgemm(4 <- ncu profiles #4) ----
    prep<<<PREP_GRID_1, 256>>>(x_u, xuh, w_o1, wo_h, wo_l, wv1, wvt_h, wvt_l,
                               bv1, b_o1, c1, nullptr, nullptr);
    mma_gemm_sk<<<gridWsk, 256, SMEM_TOT>>>(wo_h, wo_l, wvt_h, wvt_l, part, DIM);
    reduce8_half<<<512, 256>>>(part, B1h, DIM * DIM / 4);
    hgemm<false, __half><<<gridZ, 256, HSMEM>>>(xuh, B1h, zh, DIM2, nullptr, DIM);

    // ---- path 2 (reuses wo/wvt scratch after path-1 combine is done) ----
    prep<<<PREP_GRID_2, 256>>>(x_m, xmh, w_o2, wo_h, wo_l, wv2, wvt_h, wvt_l,
                               bv2, b_o2, c2, w_proj, wph);
    mma_gemm_sk<<<gridWsk, 256, SMEM_TOT>>>(wo_h, wo_l, wvt_h, wvt_l, part, DIM);
    reduce8_half<<<512, 256>>>(part, B2h, DIM * DIM / 4);
    hgemm<false, __half><<<gridZ, 256, HSMEM>>>(xmh, B2h, zh + DIM, DIM2, nullptr, DIM);

    // ---- LayerNorm(+bias) fp16 -> fp16 ----
    ln_half<<<BATCH, 256>>>(zh, c1, c2, ln_g, ln_b, znh);

    // ---- proj: out = GELU(zn @ w_proj^T + b_proj) ----
    hgemm<true, float><<<gridZ, 256, HSMEM>>>(znh, wph, out, DIM, b_proj, DIM2);
}

// round 14
// speedup vs baseline: 8.4315x; 1.0259x over previous
#include <cuda_runtime.h>
#include <cuda_bf16.h>
#include <cuda_fp16.h>
#include <math.h>
#include <stdint.h>

#define BATCH 16384
#define DIM   1024
#define DIM2  2048

// ---------------- scratch (device globals; no allocs) ----------------
__device__ __half  g_xuh[(size_t)BATCH*DIM];
__device__ __half  g_xmh[(size_t)BATCH*DIM];
__device__ __half  g_zh[(size_t)BATCH*DIM2];
__device__ __half  g_znh[(size_t)BATCH*DIM2];
__device__ __half  g_B1h[DIM*DIM], g_B2h[DIM*DIM];
__device__ __half  g_wph[DIM*DIM2];
__device__ float   g_part[8*DIM*DIM];
__device__ float   g_c1[DIM], g_c2[DIM];
__device__ __nv_bfloat16 g_wo_hi[DIM*DIM], g_wo_lo[DIM*DIM];
__device__ __nv_bfloat16 g_wvt_hi[DIM*DIM], g_wvt_lo[DIM*DIM];

// ---------------- low-level helpers (sm_80-baseline PTX only) ----------------
__device__ __forceinline__ uint32_t s2u(const void* p) {
    uint32_t a;
    asm("{ .reg .u64 t; cvta.to.shared.u64 t, %1; cvt.u32.u64 %0, t; }" : "=r"(a) : "l"(p));
    return a;
}
__device__ __forceinline__ void cp16(uint32_t d, const void* s) {
    asm volatile("cp.async.cg.shared.global [%0], [%1], 16;" :: "r"(d), "l"(s));
}
__device__ __forceinline__ void ldm4(uint32_t* r, uint32_t addr) {
    asm volatile("ldmatrix.sync.aligned.m8n8.x4.shared.b16 {%0,%1,%2,%3}, [%4];"
                 : "=r"(r[0]), "=r"(r[1]), "=r"(r[2]), "=r"(r[3]) : "r"(addr));
}
__device__ __forceinline__ void mma_bf16(float* d, const uint32_t* a, const uint32_t* b) {
    asm volatile(
        "mma.sync.aligned.m16n8k16.row.col.f32.bf16.bf16.f32 "
        "{%0,%1,%2,%3}, {%4,%5,%6,%7}, {%8,%9}, {%0,%1,%2,%3};"
        : "+f"(d[0]), "+f"(d[1]), "+f"(d[2]), "+f"(d[3])
        : "r"(a[0]), "r"(a[1]), "r"(a[2]), "r"(a[3]), "r"(b[0]), "r"(b[1]));
}
__device__ __forceinline__ void mma_f16(float* d, const uint32_t* a, uint32_t b0, uint32_t b1) {
    asm volatile(
        "mma.sync.aligned.m16n8k16.row.col.f32.f16.f16.f32 "
        "{%0,%1,%2,%3}, {%4,%5,%6,%7}, {%8,%9}, {%0,%1,%2,%3};"
        : "+f"(d[0]), "+f"(d[1]), "+f"(d[2]), "+f"(d[3])
        : "r"(a[0]), "r"(a[1]), "r"(a[2]), "r"(a[3]), "r"(b0), "r"(b1));
}

// ============================================================================
// fp16 single-pass GEMM (CTA 256x128x64, 512 threads = 16 warps 4m x 4n,
// warp tile 64x32, 3-stage cp.async). 64 acc regs/thread -> <=128 total.
// ============================================================================
#define HSTR 72
#define HA_TILE (256*HSTR*2)
#define HB_TILE (128*HSTR*2)
#define HSTAGE  (HA_TILE + HB_TILE)
#define HSMEM   (3*HSTAGE)

template <bool GELU, typename OT>
__global__ __launch_bounds__(512, 1)
void hgemm(const __half* __restrict__ A, const __half* __restrict__ B,
           OT* __restrict__ C, int ldc, const float* __restrict__ bias, int K)
{
    extern __shared__ char smem[];
    const uint32_t base = s2u(smem);
    const int tid  = threadIdx.x;
    const int wid  = tid >> 5;
    const int lane = tid & 31;
    const int m0 = blockIdx.y * 256;
    const int n0 = blockIdx.x * 128;
    const int warp_m0 = (wid & 3) * 64;       // 4 warps cover M=256
    const int warp_n0 = (wid >> 2) * 32;      // 4 warps cover N=128

    float acc[4][4][4];                        // 4 m-frags x 4 n8-frags
#pragma unroll
    for (int i = 0; i < 4; i++)
#pragma unroll
        for (int j = 0; j < 4; j++)
#pragma unroll
            for (int q = 0; q < 4; q++) acc[i][j][q] = 0.0f;

    auto load_stage = [&](int s, int k0) {
        const uint32_t stA = base + s * HSTAGE;
        const uint32_t stB = stA + HA_TILE;
        for (int i = tid; i < 256 * 8; i += 512) {
            const int r = i >> 3, seg = i & 7;
            cp16(stA + (uint32_t)(r * (HSTR * 2) + seg * 16),
                 A + (size_t)(m0 + r) * K + k0 + seg * 8);
        }
        for (int i = tid; i < 128 * 8; i += 512) {
            const int r = i >> 3, seg = i & 7;
            cp16(stB + (uint32_t)(r * (HSTR * 2) + seg * 16),
                 B + (size_t)(n0 + r) * K + k0 + seg * 8);
        }
        asm volatile("cp.async.commit_group;" ::: "memory");
    };

    const int nk = K >> 6;
    load_stage(0, 0);
    load_stage(1, 64);

    const int a_row = warp_m0 + (lane & 15);
    const int a_col = (lane >> 4) << 3;
    const int b_row = warp_n0 + (lane & 7) + ((lane >> 4) << 3);
    const int b_col = ((lane >> 3) & 1) << 3;

    for (int i = 0; i < nk; i++) {
        if (i + 2 <= nk) asm volatile("cp.async.wait_group 1;" ::: "memory");
        else             asm volatile("cp.async.wait_group 0;" ::: "memory");
        __syncthreads();
        if (i + 2 < nk) load_stage((i + 2) % 3, (i + 2) * 64);

        const uint32_t stA = base + (i % 3) * HSTAGE;
        const uint32_t stB = stA + HA_TILE;

#pragma unroll
        for (int ks = 0; ks < 4; ks++) {
            const int k0 = ks * 16;
            uint32_t af[4][4], bf[2][4];
#pragma unroll
            for (int mf = 0; mf < 4; mf++)
                ldm4(af[mf], stA + (uint32_t)((a_row + mf * 16) * HSTR + k0 + a_col) * 2);
#pragma unroll
            for (int bp = 0; bp < 2; bp++)
                ldm4(bf[bp], stB + (uint32_t)((b_row + bp * 16) * HSTR + k0 + b_col) * 2);
#pragma unroll
            for (int mf = 0; mf < 4; mf++)
#pragma unroll
                for (int bp = 0; bp < 2; bp++) {
                    mma_f16(acc[mf][2 * bp + 0], af[mf], bf[bp][0], bf[bp][1]);
                    mma_f16(acc[mf][2 * bp + 1], af[mf], bf[bp][2], bf[bp][3]);
                }
        }
    }

    // ---- epilogue ----
    const int r_base = m0 + warp_m0 + (lane >> 2);
    const int c_base = n0 + warp_n0 + ((lane & 3) << 1);
#pragma unroll
    for (int mf = 0; mf < 4; mf++) {
        const int row0 = r_base + mf * 16;
#pragma unroll
        for (int nf = 0; nf < 4; nf++) {
            const int cc = c_base + nf * 8;
            float b0 = 0.0f, b1 = 0.0f;
            if (bias) { b0 = bias[cc]; b1 = bias[cc + 1]; }
            float v0 = acc[mf][nf][0] + b0;
            float v1 = acc[mf][nf][1] + b1;
            float v2 = acc[mf][nf][2] + b0;
            float v3 = acc[mf][nf][3] + b1;
            if (GELU) {
                v0 = 0.5f * v0 * (1.0f + erff(v0 * 0.70710678118654752f));
                v1 = 0.5f * v1 * (1.0f + erff(v1 * 0.70710678118654752f));
                v2 = 0.5f * v2 * (1.0f + erff(v2 * 0.70710678118654752f));
                v3 = 0.5f * v3 * (1.0f + erff(v3 * 0.70710678118654752f));
            }
            if (sizeof(OT) == 4) {
                *reinterpret_cast<float2*>((float*)C + (size_t)row0 * ldc + cc) = make_float2(v0, v1);
                *reinterpret_cast<float2*>((float*)C + (size_t)(row0 + 8) * ldc + cc) = make_float2(v2, v3);
            } else {
                *reinterpret_cast<__half2*>((__half*)C + (size_t)row0 * ldc + cc) = __floats2half2_rn(v0, v1);
                *reinterpret_cast<__half2*>((__half*)C + (size_t)(row0 + 8) * ldc + cc) = __floats2half2_rn(v2, v3);
            }
        }
    }
}

// ============================================================================
// bf16x3 split-K GEMM for the 1024^3 weight combines (blockIdx.z = K-slice of 128)
// ============================================================================
#define MT 256
#define NT 128
#define KC 64
#define KSLICE 128
#define STRIDE 72
#define A_TILE (MT*STRIDE*2)
#define B_TILE (NT*STRIDE*2)
#define STAGE  (2*A_TILE + 2*B_TILE)
#define SMEM_TOT (2*STAGE)

__global__ __launch_bounds__(256, 1)
void mma_gemm_sk(const __nv_bfloat16* __restrict__ Ah, const __nv_bfloat16* __restrict__ Al,
                 const __nv_bfloat16* __restrict__ Bh, const __nv_bfloat16* __restrict__ Bl,
                 float* __restrict__ Cpart, int lda)
{
    extern __shared__ char smem[];
    const uint32_t base = s2u(smem);
    const int tid  = threadIdx.x;
    const int wid  = tid >> 5;
    const int lane = tid & 31;
    const int m0 = blockIdx.y * MT;
    const int n0 = blockIdx.x * NT;
    const int koff = blockIdx.z * KSLICE;
    float* Cp = Cpart + (size_t)blockIdx.z * DIM * DIM;
    const int warp_m0 = (wid & 3) * 64;
    const int warp_n0 = (wid >> 2) * 64;

    float acc[4][8][4];
#pragma unroll
    for (int i = 0; i < 4; i++)
#pragma unroll
        for (int j = 0; j < 8; j++)
#pragma unroll
            for (int q = 0; q < 4; q++) acc[i][j][q] = 0.0f;

    auto load_stage = [&](int s, int k0) {
        const uint32_t stA_h = base + s * STAGE;
        const uint32_t stA_l = stA_h + A_TILE;
        const uint32_t stB_h = stA_h + 2 * A_TILE;
        const uint32_t stB_l = stB_h + B_TILE;
        for (int i = tid; i < MT * 8; i += 256) {
            const int r = i >> 3, seg = i & 7;
            const uint32_t off = (uint32_t)(r * (STRIDE * 2) + seg * 16);
            const size_t gs = (size_t)(m0 + r) * lda + k0 + seg * 8;
            cp16(stA_h + off, Ah + gs);
            cp16(stA_l + off, Al + gs);
        }
        for (int i = tid; i < NT * 8; i += 256) {
            const int r = i >> 3, seg = i & 7;
            const uint32_t off = (uint32_t)(r * (STRIDE * 2) + seg * 16);
            const size_t gs = (size_t)(n0 + r) * lda + k0 + seg * 8;
            cp16(stB_h + off, Bh + gs);
            cp16(stB_l + off, Bl + gs);
        }
        asm volatile("cp.async.commit_group;" ::: "memory");
    };

    const int nk = KSLICE / KC;
    load_stage(0, koff);
    load_stage(1, koff + KC);

    const int a_row = warp_m0 + (lane & 15);
    const int a_col = (lane >> 4) << 3;
    const int b_row = warp_n0 + (lane & 7) + ((lane >> 4) << 3);
    const int b_col = ((lane >> 3) & 1) << 3;

    for (int i = 0; i < nk; i++) {
        if (i + 1 < nk) asm volatile("cp.async.wait_group 1;" ::: "memory");
        else            asm volatile("cp.async.wait_group 0;" ::: "memory");
        __syncthreads();

        const uint32_t stA_h = base + (i & 1) * STAGE;
        const uint32_t stA_l = stA_h + A_TILE;
        const uint32_t stB_h = stA_h + 2 * A_TILE;
        const uint32_t stB_l = stB_h + B_TILE;

#pragma unroll
        for (int ks = 0; ks < 4; ks++) {
            const int k0 = ks * 16;
            uint32_t ah[4][4], al[4][4], bh[4][4], bl[4][4];
#pragma unroll
            for (int mf = 0; mf < 4; mf++) {
                const uint32_t ao = (uint32_t)((a_row + mf * 16) * STRIDE + k0 + a_col) * 2;
                ldm4(ah[mf], stA_h + ao);
                ldm4(al[mf], stA_l + ao);
            }
#pragma unroll
            for (int bp = 0; bp < 4; bp++) {
                const uint32_t bo = (uint32_t)((b_row + bp * 16) * STRIDE + k0 + b_col) * 2;
                ldm4(bh[bp], stB_h + bo);
                ldm4(bl[bp], stB_l + bo);
            }
#pragma unroll
            for (int mf = 0; mf < 4; mf++)
#pragma unroll
                for (int bp = 0; bp < 4; bp++) {
                    mma_bf16(acc[mf][2 * bp + 0], ah[mf], &bh[bp][0]);
                    mma_bf16(acc[mf][2 * bp + 1], ah[mf], &bh[bp][2]);
                    mma_bf16(acc[mf][2 * bp + 0], ah[mf], &bl[bp][0]);
                    mma_bf16(acc[mf][2 * bp + 1], ah[mf], &bl[bp][2]);
                    mma_bf16(acc[mf][2 * bp + 0], al[mf], &bh[bp][0]);
                    mma_bf16(acc[mf][2 * bp + 1], al[mf], &bh[bp][2]);
                }
        }
        __syncthreads();
    }

    const int r_base = m0 + warp_m0 + (lane >> 2);
    const int c_base = n0 + warp_n0 + ((lane & 3) << 1);
#pragma unroll
    for (int mf = 0; mf < 4; mf++)
#pragma unroll
        for (int nf = 0; nf < 8; nf++) {
            const int cc = c_base + nf * 8;
            const int row0 = r_base + mf * 16;
            *reinterpret_cast<float2*>(&Cp[(size_t)row0 * DIM + cc]) =
                make_float2(acc[mf][nf][0], acc[mf][nf][1]);
            *reinterpret_cast<float2*>(&Cp[(size_t)(row0 + 8) * DIM + cc]) =
                make_float2(acc[mf][nf][2], acc[mf][nf][3]);
        }
}

// ---------------- reduce 8 fp32 partials -> fp16 (grid-stride) ----------------
__global__ void reduce8_half(const float* __restrict__ p, __half* __restrict__ o, int n4)
{
    const int stride = gridDim.x * blockDim.x;
    for (int i = blockIdx.x * blockDim.x + threadIdx.x; i < n4; i += stride) {
        float4 s = reinterpret_cast<const float4*>(p)[i];
#pragma unroll
        for (int j = 1; j < 8; j++) {
            float4 v = reinterpret_cast<const float4*>(p + (size_t)j * n4 * 4)[i];
            s.x += v.x; s.y += v.y; s.z += v.z; s.w += v.w;
        }
        reinterpret_cast<__half2*>(o + (size_t)i * 4)[0] = __floats2half2_rn(s.x, s.y);
        reinterpret_cast<__half2*>(o + (size_t)i * 4)[1] = __floats2half2_rn(s.z, s.w);
    }
}

// ============================================================================
// fused prep kernel (coverage verified R13)
// ============================================================================
#define NCVT   4096
#define NSPL   256
#define NTSP   1024
#define NBIA   1024
#define NWPJ   512
#define PREP_GRID_1 (NCVT + NSPL + NTSP + NBIA)
#define PREP_GRID_2 (NCVT + NSPL + NTSP + NBIA + NWPJ)

__global__ __launch_bounds__(256)
void prep(const float* __restrict__ x, __half* __restrict__ xh,
          const float* __restrict__ wo,
          __nv_bfloat16* __restrict__ wo_h, __nv_bfloat16* __restrict__ wo_l,
          const float* __restrict__ wv,
          __nv_bfloat16* __restrict__ wvt_h, __nv_bfloat16* __restrict__ wvt_l,
          const float* __restrict__ bv, const float* __restrict__ bo,
          float* __restrict__ c,
          const float* __restrict__ wp, __half* __restrict__ wph)
{
    const int bx = blockIdx.x;
    const int tid = threadIdx.x;

    if (bx < NCVT) {
        const int base = bx * 4096 + tid * 4;
#pragma unroll
        for (int k = 0; k < 4; k++) {
            const int idx = base + k * 1024;
            float4 v = *reinterpret_cast<const float4*>(x + idx);
            reinterpret_cast<__half2*>(xh + idx)[0] = __floats2half2_rn(v.x, v.y);
            reinterpret_cast<__half2*>(xh + idx)[1] = __floats2half2_rn(v.z, v.w);
        }
        return;
    }
    if (bx < NCVT + NSPL) {
        const int base = (bx - NCVT) * 4096 + tid * 4;
#pragma unroll
        for (int k = 0; k < 4; k++) {
            const int idx = base + k * 1024;
            float4 v = *reinterpret_cast<const float4*>(wo + idx);
            __nv_bfloat162 h0, h1, l0, l1;
            h0.x = __float2bfloat16_rn(v.x); h0.y = __float2bfloat16_rn(v.y);
            h1.x = __float2bfloat16_rn(v.z); h1.y = __float2bfloat16_rn(v.w);
            l0.x = __float2bfloat16_rn(v.x - __bfloat162float(h0.x));
            l0.y = __float2bfloat16_rn(v.y - __bfloat162float(h0.y));
            l1.x = __float2bfloat16_rn(v.z - __bfloat162float(h1.x));
            l1.y = __float2bfloat16_rn(v.w - __bfloat162float(h1.y));
            reinterpret_cast<__nv_bfloat162*>(wo_h + idx)[0] = h0;
            reinterpret_cast<__nv_bfloat162*>(wo_h + idx)[1] = h1;
            reinterpret_cast<__nv_bfloat162*>(wo_l + idx)[0] = l0;
            reinterpret_cast<__nv_bfloat162*>(wo_l + idx)[1] = l1;
        }
        return;
    }
    if (bx < NCVT + NSPL + NTSP) {
        __shared__ float t[32][33];
        const int bi = bx - NCVT - NSPL;
        const int r0 = (bi >> 5) * 32, c0 = (bi & 31) * 32;
        const int tx = tid & 31, ty = tid >> 5;
#pragma unroll
        for (int i = 0; i < 4; i++)
            t[ty + 8 * i][tx] = wv[(size_t)(r0 + ty + 8 * i) * DIM + c0 + tx];
        __syncthreads();
#pragma unroll
        for (int i = 0; i < 4; i++) {
            const int rr = ty + 8 * i;
            const float v = t[tx][rr];
            const size_t o = (size_t)(c0 + rr) * DIM + r0 + tx;
            __nv_bfloat16 hh = __float2bfloat16_rn(v);
            wvt_h[o] = hh;
            wvt_l[o] = __float2bfloat16_rn(v - __bfloat162float(hh));
        }
        return;
    }
    if (bx < NCVT + NSPL + NTSP + NBIA) {
        __shared__ float red[8];
        const int n = bx - NCVT - NSPL - NTSP;
        float s = 0.0f;
        for (int j = tid; j < DIM; j += 256) s += wo[(size_t)n * DIM + j] * bv[j];
#pragma unroll
        for (int o = 16; o > 0; o >>= 1) s += __shfl_xor_sync(0xFFFFFFFFu, s, o);
        if ((tid & 31) == 0) red[tid >> 5] = s;
        __syncthreads();
        if (tid == 0) {
            float t2 = bo[n];
#pragma unroll
            for (int w = 0; w < 8; w++) t2 += red[w];
            c[n] = t2;
        }
        return;
    }
    {
        const int base = (bx - NCVT - NSPL - NTSP - NBIA) * 4096 + tid * 4;
#pragma unroll
        for (int k = 0; k < 4; k++) {
            const int idx = base + k * 1024;
            float4 v = *reinterpret_cast<const float4*>(wp + idx);
            reinterpret_cast<__half2*>(wph + idx)[0] = __floats2half2_rn(v.x, v.y);
            reinterpret_cast<__half2*>(wph + idx)[1] = __floats2half2_rn(v.z, v.w);
        }
    }
}

// ---------------- LayerNorm(2048)+bias, fp16 in -> fp16 out ----------------
__global__ __launch_bounds__(256)
void ln_half(const __half* __restrict__ z,
             const float* __restrict__ c1, const float* __restrict__ c2,
             const float* __restrict__ g, const float* __restrict__ b,
             __half* __restrict__ zn)
{
    __shared__ float redS[8], redQ[8];
    const size_t base = (size_t)blockIdx.x * DIM2;
    const int tid = threadIdx.x;
    const int col = tid * 8;

    uint4 zr = *reinterpret_cast<const uint4*>(z + base + col);
    float f[8];
    {
        float2 t0 = __half22float2(*reinterpret_cast<__half2*>(&zr.x));
        float2 t1 = __half22float2(*reinterpret_cast<__half2*>(&zr.y));
        float2 t2 = __half22float2(*reinterpret_cast<__half2*>(&zr.z));
        float2 t3 = __half22float2(*reinterpret_cast<__half2*>(&zr.w));
        f[0] = t0.x; f[1] = t0.y; f[2] = t1.x; f[3] = t1.y;
        f[4] = t2.x; f[5] = t2.y; f[6] = t3.x; f[7] = t3.y;
    }
    const float* cb = (col < DIM) ? (c1 + col) : (c2 + col - DIM);
    float4 cb0 = *reinterpret_cast<const float4*>(cb);
    float4 cb1 = *reinterpret_cast<const float4*>(cb + 4);
    f[0] += cb0.x; f[1] += cb0.y; f[2] += cb0.z; f[3] += cb0.w;
    f[4] += cb1.x; f[5] += cb1.y; f[6] += cb1.z; f[7] += cb1.w;

    float s = 0.0f, q = 0.0f;
#pragma unroll
    for (int i = 0; i < 8; i++) { s += f[i]; q += f[i] * f[i]; }
#pragma unroll
    for (int o = 16; o > 0; o >>= 1) {
        s += __shfl_xor_sync(0xFFFFFFFFu, s, o);
        q += __shfl_xor_sync(0xFFFFFFFFu, q, o);
    }
    if ((tid & 31) == 0) { redS[tid >> 5] = s; redQ[tid >> 5] = q; }
    __syncthreads();
    float S = 0.0f, Q = 0.0f;
#pragma unroll
    for (int w = 0; w < 8; w++) { S += redS[w]; Q += redQ[w]; }

    const float mu = S * (1.0f / DIM2);
    const float var = Q * (1.0f / DIM2) - mu * mu;
    const float rstd = rsqrtf(var + 1e-5f);

    float4 g0 = *reinterpret_cast<const float4*>(g + col);
    float4 g1 = *reinterpret_cast<const float4*>(g + col + 4);
    float4 b0 = *reinterpret_cast<const float4*>(b + col);
    float4 b1 = *reinterpret_cast<const float4*>(b + col + 4);

    f[0] = (f[0] - mu) * rstd * g0.x + b0.x;
    f[1] = (f[1] - mu) * rstd * g0.y + b0.y;
    f[2] = (f[2] - mu) * rstd * g0.z + b0.z;
    f[3] = (f[3] - mu) * rstd * g0.w + b0.w;
    f[4] = (f[4] - mu) * rstd * g1.x + b1.x;
    f[5] = (f[5] - mu) * rstd * g1.y + b1.y;
    f[6] = (f[6] - mu) * rstd * g1.z + b1.z;
    f[7] = (f[7] - mu) * rstd * g1.w + b1.w;

    uint4 outv;
    *reinterpret_cast<__half2*>(&outv.x) = __floats2half2_rn(f[0], f[1]);
    *reinterpret_cast<__half2*>(&outv.y) = __floats2half2_rn(f[2], f[3]);
    *reinterpret_cast<__half2*>(&outv.z) = __floats2half2_rn(f[4], f[5]);
    *reinterpret_cast<__half2*>(&outv.w) = __floats2half2_rn(f[6], f[7]);
    *reinterpret_cast<uint4*>(zn + base + col) = outv;
}

// ---------------- launch ----------------
extern "C" void kernel_launch(void* const* d_in, const int* in_sizes, int n_in,
                              void* d_out, int out_size)
{
    const float* x_u    = (const float*)d_in[0];
    const float* x_m    = (const float*)d_in[1];
    const float* w_qkv1 = (const float*)d_in[2];
    const float* b_qkv1 = (const float*)d_in[3];
    const float* w_o1   = (const float*)d_in[4];
    const float* b_o1   = (const float*)d_in[5];
    const float* w_qkv2 = (const float*)d_in[6];
    const float* b_qkv2 = (const float*)d_in[7];
    const float* w_o2   = (const float*)d_in[8];
    const float* b_o2   = (const float*)d_in[9];
    const float* ln_g   = (const float*)d_in[10];
    const float* ln_b   = (const float*)d_in[11];
    const float* w_proj = (const float*)d_in[12];
    const float* b_proj = (const float*)d_in[13];
    float* out = (float*)d_out;

    const float* wv1 = w_qkv1 + (size_t)2 * DIM * DIM;
    const float* bv1 = b_qkv1 + 2 * DIM;
    const float* wv2 = w_qkv2 + (size_t)2 * DIM * DIM;
    const float* bv2 = b_qkv2 + 2 * DIM;

    __half *xuh, *xmh, *zh, *znh, *B1h, *B2h, *wph;
    float *part, *c1, *c2;
    __nv_bfloat16 *wo_h, *wo_l, *wvt_h, *wvt_l;

    cudaGetSymbolAddress((void**)&xuh, g_xuh);
    cudaGetSymbolAddress((void**)&xmh, g_xmh);
    cudaGetSymbolAddress((void**)&zh, g_zh);
    cudaGetSymbolAddress((void**)&znh, g_znh);
    cudaGetSymbolAddress((void**)&B1h, g_B1h);
    cudaGetSymbolAddress((void**)&B2h, g_B2h);
    cudaGetSymbolAddress((void**)&wph, g_wph);
    cudaGetSymbolAddress((void**)&part, g_part);
    cudaGetSymbolAddress((void**)&c1, g_c1);
    cudaGetSymbolAddress((void**)&c2, g_c2);
    cudaGetSymbolAddress((void**)&wo_h, g_wo_hi);   cudaGetSymbolAddress((void**)&wo_l, g_wo_lo);
    cudaGetSymbolAddress((void**)&wvt_h, g_wvt_hi); cudaGetSymbolAddress((void**)&wvt_l, g_wvt_lo);

    cudaFuncSetAttribute(mma_gemm_sk, cudaFuncAttributeMaxDynamicSharedMemorySize, SMEM_TOT);
    cudaFuncSetAttribute(hgemm<false, __half>, cudaFuncAttributeMaxDynamicSharedMemorySize, HSMEM);
    cudaFuncSetAttribute(hgemm<true, float>,   cudaFuncAttributeMaxDynamicSharedMemorySize, HSMEM);

    const dim3 gridZ(DIM / 128, BATCH / 256);       // (8, 64)
    const dim3 gridWsk(DIM / NT, DIM / MT, 8);      // (8, 4, 8) split-K

    // ---- path 1: prep(1), combine(2), reduce(3), z1-hgemm(4 <- ncu profiles #4) ----
    prep<<<PREP_GRID_1, 256>>>(x_u, xuh, w_o1, wo_h, wo_l, wv1, wvt_h, wvt_l,
                               bv1, b_o1, c1, nullptr, nullptr);
    mma_gemm_sk<<<gridWsk, 256, SMEM_TOT>>>(wo_h, wo_l, wvt_h, wvt_l, part, DIM);
    reduce8_half<<<512, 256>>>(part, B1h, DIM * DIM / 4);
    hgemm<false, __half><<<gridZ, 512, HSMEM>>>(xuh, B1h, zh, DIM2, nullptr, DIM);

    // ---- path 2 ----
    prep<<<PREP_GRID_2, 256>>>(x_m, xmh, w_o2, wo_h, wo_l, wv2, wvt_h, wvt_l,
                               bv2, b_o2, c2, w_proj, wph);
    mma_gemm_sk<<<gridWsk, 256, SMEM_TOT>>>(wo_h, wo_l, wvt_h, wvt_l, part, DIM);
    reduce8_half<<<512, 256>>>(part, B2h, DIM * DIM / 4);
    hgemm<false, __half><<<gridZ, 512, HSMEM>>>(xmh, B2h, zh + DIM, DIM2, nullptr, DIM);

    // ---- LayerNorm(+bias) fp16 -> fp16 ----
    ln_half<<<BATCH, 256>>>(zh, c1, c2, ln_g, ln_b, znh);

    // ---- proj: out = GELU(zn @ w_proj^T + b_proj) ----
    hgemm<true, float><<<gridZ, 512, HSMEM>>>(znh, wph, out, DIM, b_proj, DIM2);
}

// round 15
// speedup vs baseline: 9.1862x; 1.0895x over previous
#include <cuda_runtime.h>
#include <cuda_bf16.h>
#include <cuda_fp16.h>
#include <math.h>
#include <stdint.h>

#define BATCH 16384
#define DIM   1024
#define DIM2  2048

// ---------------- scratch (device globals; no allocs) ----------------
__device__ __half  g_xuh[(size_t)BATCH*DIM];
__device__ __half  g_xmh[(size_t)BATCH*DIM];
__device__ __half  g_zh[(size_t)BATCH*DIM2];
__device__ __half  g_B1h[DIM*DIM], g_B2h[DIM*DIM];
__device__ __half  g_wpg[DIM*DIM2];              // g[k] * w_proj[n,k] in fp16
__device__ float   g_part[16*DIM*DIM];           // split-K partials, 2 paths x 8 slices
__device__ float   g_c1[DIM], g_c2[DIM];
__device__ float   g_t1[DIM], g_t2[DIM], g_t3[DIM];
__device__ float2  g_rowP[BATCH];                // (rstd, mu*rstd) per row
__device__ __nv_bfloat16 g_wo1_hi[DIM*DIM], g_wo1_lo[DIM*DIM];
__device__ __nv_bfloat16 g_wvt1_hi[DIM*DIM], g_wvt1_lo[DIM*DIM];
__device__ __nv_bfloat16 g_wo2_hi[DIM*DIM], g_wo2_lo[DIM*DIM];
__device__ __nv_bfloat16 g_wvt2_hi[DIM*DIM], g_wvt2_lo[DIM*DIM];

// ---------------- low-level helpers (sm_80-baseline PTX only) ----------------
__device__ __forceinline__ uint32_t s2u(const void* p) {
    uint32_t a;
    asm("{ .reg .u64 t; cvta.to.shared.u64 t, %1; cvt.u32.u64 %0, t; }" : "=r"(a) : "l"(p));
    return a;
}
__device__ __forceinline__ void cp16(uint32_t d, const void* s) {
    asm volatile("cp.async.cg.shared.global [%0], [%1], 16;" :: "r"(d), "l"(s));
}
__device__ __forceinline__ void ldm4(uint32_t* r, uint32_t addr) {
    asm volatile("ldmatrix.sync.aligned.m8n8.x4.shared.b16 {%0,%1,%2,%3}, [%4];"
                 : "=r"(r[0]), "=r"(r[1]), "=r"(r[2]), "=r"(r[3]) : "r"(addr));
}
__device__ __forceinline__ void mma_bf16(float* d, const uint32_t* a, const uint32_t* b) {
    asm volatile(
        "mma.sync.aligned.m16n8k16.row.col.f32.bf16.bf16.f32 "
        "{%0,%1,%2,%3}, {%4,%5,%6,%7}, {%8,%9}, {%0,%1,%2,%3};"
        : "+f"(d[0]), "+f"(d[1]), "+f"(d[2]), "+f"(d[3])
        : "r"(a[0]), "r"(a[1]), "r"(a[2]), "r"(a[3]), "r"(b[0]), "r"(b[1]));
}
__device__ __forceinline__ void mma_f16(float* d, const uint32_t* a, uint32_t b0, uint32_t b1) {
    asm volatile(
        "mma.sync.aligned.m16n8k16.row.col.f32.f16.f16.f32 "
        "{%0,%1,%2,%3}, {%4,%5,%6,%7}, {%8,%9}, {%0,%1,%2,%3};"
        : "+f"(d[0]), "+f"(d[1]), "+f"(d[2]), "+f"(d[3])
        : "r"(a[0]), "r"(a[1]), "r"(a[2]), "r"(a[3]), "r"(b0), "r"(b1));
}

// ============================================================================
// fp16 GEMM core config (CTA 256x128x64, 512 threads, warp tile 64x32, 3-stage)
// ============================================================================
#define HSTR 72
#define HA_TILE (256*HSTR*2)
#define HB_TILE (128*HSTR*2)
#define HSTAGE  (HA_TILE + HB_TILE)
#define HSMEM   (3*HSTAGE)

// common mainloop macro-free body implemented per-kernel (two kernels below)

// ---- merged z-GEMM: path = blockIdx.y >> 6 ----
__global__ __launch_bounds__(512, 1)
void zgemm2(const __half* __restrict__ Axu, const __half* __restrict__ Axm,
            const __half* __restrict__ B1, const __half* __restrict__ B2,
            __half* __restrict__ Z)
{
    extern __shared__ char smem[];
    const uint32_t base = s2u(smem);
    const int tid  = threadIdx.x;
    const int wid  = tid >> 5;
    const int lane = tid & 31;
    const int path = blockIdx.y >> 6;
    const int m0 = (blockIdx.y & 63) * 256;
    const int n0 = blockIdx.x * 128;
    const __half* A = path ? Axm : Axu;
    const __half* B = path ? B2  : B1;
    __half* C = Z + path * DIM;
    const int K = DIM, ldc = DIM2;
    const int warp_m0 = (wid & 3) * 64;
    const int warp_n0 = (wid >> 2) * 32;

    float acc[4][4][4];
#pragma unroll
    for (int i = 0; i < 4; i++)
#pragma unroll
        for (int j = 0; j < 4; j++)
#pragma unroll
            for (int q = 0; q < 4; q++) acc[i][j][q] = 0.0f;

    auto load_stage = [&](int s, int k0) {
        const uint32_t stA = base + s * HSTAGE;
        const uint32_t stB = stA + HA_TILE;
        for (int i = tid; i < 256 * 8; i += 512) {
            const int r = i >> 3, seg = i & 7;
            cp16(stA + (uint32_t)(r * (HSTR * 2) + seg * 16),
                 A + (size_t)(m0 + r) * K + k0 + seg * 8);
        }
        for (int i = tid; i < 128 * 8; i += 512) {
            const int r = i >> 3, seg = i & 7;
            cp16(stB + (uint32_t)(r * (HSTR * 2) + seg * 16),
                 B + (size_t)(n0 + r) * K + k0 + seg * 8);
        }
        asm volatile("cp.async.commit_group;" ::: "memory");
    };

    const int nk = K >> 6;
    load_stage(0, 0);
    load_stage(1, 64);

    const int a_row = warp_m0 + (lane & 15);
    const int a_col = (lane >> 4) << 3;
    const int b_row = warp_n0 + (lane & 7) + ((lane >> 4) << 3);
    const int b_col = ((lane >> 3) & 1) << 3;

    for (int i = 0; i < nk; i++) {
        if (i + 2 <= nk) asm volatile("cp.async.wait_group 1;" ::: "memory");
        else             asm volatile("cp.async.wait_group 0;" ::: "memory");
        __syncthreads();
        if (i + 2 < nk) load_stage((i + 2) % 3, (i + 2) * 64);

        const uint32_t stA = base + (i % 3) * HSTAGE;
        const uint32_t stB = stA + HA_TILE;
#pragma unroll
        for (int ks = 0; ks < 4; ks++) {
            const int k0 = ks * 16;
            uint32_t af[4][4], bf[2][4];
#pragma unroll
            for (int mf = 0; mf < 4; mf++)
                ldm4(af[mf], stA + (uint32_t)((a_row + mf * 16) * HSTR + k0 + a_col) * 2);
#pragma unroll
            for (int bp = 0; bp < 2; bp++)
                ldm4(bf[bp], stB + (uint32_t)((b_row + bp * 16) * HSTR + k0 + b_col) * 2);
#pragma unroll
            for (int mf = 0; mf < 4; mf++)
#pragma unroll
                for (int bp = 0; bp < 2; bp++) {
                    mma_f16(acc[mf][2 * bp + 0], af[mf], bf[bp][0], bf[bp][1]);
                    mma_f16(acc[mf][2 * bp + 1], af[mf], bf[bp][2], bf[bp][3]);
                }
        }
    }

    const int r_base = m0 + warp_m0 + (lane >> 2);
    const int c_base = n0 + warp_n0 + ((lane & 3) << 1);
#pragma unroll
    for (int mf = 0; mf < 4; mf++) {
        const int row0 = r_base + mf * 16;
#pragma unroll
        for (int nf = 0; nf < 4; nf++) {
            const int cc = c_base + nf * 8;
            *reinterpret_cast<__half2*>(C + (size_t)row0 * ldc + cc) =
                __floats2half2_rn(acc[mf][nf][0], acc[mf][nf][1]);
            *reinterpret_cast<__half2*>(C + (size_t)(row0 + 8) * ldc + cc) =
                __floats2half2_rn(acc[mf][nf][2], acc[mf][nf][3]);
        }
    }
}

// ---- proj GEMM with folded LayerNorm epilogue + exact GELU ----
// out[m,n] = GELU( a1[m]*(acc[m,n] + t3[n]) + t1[n] - a2[m]*t2[n] )
__global__ __launch_bounds__(512, 1)
void proj_ln(const __half* __restrict__ A, const __half* __restrict__ B,
             float* __restrict__ C,
             const float* __restrict__ t1, const float* __restrict__ t2,
             const float* __restrict__ t3, const float2* __restrict__ rowP)
{
    extern __shared__ char smem[];
    const uint32_t base = s2u(smem);
    const int tid  = threadIdx.x;
    const int wid  = tid >> 5;
    const int lane = tid & 31;
    const int m0 = blockIdx.y * 256;
    const int n0 = blockIdx.x * 128;
    const int K = DIM2, ldc = DIM;
    const int warp_m0 = (wid & 3) * 64;
    const int warp_n0 = (wid >> 2) * 32;

    float acc[4][4][4];
#pragma unroll
    for (int i = 0; i < 4; i++)
#pragma unroll
        for (int j = 0; j < 4; j++)
#pragma unroll
            for (int q = 0; q < 4; q++) acc[i][j][q] = 0.0f;

    auto load_stage = [&](int s, int k0) {
        const uint32_t stA = base + s * HSTAGE;
        const uint32_t stB = stA + HA_TILE;
        for (int i = tid; i < 256 * 8; i += 512) {
            const int r = i >> 3, seg = i & 7;
            cp16(stA + (uint32_t)(r * (HSTR * 2) + seg * 16),
                 A + (size_t)(m0 + r) * K + k0 + seg * 8);
        }
        for (int i = tid; i < 128 * 8; i += 512) {
            const int r = i >> 3, seg = i & 7;
            cp16(stB + (uint32_t)(r * (HSTR * 2) + seg * 16),
                 B + (size_t)(n0 + r) * K + k0 + seg * 8);
        }
        asm volatile("cp.async.commit_group;" ::: "memory");
    };

    const int nk = K >> 6;
    load_stage(0, 0);
    load_stage(1, 64);

    const int a_row = warp_m0 + (lane & 15);
    const int a_col = (lane >> 4) << 3;
    const int b_row = warp_n0 + (lane & 7) + ((lane >> 4) << 3);
    const int b_col = ((lane >> 3) & 1) << 3;

    for (int i = 0; i < nk; i++) {
        if (i + 2 <= nk) asm volatile("cp.async.wait_group 1;" ::: "memory");
        else             asm volatile("cp.async.wait_group 0;" ::: "memory");
        __syncthreads();
        if (i + 2 < nk) load_stage((i + 2) % 3, (i + 2) * 64);

        const uint32_t stA = base + (i % 3) * HSTAGE;
        const uint32_t stB = stA + HA_TILE;
#pragma unroll
        for (int ks = 0; ks < 4; ks++) {
            const int k0 = ks * 16;
            uint32_t af[4][4], bf[2][4];
#pragma unroll
            for (int mf = 0; mf < 4; mf++)
                ldm4(af[mf], stA + (uint32_t)((a_row + mf * 16) * HSTR + k0 + a_col) * 2);
#pragma unroll
            for (int bp = 0; bp < 2; bp++)
                ldm4(bf[bp], stB + (uint32_t)((b_row + bp * 16) * HSTR + k0 + b_col) * 2);
#pragma unroll
            for (int mf = 0; mf < 4; mf++)
#pragma unroll
                for (int bp = 0; bp < 2; bp++) {
                    mma_f16(acc[mf][2 * bp + 0], af[mf], bf[bp][0], bf[bp][1]);
                    mma_f16(acc[mf][2 * bp + 1], af[mf], bf[bp][2], bf[bp][3]);
                }
        }
    }

    const int r_base = m0 + warp_m0 + (lane >> 2);
    const int c_base = n0 + warp_n0 + ((lane & 3) << 1);
#pragma unroll
    for (int mf = 0; mf < 4; mf++) {
        const int row0 = r_base + mf * 16;
        const float2 p0 = rowP[row0];
        const float2 p1 = rowP[row0 + 8];
#pragma unroll
        for (int nf = 0; nf < 4; nf++) {
            const int cc = c_base + nf * 8;
            const float t1a = t1[cc],     t1b = t1[cc + 1];
            const float t2a = t2[cc],     t2b = t2[cc + 1];
            const float t3a = t3[cc],     t3b = t3[cc + 1];
            float v0 = p0.x * (acc[mf][nf][0] + t3a) + t1a - p0.y * t2a;
            float v1 = p0.x * (acc[mf][nf][1] + t3b) + t1b - p0.y * t2b;
            float v2 = p1.x * (acc[mf][nf][2] + t3a) + t1a - p1.y * t2a;
            float v3 = p1.x * (acc[mf][nf][3] + t3b) + t1b - p1.y * t2b;
            v0 = 0.5f * v0 * (1.0f + erff(v0 * 0.70710678118654752f));
            v1 = 0.5f * v1 * (1.0f + erff(v1 * 0.70710678118654752f));
            v2 = 0.5f * v2 * (1.0f + erff(v2 * 0.70710678118654752f));
            v3 = 0.5f * v3 * (1.0f + erff(v3 * 0.70710678118654752f));
            *reinterpret_cast<float2*>(C + (size_t)row0 * ldc + cc)       = make_float2(v0, v1);
            *reinterpret_cast<float2*>(C + (size_t)(row0 + 8) * ldc + cc) = make_float2(v2, v3);
        }
    }
}

// ============================================================================
// bf16x3 split-K GEMM, both weight combines in one launch.
// blockIdx.z: 0..15 = path*8 + kslice.
// ============================================================================
#define MT 256
#define NT 128
#define KC 64
#define KSLICE 128
#define STRIDE 72
#define A_TILE (MT*STRIDE*2)
#define B_TILE (NT*STRIDE*2)
#define STAGE  (2*A_TILE + 2*B_TILE)
#define SMEM_TOT (2*STAGE)

__global__ __launch_bounds__(256, 1)
void mma_gemm_sk2(const __nv_bfloat16* __restrict__ A1h, const __nv_bfloat16* __restrict__ A1l,
                  const __nv_bfloat16* __restrict__ B1hh, const __nv_bfloat16* __restrict__ B1ll,
                  const __nv_bfloat16* __restrict__ A2h, const __nv_bfloat16* __restrict__ A2l,
                  const __nv_bfloat16* __restrict__ B2hh, const __nv_bfloat16* __restrict__ B2ll,
                  float* __restrict__ Cpart)
{
    extern __shared__ char smem[];
    const uint32_t base = s2u(smem);
    const int tid  = threadIdx.x;
    const int wid  = tid >> 5;
    const int lane = tid & 31;
    const int m0 = blockIdx.y * MT;
    const int n0 = blockIdx.x * NT;
    const int path = blockIdx.z >> 3;
    const int koff = (blockIdx.z & 7) * KSLICE;
    const __nv_bfloat16* Ah = path ? A2h : A1h;
    const __nv_bfloat16* Al = path ? A2l : A1l;
    const __nv_bfloat16* Bh = path ? B2hh : B1hh;
    const __nv_bfloat16* Bl = path ? B2ll : B1ll;
    float* Cp = Cpart + (size_t)blockIdx.z * DIM * DIM;
    const int lda = DIM;
    const int warp_m0 = (wid & 3) * 64;
    const int warp_n0 = (wid >> 2) * 64;

    float acc[4][8][4];
#pragma unroll
    for (int i = 0; i < 4; i++)
#pragma unroll
        for (int j = 0; j < 8; j++)
#pragma unroll
            for (int q = 0; q < 4; q++) acc[i][j][q] = 0.0f;

    auto load_stage = [&](int s, int k0) {
        const uint32_t stA_h = base + s * STAGE;
        const uint32_t stA_l = stA_h + A_TILE;
        const uint32_t stB_h = stA_h + 2 * A_TILE;
        const uint32_t stB_l = stB_h + B_TILE;
        for (int i = tid; i < MT * 8; i += 256) {
            const int r = i >> 3, seg = i & 7;
            const uint32_t off = (uint32_t)(r * (STRIDE * 2) + seg * 16);
            const size_t gs = (size_t)(m0 + r) * lda + k0 + seg * 8;
            cp16(stA_h + off, Ah + gs);
            cp16(stA_l + off, Al + gs);
        }
        for (int i = tid; i < NT * 8; i += 256) {
            const int r = i >> 3, seg = i & 7;
            const uint32_t off = (uint32_t)(r * (STRIDE * 2) + seg * 16);
            const size_t gs = (size_t)(n0 + r) * lda + k0 + seg * 8;
            cp16(stB_h + off, Bh + gs);
            cp16(stB_l + off, Bl + gs);
        }
        asm volatile("cp.async.commit_group;" ::: "memory");
    };

    const int nk = KSLICE / KC;
    load_stage(0, koff);
    load_stage(1, koff + KC);

    const int a_row = warp_m0 + (lane & 15);
    const int a_col = (lane >> 4) << 3;
    const int b_row = warp_n0 + (lane & 7) + ((lane >> 4) << 3);
    const int b_col = ((lane >> 3) & 1) << 3;

    for (int i = 0; i < nk; i++) {
        if (i + 1 < nk) asm volatile("cp.async.wait_group 1;" ::: "memory");
        else            asm volatile("cp.async.wait_group 0;" ::: "memory");
        __syncthreads();

        const uint32_t stA_h = base + (i & 1) * STAGE;
        const uint32_t stA_l = stA_h + A_TILE;
        const uint32_t stB_h = stA_h + 2 * A_TILE;
        const uint32_t stB_l = stB_h + B_TILE;

#pragma unroll
        for (int ks = 0; ks < 4; ks++) {
            const int k0 = ks * 16;
            uint32_t ah[4][4], al[4][4], bh[4][4], bl[4][4];
#pragma unroll
            for (int mf = 0; mf < 4; mf++) {
                const uint32_t ao = (uint32_t)((a_row + mf * 16) * STRIDE + k0 + a_col) * 2;
                ldm4(ah[mf], stA_h + ao);
                ldm4(al[mf], stA_l + ao);
            }
#pragma unroll
            for (int bp = 0; bp < 4; bp++) {
                const uint32_t bo = (uint32_t)((b_row + bp * 16) * STRIDE + k0 + b_col) * 2;
                ldm4(bh[bp], stB_h + bo);
                ldm4(bl[bp], stB_l + bo);
            }
#pragma unroll
            for (int mf = 0; mf < 4; mf++)
#pragma unroll
                for (int bp = 0; bp < 4; bp++) {
                    mma_bf16(acc[mf][2 * bp + 0], ah[mf], &bh[bp][0]);
                    mma_bf16(acc[mf][2 * bp + 1], ah[mf], &bh[bp][2]);
                    mma_bf16(acc[mf][2 * bp + 0], ah[mf], &bl[bp][0]);
                    mma_bf16(acc[mf][2 * bp + 1], ah[mf], &bl[bp][2]);
                    mma_bf16(acc[mf][2 * bp + 0], al[mf], &bh[bp][0]);
                    mma_bf16(acc[mf][2 * bp + 1], al[mf], &bh[bp][2]);
                }
        }
        __syncthreads();
    }

    const int r_base = m0 + warp_m0 + (lane >> 2);
    const int c_base = n0 + warp_n0 + ((lane & 3) << 1);
#pragma unroll
    for (int mf = 0; mf < 4; mf++)
#pragma unroll
        for (int nf = 0; nf < 8; nf++) {
            const int cc = c_base + nf * 8;
            const int row0 = r_base + mf * 16;
            *reinterpret_cast<float2*>(&Cp[(size_t)row0 * DIM + cc]) =
                make_float2(acc[mf][nf][0], acc[mf][nf][1]);
            *reinterpret_cast<float2*>(&Cp[(size_t)(row0 + 8) * DIM + cc]) =
                make_float2(acc[mf][nf][2], acc[mf][nf][3]);
        }
}

// ---------------- reduce both paths' 8 partials -> fp16 B1h/B2h ----------------
__global__ void reduce8_half2(const float* __restrict__ p,
                              __half* __restrict__ o1, __half* __restrict__ o2)
{
    const int n4half = DIM * DIM / 4;   // 262144
    const int total = 2 * n4half;
    const int stride = gridDim.x * blockDim.x;
    for (int i = blockIdx.x * blockDim.x + threadIdx.x; i < total; i += stride) {
        const int path = i / n4half;
        const int ii = i - path * n4half;
        const float* pb = p + (size_t)path * 8 * DIM * DIM;
        float4 s = reinterpret_cast<const float4*>(pb)[ii];
#pragma unroll
        for (int j = 1; j < 8; j++) {
            float4 v = reinterpret_cast<const float4*>(pb + (size_t)j * DIM * DIM)[ii];
            s.x += v.x; s.y += v.y; s.z += v.z; s.w += v.w;
        }
        __half* o = path ? o2 : o1;
        reinterpret_cast<__half2*>(o + (size_t)ii * 4)[0] = __floats2half2_rn(s.x, s.y);
        reinterpret_cast<__half2*>(o + (size_t)ii * 4)[1] = __floats2half2_rn(s.z, s.w);
    }
}

// ============================================================================
// fused prep kernel (coverage verified R13): cvt x | split wo | tsplit wv |
// biasc | (path2 only) cvt wpg = g*wp
// ============================================================================
#define NCVT   4096
#define NSPL   256
#define NTSP   1024
#define NBIA   1024
#define NWPJ   512
#define PREP_GRID_1 (NCVT + NSPL + NTSP + NBIA)
#define PREP_GRID_2 (NCVT + NSPL + NTSP + NBIA + NWPJ)

__global__ __launch_bounds__(256)
void prep(const float* __restrict__ x, __half* __restrict__ xh,
          const float* __restrict__ wo,
          __nv_bfloat16* __restrict__ wo_h, __nv_bfloat16* __restrict__ wo_l,
          const float* __restrict__ wv,
          __nv_bfloat16* __restrict__ wvt_h, __nv_bfloat16* __restrict__ wvt_l,
          const float* __restrict__ bv, const float* __restrict__ bo,
          float* __restrict__ c,
          const float* __restrict__ wp, const float* __restrict__ lng,
          __half* __restrict__ wpg)
{
    const int bx = blockIdx.x;
    const int tid = threadIdx.x;

    if (bx < NCVT) {
        const int base = bx * 4096 + tid * 4;
#pragma unroll
        for (int k = 0; k < 4; k++) {
            const int idx = base + k * 1024;
            float4 v = *reinterpret_cast<const float4*>(x + idx);
            reinterpret_cast<__half2*>(xh + idx)[0] = __floats2half2_rn(v.x, v.y);
            reinterpret_cast<__half2*>(xh + idx)[1] = __floats2half2_rn(v.z, v.w);
        }
        return;
    }
    if (bx < NCVT + NSPL) {
        const int base = (bx - NCVT) * 4096 + tid * 4;
#pragma unroll
        for (int k = 0; k < 4; k++) {
            const int idx = base + k * 1024;
            float4 v = *reinterpret_cast<const float4*>(wo + idx);
            __nv_bfloat162 h0, h1, l0, l1;
            h0.x = __float2bfloat16_rn(v.x); h0.y = __float2bfloat16_rn(v.y);
            h1.x = __float2bfloat16_rn(v.z); h1.y = __float2bfloat16_rn(v.w);
            l0.x = __float2bfloat16_rn(v.x - __bfloat162float(h0.x));
            l0.y = __float2bfloat16_rn(v.y - __bfloat162float(h0.y));
            l1.x = __float2bfloat16_rn(v.z - __bfloat162float(h1.x));
            l1.y = __float2bfloat16_rn(v.w - __bfloat162float(h1.y));
            reinterpret_cast<__nv_bfloat162*>(wo_h + idx)[0] = h0;
            reinterpret_cast<__nv_bfloat162*>(wo_h + idx)[1] = h1;
            reinterpret_cast<__nv_bfloat162*>(wo_l + idx)[0] = l0;
            reinterpret_cast<__nv_bfloat162*>(wo_l + idx)[1] = l1;
        }
        return;
    }
    if (bx < NCVT + NSPL + NTSP) {
        __shared__ float t[32][33];
        const int bi = bx - NCVT - NSPL;
        const int r0 = (bi >> 5) * 32, c0 = (bi & 31) * 32;
        const int tx = tid & 31, ty = tid >> 5;
#pragma unroll
        for (int i = 0; i < 4; i++)
            t[ty + 8 * i][tx] = wv[(size_t)(r0 + ty + 8 * i) * DIM + c0 + tx];
        __syncthreads();
#pragma unroll
        for (int i = 0; i < 4; i++) {
            const int rr = ty + 8 * i;
            const float v = t[tx][rr];
            const size_t o = (size_t)(c0 + rr) * DIM + r0 + tx;
            __nv_bfloat16 hh = __float2bfloat16_rn(v);
            wvt_h[o] = hh;
            wvt_l[o] = __float2bfloat16_rn(v - __bfloat162float(hh));
        }
        return;
    }
    if (bx < NCVT + NSPL + NTSP + NBIA) {
        __shared__ float red[8];
        const int n = bx - NCVT - NSPL - NTSP;
        float s = 0.0f;
        for (int j = tid; j < DIM; j += 256) s += wo[(size_t)n * DIM + j] * bv[j];
#pragma unroll
        for (int o = 16; o > 0; o >>= 1) s += __shfl_xor_sync(0xFFFFFFFFu, s, o);
        if ((tid & 31) == 0) red[tid >> 5] = s;
        __syncthreads();
        if (tid == 0) {
            float t2 = bo[n];
#pragma unroll
            for (int w = 0; w < 8; w++) t2 += red[w];
            c[n] = t2;
        }
        return;
    }
    {
        // wpg[n,k] = lng[k] * wp[n,k], fp16
        const int base = (bx - NCVT - NSPL - NTSP - NBIA) * 4096 + tid * 4;
#pragma unroll
        for (int k = 0; k < 4; k++) {
            const int idx = base + k * 1024;
            const int kk = idx & (DIM2 - 1);
            float4 v = *reinterpret_cast<const float4*>(wp + idx);
            float4 gv = *reinterpret_cast<const float4*>(lng + kk);
            v.x *= gv.x; v.y *= gv.y; v.z *= gv.z; v.w *= gv.w;
            reinterpret_cast<__half2*>(wpg + idx)[0] = __floats2half2_rn(v.x, v.y);
            reinterpret_cast<__half2*>(wpg + idx)[1] = __floats2half2_rn(v.z, v.w);
        }
    }
}

// ---------------- t-vectors: t1=wp·b, t2=wp·g, t3=wp·(c⊙g) per out-col n ----------------
__global__ __launch_bounds__(256)
void tvec(const float* __restrict__ wp, const float* __restrict__ g,
          const float* __restrict__ b,
          const float* __restrict__ c1, const float* __restrict__ c2,
          float* __restrict__ t1, float* __restrict__ t2, float* __restrict__ t3)
{
    __shared__ float r1[8], r2[8], r3[8];
    const int n = blockIdx.x;
    const int tid = threadIdx.x;
    float s1 = 0.0f, s2 = 0.0f, s3 = 0.0f;
    for (int j = tid * 4; j < DIM2; j += 1024) {
        float4 w  = *reinterpret_cast<const float4*>(wp + (size_t)n * DIM2 + j);
        float4 gv = *reinterpret_cast<const float4*>(g + j);
        float4 bv = *reinterpret_cast<const float4*>(b + j);
        float4 cv = (j < DIM) ? *reinterpret_cast<const float4*>(c1 + j)
                              : *reinterpret_cast<const float4*>(c2 + j - DIM);
        s1 += w.x * bv.x + w.y * bv.y + w.z * bv.z + w.w * bv.w;
        s2 += w.x * gv.x + w.y * gv.y + w.z * gv.z + w.w * gv.w;
        s3 += w.x * gv.x * cv.x + w.y * gv.y * cv.y + w.z * gv.z * cv.z + w.w * gv.w * cv.w;
    }
#pragma unroll
    for (int o = 16; o > 0; o >>= 1) {
        s1 += __shfl_xor_sync(0xFFFFFFFFu, s1, o);
        s2 += __shfl_xor_sync(0xFFFFFFFFu, s2, o);
        s3 += __shfl_xor_sync(0xFFFFFFFFu, s3, o);
    }
    if ((tid & 31) == 0) { r1[tid >> 5] = s1; r2[tid >> 5] = s2; r3[tid >> 5] = s3; }
    __syncthreads();
    if (tid == 0) {
        float a = 0, bb = 0, cc = 0;
#pragma unroll
        for (int w = 0; w < 8; w++) { a += r1[w]; bb += r2[w]; cc += r3[w]; }
        t1[n] = a; t2[n] = bb; t3[n] = cc;
    }
}

// ---------------- per-row LN stats of (z + c): rowP = (rstd, mu*rstd) ----------------
__global__ __launch_bounds__(256)
void stats(const __half* __restrict__ z,
           const float* __restrict__ c1, const float* __restrict__ c2,
           float2* __restrict__ rowP)
{
    __shared__ float redS[8], redQ[8];
    const size_t base = (size_t)blockIdx.x * DIM2;
    const int tid = threadIdx.x;
    const int col = tid * 8;

    uint4 zr = *reinterpret_cast<const uint4*>(z + base + col);
    float f[8];
    {
        float2 t0 = __half22float2(*reinterpret_cast<__half2*>(&zr.x));
        float2 t1 = __half22float2(*reinterpret_cast<__half2*>(&zr.y));
        float2 t2 = __half22float2(*reinterpret_cast<__half2*>(&zr.z));
        float2 t3 = __half22float2(*reinterpret_cast<__half2*>(&zr.w));
        f[0] = t0.x; f[1] = t0.y; f[2] = t1.x; f[3] = t1.y;
        f[4] = t2.x; f[5] = t2.y; f[6] = t3.x; f[7] = t3.y;
    }
    const float* cb = (col < DIM) ? (c1 + col) : (c2 + col - DIM);
    float4 cb0 = *reinterpret_cast<const float4*>(cb);
    float4 cb1 = *reinterpret_cast<const float4*>(cb + 4);
    f[0] += cb0.x; f[1] += cb0.y; f[2] += cb0.z; f[3] += cb0.w;
    f[4] += cb1.x; f[5] += cb1.y; f[6] += cb1.z; f[7] += cb1.w;

    float s = 0.0f, q = 0.0f;
#pragma unroll
    for (int i = 0; i < 8; i++) { s += f[i]; q += f[i] * f[i]; }
#pragma unroll
    for (int o = 16; o > 0; o >>= 1) {
        s += __shfl_xor_sync(0xFFFFFFFFu, s, o);
        q += __shfl_xor_sync(0xFFFFFFFFu, q, o);
    }
    if ((tid & 31) == 0) { redS[tid >> 5] = s; redQ[tid >> 5] = q; }
    __syncthreads();
    if (tid == 0) {
        float S = 0.0f, Q = 0.0f;
#pragma unroll
        for (int w = 0; w < 8; w++) { S += redS[w]; Q += redQ[w]; }
        const float mu = S * (1.0f / DIM2);
        const float var = Q * (1.0f / DIM2) - mu * mu;
        const float rstd = rsqrtf(var + 1e-5f);
        rowP[blockIdx.x] = make_float2(rstd, mu * rstd);
    }
}

// ---------------- launch ----------------
extern "C" void kernel_launch(void* const* d_in, const int* in_sizes, int n_in,
                              void* d_out, int out_size)
{
    const float* x_u    = (const float*)d_in[0];
    const float* x_m    = (const float*)d_in[1];
    const float* w_qkv1 = (const float*)d_in[2];
    const float* b_qkv1 = (const float*)d_in[3];
    const float* w_o1   = (const float*)d_in[4];
    const float* b_o1   = (const float*)d_in[5];
    const float* w_qkv2 = (const float*)d_in[6];
    const float* b_qkv2 = (const float*)d_in[7];
    const float* w_o2   = (const float*)d_in[8];
    const float* b_o2   = (const float*)d_in[9];
    const float* ln_g   = (const float*)d_in[10];
    const float* ln_b   = (const float*)d_in[11];
    const float* w_proj = (const float*)d_in[12];
    const float* b_proj = (const float*)d_in[13];
    float* out = (float*)d_out;

    const float* wv1 = w_qkv1 + (size_t)2 * DIM * DIM;
    const float* bv1 = b_qkv1 + 2 * DIM;
    const float* wv2 = w_qkv2 + (size_t)2 * DIM * DIM;
    const float* bv2 = b_qkv2 + 2 * DIM;

    __half *xuh, *xmh, *zh, *B1h, *B2h, *wpg;
    float *part, *c1, *c2, *t1, *t2, *t3;
    float2* rowP;
    __nv_bfloat16 *wo1_h, *wo1_l, *wvt1_h, *wvt1_l, *wo2_h, *wo2_l, *wvt2_h, *wvt2_l;

    cudaGetSymbolAddress((void**)&xuh, g_xuh);
    cudaGetSymbolAddress((void**)&xmh, g_xmh);
    cudaGetSymbolAddress((void**)&zh, g_zh);
    cudaGetSymbolAddress((void**)&B1h, g_B1h);
    cudaGetSymbolAddress((void**)&B2h, g_B2h);
    cudaGetSymbolAddress((void**)&wpg, g_wpg);
    cudaGetSymbolAddress((void**)&part, g_part);
    cudaGetSymbolAddress((void**)&c1, g_c1);
    cudaGetSymbolAddress((void**)&c2, g_c2);
    cudaGetSymbolAddress((void**)&t1, g_t1);
    cudaGetSymbolAddress((void**)&t2, g_t2);
    cudaGetSymbolAddress((void**)&t3, g_t3);
    cudaGetSymbolAddress((void**)&rowP, g_rowP);
    cudaGetSymbolAddress((void**)&wo1_h, g_wo1_hi);   cudaGetSymbolAddress((void**)&wo1_l, g_wo1_lo);
    cudaGetSymbolAddress((void**)&wvt1_h, g_wvt1_hi); cudaGetSymbolAddress((void**)&wvt1_l, g_wvt1_lo);
    cudaGetSymbolAddress((void**)&wo2_h, g_wo2_hi);   cudaGetSymbolAddress((void**)&wo2_l, g_wo2_lo);
    cudaGetSymbolAddress((void**)&wvt2_h, g_wvt2_hi); cudaGetSymbolAddress((void**)&wvt2_l, g_wvt2_lo);

    cudaFuncSetAttribute(mma_gemm_sk2, cudaFuncAttributeMaxDynamicSharedMemorySize, SMEM_TOT);
    cudaFuncSetAttribute(zgemm2,  cudaFuncAttributeMaxDynamicSharedMemorySize, HSMEM);
    cudaFuncSetAttribute(proj_ln, cudaFuncAttributeMaxDynamicSharedMemorySize, HSMEM);

    // 1-2) prep both paths
    prep<<<PREP_GRID_1, 256>>>(x_u, xuh, w_o1, wo1_h, wo1_l, wv1, wvt1_h, wvt1_l,
                               bv1, b_o1, c1, nullptr, nullptr, nullptr);
    prep<<<PREP_GRID_2, 256>>>(x_m, xmh, w_o2, wo2_h, wo2_l, wv2, wvt2_h, wvt2_l,
                               bv2, b_o2, c2, w_proj, ln_g, wpg);

    // 3) t-vectors (needs c1, c2)
    tvec<<<DIM, 256>>>(w_proj, ln_g, ln_b, c1, c2, t1, t2, t3);

    // 4) both weight combines, split-K (grid z = 2 paths x 8 slices)
    mma_gemm_sk2<<<dim3(DIM / NT, DIM / MT, 16), 256, SMEM_TOT>>>(
        wo1_h, wo1_l, wvt1_h, wvt1_l, wo2_h, wo2_l, wvt2_h, wvt2_l, part);

    // 5) reduce both -> B1h, B2h
    reduce8_half2<<<1024, 256>>>(part, B1h, B2h);

    // 6) merged z-GEMM (1024 CTAs; ncu -s 5 profiles this)
    zgemm2<<<dim3(DIM / 128, 2 * BATCH / 256), 512, HSMEM>>>(xuh, xmh, B1h, B2h, zh);

    // 7) per-row LN stats of z + c
    stats<<<BATCH, 256>>>(zh, c1, c2, rowP);

    // 8) proj GEMM with folded LN + GELU
    proj_ln<<<dim3(DIM / 128, BATCH / 256), 512, HSMEM>>>(zh, wpg, out, t1, t2, t3, rowP);
}